// round 6
// baseline (speedup 1.0000x reference)
#include <cuda_runtime.h>

// ---------------------------------------------------------------------------
// PromptedAttention: B=8, H=W=32, C=768, heads=12, hd=64, nt=8, N=1032
// Round 5: tf32 mma + cp.async double-buffered pipelines everywhere.
// ---------------------------------------------------------------------------

#define BATCH     8
#define HEADS     12
#define HD        64
#define C_DIM     768
#define NT        8
#define HW        1024
#define NSEQ      1032
#define BHN       96
#define MROWS     8256
#define QKV_N     2304
#define XOUT_ELEMS 6291456

__device__ float g_q[BHN * NSEQ * HD];
__device__ float g_k[BHN * NSEQ * HD];
__device__ float g_v[BHN * NSEQ * HD];
__device__ float g_relh[BHN * 32 * 32 * 32];
__device__ float g_relw[BHN * 32 * 32 * 32];
__device__ float g_ctx[MROWS * C_DIM];

__device__ __forceinline__ unsigned f2tf(float f) {
    unsigned u;
    asm("cvt.rna.tf32.f32 %0, %1;" : "=r"(u) : "f"(f));
    return u;
}
__device__ __forceinline__ float f2tff(float f) { return __uint_as_float(f2tf(f)); }
__device__ __forceinline__ unsigned u2tf(unsigned raw) {
    return f2tf(__uint_as_float(raw));
}

__device__ __forceinline__ void mma8(float* c, const unsigned* a, const unsigned* b) {
    asm volatile(
        "mma.sync.aligned.m16n8k8.row.col.f32.tf32.tf32.f32 "
        "{%0,%1,%2,%3}, {%4,%5,%6,%7}, {%8,%9}, {%0,%1,%2,%3};\n"
        : "+f"(c[0]), "+f"(c[1]), "+f"(c[2]), "+f"(c[3])
        : "r"(a[0]), "r"(a[1]), "r"(a[2]), "r"(a[3]), "r"(b[0]), "r"(b[1]));
}

__device__ __forceinline__ unsigned smem_u32(const void* p) {
    return (unsigned)__cvta_generic_to_shared(p);
}
__device__ __forceinline__ void cpasync16(unsigned dst, const void* src, bool pred) {
    asm volatile("cp.async.cg.shared.global [%0], [%1], 16, %2;\n"
                 :: "r"(dst), "l"(src), "r"(pred ? 16 : 0));
}
#define CP_COMMIT() asm volatile("cp.async.commit_group;\n" ::: "memory")
#define CP_WAIT(N)  asm volatile("cp.async.wait_group %0;\n" :: "n"(N) : "memory")

// ---------------------------------------------------------------------------
// K1: fused concat + QKV GEMM, 2-stage cp.async pipeline. 128x128, BK=16.
// ---------------------------------------------------------------------------
__global__ __launch_bounds__(256) void qkv_mma_kernel(
    const float* __restrict__ x, const float* __restrict__ vp,
    const float* __restrict__ W, const float* __restrict__ bias)
{
    __shared__ float As[2][128 * 20];
    __shared__ float Bs[2][16 * 136];

    const int m0 = blockIdx.y * 128;
    const int n0 = blockIdx.x * 128;
    const int tid = threadIdx.x;
    const int wid = tid >> 5, lane = tid & 31;
    const int g = lane >> 2, tig = lane & 3;
    const int wm = wid >> 1, wn = wid & 1;

    const int aRow = tid >> 1;
    const int aK   = (tid & 1) * 8;
    const int am   = m0 + aRow;
    const bool av  = (am < MROWS);
    const float* arp;
    {
        int mm = av ? am : 0;
        int b = mm / NSEQ, n = mm % NSEQ;
        arp = (n < NT) ? (vp + ((size_t)b * NT + n) * C_DIM)
                       : (x  + ((size_t)b * HW + (n - NT)) * C_DIM);
    }
    const int bk = tid >> 5;
    const int bn = (tid & 31) * 4;

    const unsigned aDst0 = smem_u32(&As[0][aRow * 20 + aK]);
    const unsigned aDst1 = smem_u32(&As[1][aRow * 20 + aK]);
    const unsigned bDst0 = smem_u32(&Bs[0][bk * 136 + bn]);
    const unsigned bDst1 = smem_u32(&Bs[1][bk * 136 + bn]);

    float c[2][8][4];
#pragma unroll
    for (int mt = 0; mt < 2; ++mt)
#pragma unroll
        for (int nt = 0; nt < 8; ++nt)
#pragma unroll
            for (int j = 0; j < 4; ++j) c[mt][nt][j] = 0.f;

    auto load_stage = [&](int s, int k0) {
        unsigned ad = s ? aDst1 : aDst0;
        unsigned bd = s ? bDst1 : bDst0;
        cpasync16(ad,      arp + k0 + aK,     av);
        cpasync16(ad + 16, arp + k0 + aK + 4, av);
        cpasync16(bd,                W + (size_t)(k0 + bk)     * QKV_N + n0 + bn, true);
        cpasync16(bd + 8 * 136 * 4,  W + (size_t)(k0 + bk + 8) * QKV_N + n0 + bn, true);
        CP_COMMIT();
    };

    load_stage(0, 0);

    const int NKT = C_DIM / 16;      // 48
    for (int kt = 0; kt < NKT; ++kt) {
        int s = kt & 1;
        if (kt + 1 < NKT) { load_stage(s ^ 1, (kt + 1) * 16); CP_WAIT(1); }
        else              { CP_WAIT(0); }
        __syncthreads();

        const unsigned* Au = (const unsigned*)As[s];
        const unsigned* Bu = (const unsigned*)Bs[s];
#pragma unroll
        for (int ks = 0; ks < 2; ++ks) {
            unsigned a[2][4];
#pragma unroll
            for (int mt = 0; mt < 2; ++mt) {
                int mr = wm * 32 + mt * 16;
                a[mt][0] = u2tf(Au[(mr + g    ) * 20 + ks * 8 + tig]);
                a[mt][1] = u2tf(Au[(mr + g + 8) * 20 + ks * 8 + tig]);
                a[mt][2] = u2tf(Au[(mr + g    ) * 20 + ks * 8 + tig + 4]);
                a[mt][3] = u2tf(Au[(mr + g + 8) * 20 + ks * 8 + tig + 4]);
            }
            unsigned b[8][2];
#pragma unroll
            for (int nt = 0; nt < 8; ++nt) {
                int nc = wn * 64 + nt * 8 + g;
                b[nt][0] = u2tf(Bu[(ks * 8 + tig    ) * 136 + nc]);
                b[nt][1] = u2tf(Bu[(ks * 8 + tig + 4) * 136 + nc]);
            }
#pragma unroll
            for (int mt = 0; mt < 2; ++mt)
#pragma unroll
                for (int nt = 0; nt < 8; ++nt) mma8(c[mt][nt], a[mt], b[nt]);
        }
        __syncthreads();
    }

    float* bufs[3] = {g_q, g_k, g_v};
#pragma unroll
    for (int nt = 0; nt < 8; ++nt) {
        int col = n0 + wn * 64 + nt * 8 + tig * 2;
        int which = col / C_DIM;
        int c2 = col % C_DIM;
        int head = c2 >> 6, db = c2 & 63;
        float b0v = bias[col], b1v = bias[col + 1];
        float* buf = bufs[which];
#pragma unroll
        for (int mt = 0; mt < 2; ++mt) {
#pragma unroll
            for (int h = 0; h < 2; ++h) {
                int m = m0 + wm * 32 + mt * 16 + g + h * 8;
                if (m >= MROWS) continue;
                int bb = m / NSEQ, nn = m % NSEQ;
                float* dst = buf + (size_t)bb * (HEADS * NSEQ * HD)
                                 + (size_t)head * (NSEQ * HD)
                                 + (size_t)nn * HD + db;
                float2 v;
                v.x = c[mt][nt][h * 2 + 0] + b0v;
                v.y = c[mt][nt][h * 2 + 1] + b1v;
                *(float2*)dst = v;
            }
        }
    }
}

// ---------------------------------------------------------------------------
// K2: rel_h / rel_w bias GEMMs (SIMT fp32, small).
// ---------------------------------------------------------------------------
__global__ __launch_bounds__(256) void rel_kernel(
    const float* __restrict__ rph, const float* __restrict__ rpw)
{
    __shared__ float qs[32 * 64];
    __shared__ float RsT[64 * 33];

    const int bh = blockIdx.y;
    const int idx0 = blockIdx.x;
    const int variant = blockIdx.z;
    const int tid = threadIdx.x;

#pragma unroll
    for (int it = 0; it < 8; ++it) {
        int idx = tid + it * 256;
        int r = idx >> 6, c = idx & 63;
        int n = (variant == 0) ? (NT + idx0 * 32 + r) : (NT + r * 32 + idx0);
        qs[idx] = g_q[((size_t)bh * NSEQ + n) * HD + c];
    }
    const float* rp = (variant == 0) ? rph : rpw;
#pragma unroll
    for (int it = 0; it < 8; ++it) {
        int idx = tid + it * 256;
        int k = idx >> 6, c = idx & 63;
        RsT[c * 33 + k] = rp[(size_t)(idx0 - k + 31) * HD + c];
    }
    __syncthreads();

    const int ty = tid >> 3;
    const int txk = tid & 7;
    float acc[4] = {0.f, 0.f, 0.f, 0.f};
#pragma unroll 8
    for (int c = 0; c < 64; ++c) {
        float q = qs[ty * 64 + c];
#pragma unroll
        for (int j = 0; j < 4; ++j) acc[j] += q * RsT[c * 33 + txk * 4 + j];
    }
    float* outb = (variant == 0) ? g_relh : g_relw;
    size_t base = (variant == 0)
        ? ((((size_t)bh * 32 + idx0) * 32 + ty) * 32)
        : ((((size_t)bh * 32 + ty) * 32 + idx0) * 32);
#pragma unroll
    for (int j = 0; j < 4; ++j) outb[base + txk * 4 + j] = acc[j];
}

// ---------------------------------------------------------------------------
// K3: flash attention, tf32 mma, cp.async double-buffered K/V.
// ---------------------------------------------------------------------------
#define ATT_SM_FLOATS (64*68 + 64*68 + 2*64*68 + 2*64*72 + 2*64*32 + 3*64)
#define ATT_SM_BYTES  (ATT_SM_FLOATS * 4)

__global__ __launch_bounds__(256) void attn_mma_kernel()
{
    extern __shared__ float sm[];
    float* Qs   = sm;                    // [64 q][68] tf32, prescaled
    float* ps   = Qs + 64 * 68;          // [64 q][68] S then P(tf32)
    float* Ks0  = ps + 64 * 68;          // [2][64 key][68] raw fp32
    float* Vs0  = Ks0 + 2 * 64 * 68;     // [2][64 key][72] raw fp32
    float* rhs  = Vs0 + 2 * 64 * 72;     // [64 q][32]
    float* rws  = rhs + 64 * 32;         // [64 q][32]
    float* rowm = rws + 64 * 32;
    float* rowl = rowm + 64;
    float* rowsc = rowl + 64;

    const int tid = threadIdx.x;
    const int wid = tid >> 5, lane = tid & 31;
    const int g = lane >> 2, tig = lane & 3;
    const int wm = wid >> 1, wn = wid & 1;
    const int bh = blockIdx.y;
    const int b = bh / HEADS, head = bh % HEADS;
    const int q0 = blockIdx.x * 64;

    const float* qbase = g_q + (size_t)bh * NSEQ * HD;
    const float* kbase = g_k + (size_t)bh * NSEQ * HD;
    const float* vbase = g_v + (size_t)bh * NSEQ * HD;

    // K/V stage loader: 4 float4 per tensor per thread.
    const int lr  = tid >> 4;            // row 0..15 base (16 rows per chunk of 256 thr? no:)
    const int ld4 = (tid & 15) * 4;      // d 0..60 step 4
    auto load_kv = [&](int s, int k0) {
        float* Ksb = Ks0 + s * 64 * 68;
        float* Vsb = Vs0 + s * 64 * 72;
#pragma unroll
        for (int t = 0; t < 4; ++t) {
            int r = lr + t * 16;
            int kg = k0 + r;
            bool pv = (kg < NSEQ);
            const float* ksrc = kbase + (size_t)(pv ? kg : 0) * HD + ld4;
            const float* vsrc = vbase + (size_t)(pv ? kg : 0) * HD + ld4;
            cpasync16(smem_u32(&Ksb[r * 68 + ld4]), ksrc, pv);
            cpasync16(smem_u32(&Vsb[r * 72 + ld4]), vsrc, pv);
        }
        CP_COMMIT();
    };

    load_kv(0, 0);

#pragma unroll
    for (int it = 0; it < 16; ++it) {
        int idx = tid + it * 256;
        int r = idx >> 6, d = idx & 63;
        int qg = q0 + r;
        float v = (qg < NSEQ) ? qbase[(size_t)qg * HD + d] * 0.125f : 0.f;
        Qs[r * 68 + d] = f2tff(v);
    }
#pragma unroll
    for (int it = 0; it < 8; ++it) {
        int idx = tid + it * 256;
        int r = idx >> 5, cc = idx & 31;
        int qg = q0 + r;
        float hv = 0.f, wv = 0.f;
        if (qg >= NT && qg < NSEQ) {
            int pix = qg - NT;
            int hq = pix >> 5, wq = pix & 31;
            size_t rbase = (((size_t)bh * 32 + hq) * 32 + wq) * 32;
            hv = g_relh[rbase + cc];
            wv = g_relw[rbase + cc];
        }
        rhs[idx] = hv;
        rws[idx] = wv;
    }
    if (tid < 64) { rowm[tid] = -3.0e38f; rowl[tid] = 0.f; }

    float oc[4][4];
#pragma unroll
    for (int nt = 0; nt < 4; ++nt)
#pragma unroll
        for (int j = 0; j < 4; ++j) oc[nt][j] = 0.f;

    const int NIT = (NSEQ + 63) / 64;    // 17
    for (int itk = 0; itk < NIT; ++itk) {
        int s = itk & 1;
        int k0 = itk * 64;
        if (itk + 1 < NIT) { load_kv(s ^ 1, k0 + 64); CP_WAIT(1); }
        else               { CP_WAIT(0); }
        __syncthreads();

        const unsigned* Qu = (const unsigned*)Qs;
        const unsigned* Ku = (const unsigned*)(Ks0 + s * 64 * 68);
        const unsigned* Vu = (const unsigned*)(Vs0 + s * 64 * 72);

        float sc4[4][4];
#pragma unroll
        for (int nt = 0; nt < 4; ++nt)
#pragma unroll
            for (int j = 0; j < 4; ++j) sc4[nt][j] = 0.f;

#pragma unroll
        for (int ks = 0; ks < 8; ++ks) {
            unsigned a[4];
            int mr = wm * 16;
            a[0] = Qu[(mr + g    ) * 68 + ks * 8 + tig];
            a[1] = Qu[(mr + g + 8) * 68 + ks * 8 + tig];
            a[2] = Qu[(mr + g    ) * 68 + ks * 8 + tig + 4];
            a[3] = Qu[(mr + g + 8) * 68 + ks * 8 + tig + 4];
#pragma unroll
            for (int nt = 0; nt < 4; ++nt) {
                unsigned bb[2];
                int key = wn * 32 + nt * 8 + g;
                bb[0] = u2tf(Ku[key * 68 + ks * 8 + tig]);
                bb[1] = u2tf(Ku[key * 68 + ks * 8 + tig + 4]);
                mma8(sc4[nt], a, bb);
            }
        }

#pragma unroll
        for (int nt = 0; nt < 4; ++nt) {
            int col = wn * 32 + nt * 8 + tig * 2;
            int r0 = wm * 16 + g;
            *(float2*)&ps[r0 * 68 + col] = make_float2(sc4[nt][0], sc4[nt][1]);
            *(float2*)&ps[(r0 + 8) * 68 + col] = make_float2(sc4[nt][2], sc4[nt][3]);
        }
        __syncthreads();

        // online softmax (4 threads per row)
        {
            int r = tid >> 2, tg = tid & 3;
            int qg = q0 + r;
            float vreg[16];
            float tm = -3.0e38f;
#pragma unroll
            for (int cc = 0; cc < 16; ++cc) {
                int cj = tg * 16 + cc;
                int jg = k0 + cj;
                float val = ps[r * 68 + cj];
                if (jg >= NSEQ) {
                    val = -1e30f;
                } else if (qg >= NT) {
                    if (jg < NT) val -= 100.f;
                    else {
                        int pj = jg - NT;
                        val += rhs[r * 32 + (pj >> 5)] + rws[r * 32 + (pj & 31)];
                    }
                }
                vreg[cc] = val;
                tm = fmaxf(tm, val);
            }
            tm = fmaxf(tm, __shfl_xor_sync(0xffffffffu, tm, 1));
            tm = fmaxf(tm, __shfl_xor_sync(0xffffffffu, tm, 2));
            float oldm = rowm[r];
            float newm = fmaxf(oldm, tm);
            float sum = 0.f;
#pragma unroll
            for (int cc = 0; cc < 16; ++cc) {
                float p = __expf(vreg[cc] - newm);
                sum += p;
                ps[r * 68 + tg * 16 + cc] = f2tff(p);
            }
            sum += __shfl_xor_sync(0xffffffffu, sum, 1);
            sum += __shfl_xor_sync(0xffffffffu, sum, 2);
            if (tg == 0) {
                float sc = __expf(oldm - newm);
                rowsc[r] = sc;
                rowl[r] = rowl[r] * sc + sum;
                rowm[r] = newm;
            }
        }
        __syncthreads();

        // O rescale + PV
        const unsigned* pu = (const unsigned*)ps;
        float s0 = rowsc[wm * 16 + g], s1 = rowsc[wm * 16 + g + 8];
#pragma unroll
        for (int nt = 0; nt < 4; ++nt) {
            oc[nt][0] *= s0; oc[nt][1] *= s0;
            oc[nt][2] *= s1; oc[nt][3] *= s1;
        }
#pragma unroll
        for (int ks = 0; ks < 8; ++ks) {
            unsigned a[4];
            int mr = wm * 16;
            a[0] = pu[(mr + g    ) * 68 + ks * 8 + tig];
            a[1] = pu[(mr + g + 8) * 68 + ks * 8 + tig];
            a[2] = pu[(mr + g    ) * 68 + ks * 8 + tig + 4];
            a[3] = pu[(mr + g + 8) * 68 + ks * 8 + tig + 4];
#pragma unroll
            for (int nt = 0; nt < 4; ++nt) {
                unsigned bb[2];
                int dcol = wn * 32 + nt * 8 + g;
                bb[0] = u2tf(Vu[(ks * 8 + tig    ) * 72 + dcol]);
                bb[1] = u2tf(Vu[(ks * 8 + tig + 4) * 72 + dcol]);
                mma8(oc[nt], a, bb);
            }
        }
        __syncthreads();
    }

    {
        int r0 = wm * 16 + g, r1 = r0 + 8;
        int qg0 = q0 + r0, qg1 = q0 + r1;
        float inv0 = (qg0 < NSEQ) ? (1.f / rowl[r0]) : 0.f;
        float inv1 = (qg1 < NSEQ) ? (1.f / rowl[r1]) : 0.f;
#pragma unroll
        for (int nt = 0; nt < 4; ++nt) {
            int col = wn * 32 + nt * 8 + tig * 2;
            if (qg0 < NSEQ) {
                float2 v = make_float2(oc[nt][0] * inv0, oc[nt][1] * inv0);
                *(float2*)(g_ctx + ((size_t)b * NSEQ + qg0) * C_DIM + head * HD + col) = v;
            }
            if (qg1 < NSEQ) {
                float2 v = make_float2(oc[nt][2] * inv1, oc[nt][3] * inv1);
                *(float2*)(g_ctx + ((size_t)b * NSEQ + qg1) * C_DIM + head * HD + col) = v;
            }
        }
    }
}

// ---------------------------------------------------------------------------
// K4: output projection GEMM, 2-stage cp.async pipeline.
// ---------------------------------------------------------------------------
__global__ __launch_bounds__(256) void proj_mma_kernel(
    const float* __restrict__ W, const float* __restrict__ bias,
    float* __restrict__ out)
{
    __shared__ float As[2][128 * 20];
    __shared__ float Bs[2][16 * 136];

    const int m0 = blockIdx.y * 128;
    const int n0 = blockIdx.x * 128;
    const int tid = threadIdx.x;
    const int wid = tid >> 5, lane = tid & 31;
    const int g = lane >> 2, tig = lane & 3;
    const int wm = wid >> 1, wn = wid & 1;

    const int aRow = tid >> 1;
    const int aK   = (tid & 1) * 8;
    const int am   = m0 + aRow;
    const bool av  = (am < MROWS);
    const float* arp = g_ctx + (size_t)(av ? am : 0) * C_DIM;

    const int bk = tid >> 5;
    const int bn = (tid & 31) * 4;

    const unsigned aDst0 = smem_u32(&As[0][aRow * 20 + aK]);
    const unsigned aDst1 = smem_u32(&As[1][aRow * 20 + aK]);
    const unsigned bDst0 = smem_u32(&Bs[0][bk * 136 + bn]);
    const unsigned bDst1 = smem_u32(&Bs[1][bk * 136 + bn]);

    float c[2][8][4];
#pragma unroll
    for (int mt = 0; mt < 2; ++mt)
#pragma unroll
        for (int nt = 0; nt < 8; ++nt)
#pragma unroll
            for (int j = 0; j < 4; ++j) c[mt][nt][j] = 0.f;

    auto load_stage = [&](int s, int k0) {
        unsigned ad = s ? aDst1 : aDst0;
        unsigned bd = s ? bDst1 : bDst0;
        cpasync16(ad,      arp + k0 + aK,     av);
        cpasync16(ad + 16, arp + k0 + aK + 4, av);
        cpasync16(bd,                W + (size_t)(k0 + bk)     * C_DIM + n0 + bn, true);
        cpasync16(bd + 8 * 136 * 4,  W + (size_t)(k0 + bk + 8) * C_DIM + n0 + bn, true);
        CP_COMMIT();
    };

    load_stage(0, 0);

    const int NKT = C_DIM / 16;
    for (int kt = 0; kt < NKT; ++kt) {
        int s = kt & 1;
        if (kt + 1 < NKT) { load_stage(s ^ 1, (kt + 1) * 16); CP_WAIT(1); }
        else              { CP_WAIT(0); }
        __syncthreads();

        const unsigned* Au = (const unsigned*)As[s];
        const unsigned* Bu = (const unsigned*)Bs[s];
#pragma unroll
        for (int ks = 0; ks < 2; ++ks) {
            unsigned a[2][4];
#pragma unroll
            for (int mt = 0; mt < 2; ++mt) {
                int mr = wm * 32 + mt * 16;
                a[mt][0] = u2tf(Au[(mr + g    ) * 20 + ks * 8 + tig]);
                a[mt][1] = u2tf(Au[(mr + g + 8) * 20 + ks * 8 + tig]);
                a[mt][2] = u2tf(Au[(mr + g    ) * 20 + ks * 8 + tig + 4]);
                a[mt][3] = u2tf(Au[(mr + g + 8) * 20 + ks * 8 + tig + 4]);
            }
            unsigned b[8][2];
#pragma unroll
            for (int nt = 0; nt < 8; ++nt) {
                int nc = wn * 64 + nt * 8 + g;
                b[nt][0] = u2tf(Bu[(ks * 8 + tig    ) * 136 + nc]);
                b[nt][1] = u2tf(Bu[(ks * 8 + tig + 4) * 136 + nc]);
            }
#pragma unroll
            for (int mt = 0; mt < 2; ++mt)
#pragma unroll
                for (int nt = 0; nt < 8; ++nt) mma8(c[mt][nt], a[mt], b[nt]);
        }
        __syncthreads();
    }

#pragma unroll
    for (int nt = 0; nt < 8; ++nt) {
        int col = n0 + wn * 64 + nt * 8 + tig * 2;
        float b0v = bias[col], b1v = bias[col + 1];
#pragma unroll
        for (int mt = 0; mt < 2; ++mt) {
#pragma unroll
            for (int h = 0; h < 2; ++h) {
                int m = m0 + wm * 32 + mt * 16 + g + h * 8;
                if (m >= MROWS) continue;
                int bb = m / NSEQ, nn = m % NSEQ;
                float* dst = (nn < NT)
                    ? (out + XOUT_ELEMS + ((size_t)bb * NT + nn) * C_DIM)
                    : (out + ((size_t)bb * HW + (nn - NT)) * C_DIM);
                float2 v;
                v.x = c[mt][nt][h * 2 + 0] + b0v;
                v.y = c[mt][nt][h * 2 + 1] + b1v;
                *(float2*)(dst + col) = v;
            }
        }
    }
}

// ---------------------------------------------------------------------------
extern "C" void kernel_launch(void* const* d_in, const int* in_sizes, int n_in,
                              void* d_out, int out_size)
{
    const float* x      = (const float*)d_in[0];
    const float* vp     = (const float*)d_in[1];
    const float* qkv_w  = (const float*)d_in[2];
    const float* qkv_b  = (const float*)d_in[3];
    const float* proj_w = (const float*)d_in[4];
    const float* proj_b = (const float*)d_in[5];
    const float* rph    = (const float*)d_in[6];
    const float* rpw    = (const float*)d_in[7];
    float* out = (float*)d_out;

    (void)in_sizes; (void)n_in; (void)out_size;

    cudaFuncSetAttribute(attn_mma_kernel,
                         cudaFuncAttributeMaxDynamicSharedMemorySize,
                         ATT_SM_BYTES);

    qkv_mma_kernel<<<dim3(QKV_N / 128, (MROWS + 127) / 128), 256>>>(x, vp, qkv_w, qkv_b);
    rel_kernel<<<dim3(32, BHN, 2), 256>>>(rph, rpw);
    attn_mma_kernel<<<dim3((NSEQ + 63) / 64, BHN), 256, ATT_SM_BYTES>>>();
    proj_mma_kernel<<<dim3(C_DIM / 128, (MROWS + 127) / 128), 256>>>(proj_w, proj_b, out);
}

// round 8
// speedup vs baseline: 1.0916x; 1.0916x over previous
#include <cuda_runtime.h>

// ---------------------------------------------------------------------------
// PromptedAttention: B=8, H=W=32, C=768, heads=12, hd=64, nt=8, N=1032
// Round 8: 3-stage cp.async GEMMs in DYNAMIC smem (fix 48KB static limit);
// attention = R4 sync version (2 CTAs/SM).
// ---------------------------------------------------------------------------

#define BATCH     8
#define HEADS     12
#define HD        64
#define C_DIM     768
#define NT        8
#define HW        1024
#define NSEQ      1032
#define BHN       96
#define MROWS     8256
#define QKV_N     2304
#define XOUT_ELEMS 6291456

__device__ float g_q[BHN * NSEQ * HD];
__device__ float g_k[BHN * NSEQ * HD];
__device__ float g_v[BHN * NSEQ * HD];
__device__ float g_relh[BHN * 32 * 32 * 32];
__device__ float g_relw[BHN * 32 * 32 * 32];
__device__ float g_ctx[MROWS * C_DIM];

__device__ __forceinline__ unsigned f2tf(float f) {
    unsigned u;
    asm("cvt.rna.tf32.f32 %0, %1;" : "=r"(u) : "f"(f));
    return u;
}
__device__ __forceinline__ float f2tff(float f) { return __uint_as_float(f2tf(f)); }
__device__ __forceinline__ unsigned u2tf(unsigned raw) {
    return f2tf(__uint_as_float(raw));
}

__device__ __forceinline__ void mma8(float* c, const unsigned* a, const unsigned* b) {
    asm volatile(
        "mma.sync.aligned.m16n8k8.row.col.f32.tf32.tf32.f32 "
        "{%0,%1,%2,%3}, {%4,%5,%6,%7}, {%8,%9}, {%0,%1,%2,%3};\n"
        : "+f"(c[0]), "+f"(c[1]), "+f"(c[2]), "+f"(c[3])
        : "r"(a[0]), "r"(a[1]), "r"(a[2]), "r"(a[3]), "r"(b[0]), "r"(b[1]));
}

__device__ __forceinline__ unsigned smem_u32(const void* p) {
    return (unsigned)__cvta_generic_to_shared(p);
}
__device__ __forceinline__ void cpasync16(unsigned dst, const void* src, bool pred) {
    asm volatile("cp.async.cg.shared.global [%0], [%1], 16, %2;\n"
                 :: "r"(dst), "l"(src), "r"(pred ? 16 : 0));
}
#define CP_COMMIT() asm volatile("cp.async.commit_group;\n" ::: "memory")
#define CP_WAIT(N)  asm volatile("cp.async.wait_group %0;\n" :: "n"(N) : "memory")

#define A_LD 20
#define B_LD 136
#define A_STG (128 * A_LD)
#define B_STG (16 * B_LD)
#define GEMM_SM_BYTES (3 * (A_STG + B_STG) * 4)   // 56832

// ---------------------------------------------------------------------------
// K1: fused concat + QKV GEMM, 3-stage cp.async pipeline, dynamic smem.
// ---------------------------------------------------------------------------
__global__ __launch_bounds__(256) void qkv_mma_kernel(
    const float* __restrict__ x, const float* __restrict__ vp,
    const float* __restrict__ W, const float* __restrict__ bias)
{
    extern __shared__ float dynsm[];
    float* Asb = dynsm;                 // [3][A_STG]
    float* Bsb = dynsm + 3 * A_STG;     // [3][B_STG]

    const int m0 = blockIdx.y * 128;
    const int n0 = blockIdx.x * 128;
    const int tid = threadIdx.x;
    const int wid = tid >> 5, lane = tid & 31;
    const int g = lane >> 2, tig = lane & 3;
    const int wm = wid >> 1, wn = wid & 1;

    const int aRow = tid >> 1;
    const int aK   = (tid & 1) * 8;
    const int am   = m0 + aRow;
    const bool av  = (am < MROWS);
    const float* arp;
    {
        int mm = av ? am : 0;
        int b = mm / NSEQ, n = mm % NSEQ;
        arp = (n < NT) ? (vp + ((size_t)b * NT + n) * C_DIM)
                       : (x  + ((size_t)b * HW + (n - NT)) * C_DIM);
    }
    const int bk = tid >> 5;
    const int bn = (tid & 31) * 4;

    float c[2][8][4];
#pragma unroll
    for (int mt = 0; mt < 2; ++mt)
#pragma unroll
        for (int nt = 0; nt < 8; ++nt)
#pragma unroll
            for (int j = 0; j < 4; ++j) c[mt][nt][j] = 0.f;

    auto load_stage = [&](int s, int k0) {
        unsigned ad = smem_u32(&Asb[s * A_STG + aRow * A_LD + aK]);
        unsigned bd = smem_u32(&Bsb[s * B_STG + bk * B_LD + bn]);
        cpasync16(ad,      arp + k0 + aK,     av);
        cpasync16(ad + 16, arp + k0 + aK + 4, av);
        cpasync16(bd,                  W + (size_t)(k0 + bk)     * QKV_N + n0 + bn, true);
        cpasync16(bd + 8 * B_LD * 4,   W + (size_t)(k0 + bk + 8) * QKV_N + n0 + bn, true);
        CP_COMMIT();
    };

    const int NKT = C_DIM / 16;      // 48
    load_stage(0, 0);
    load_stage(1, 16);

    for (int kt = 0; kt < NKT; ++kt) {
        int s = kt % 3;
        if (kt + 2 < NKT) { load_stage((kt + 2) % 3, (kt + 2) * 16); CP_WAIT(2); }
        else if (kt + 1 < NKT) { CP_WAIT(1); }
        else { CP_WAIT(0); }
        __syncthreads();

        const unsigned* Au = (const unsigned*)(Asb + s * A_STG);
        const unsigned* Bu = (const unsigned*)(Bsb + s * B_STG);
#pragma unroll
        for (int ks = 0; ks < 2; ++ks) {
            unsigned a[2][4];
#pragma unroll
            for (int mt = 0; mt < 2; ++mt) {
                int mr = wm * 32 + mt * 16;
                a[mt][0] = u2tf(Au[(mr + g    ) * A_LD + ks * 8 + tig]);
                a[mt][1] = u2tf(Au[(mr + g + 8) * A_LD + ks * 8 + tig]);
                a[mt][2] = u2tf(Au[(mr + g    ) * A_LD + ks * 8 + tig + 4]);
                a[mt][3] = u2tf(Au[(mr + g + 8) * A_LD + ks * 8 + tig + 4]);
            }
            unsigned b[8][2];
#pragma unroll
            for (int nt = 0; nt < 8; ++nt) {
                int nc = wn * 64 + nt * 8 + g;
                b[nt][0] = u2tf(Bu[(ks * 8 + tig    ) * B_LD + nc]);
                b[nt][1] = u2tf(Bu[(ks * 8 + tig + 4) * B_LD + nc]);
            }
#pragma unroll
            for (int mt = 0; mt < 2; ++mt)
#pragma unroll
                for (int nt = 0; nt < 8; ++nt) mma8(c[mt][nt], a[mt], b[nt]);
        }
        __syncthreads();
    }

    float* bufs[3] = {g_q, g_k, g_v};
#pragma unroll
    for (int nt = 0; nt < 8; ++nt) {
        int col = n0 + wn * 64 + nt * 8 + tig * 2;
        int which = col / C_DIM;
        int c2 = col % C_DIM;
        int head = c2 >> 6, db = c2 & 63;
        float b0v = bias[col], b1v = bias[col + 1];
        float* buf = bufs[which];
#pragma unroll
        for (int mt = 0; mt < 2; ++mt) {
#pragma unroll
            for (int h = 0; h < 2; ++h) {
                int m = m0 + wm * 32 + mt * 16 + g + h * 8;
                if (m >= MROWS) continue;
                int bb = m / NSEQ, nn = m % NSEQ;
                float* dst = buf + (size_t)bb * (HEADS * NSEQ * HD)
                                 + (size_t)head * (NSEQ * HD)
                                 + (size_t)nn * HD + db;
                float2 v;
                v.x = c[mt][nt][h * 2 + 0] + b0v;
                v.y = c[mt][nt][h * 2 + 1] + b1v;
                *(float2*)dst = v;
            }
        }
    }
}

// ---------------------------------------------------------------------------
// K2: rel_h / rel_w bias GEMMs (SIMT fp32, small).
// ---------------------------------------------------------------------------
__global__ __launch_bounds__(256) void rel_kernel(
    const float* __restrict__ rph, const float* __restrict__ rpw)
{
    __shared__ float qs[32 * 64];
    __shared__ float RsT[64 * 33];

    const int bh = blockIdx.y;
    const int idx0 = blockIdx.x;
    const int variant = blockIdx.z;
    const int tid = threadIdx.x;

#pragma unroll
    for (int it = 0; it < 8; ++it) {
        int idx = tid + it * 256;
        int r = idx >> 6, c = idx & 63;
        int n = (variant == 0) ? (NT + idx0 * 32 + r) : (NT + r * 32 + idx0);
        qs[idx] = g_q[((size_t)bh * NSEQ + n) * HD + c];
    }
    const float* rp = (variant == 0) ? rph : rpw;
#pragma unroll
    for (int it = 0; it < 8; ++it) {
        int idx = tid + it * 256;
        int k = idx >> 6, c = idx & 63;
        RsT[c * 33 + k] = rp[(size_t)(idx0 - k + 31) * HD + c];
    }
    __syncthreads();

    const int ty = tid >> 3;
    const int txk = tid & 7;
    float acc[4] = {0.f, 0.f, 0.f, 0.f};
#pragma unroll 8
    for (int c = 0; c < 64; ++c) {
        float q = qs[ty * 64 + c];
#pragma unroll
        for (int j = 0; j < 4; ++j) acc[j] += q * RsT[c * 33 + txk * 4 + j];
    }
    float* outb = (variant == 0) ? g_relh : g_relw;
    size_t base = (variant == 0)
        ? ((((size_t)bh * 32 + idx0) * 32 + ty) * 32)
        : ((((size_t)bh * 32 + ty) * 32 + idx0) * 32);
#pragma unroll
    for (int j = 0; j < 4; ++j) outb[base + txk * 4 + j] = acc[j];
}

// ---------------------------------------------------------------------------
// K3: flash attention (sync loads, ~88KB smem, 2 CTAs/SM).
// ---------------------------------------------------------------------------
#define ATT_SM_FLOATS (3 * 64 * 68 + 64 * 72 + 2 * 64 * 32 + 3 * 64)
#define ATT_SM_BYTES  (ATT_SM_FLOATS * 4)

__global__ __launch_bounds__(256) void attn_mma_kernel()
{
    extern __shared__ float sm[];
    float* Qs   = sm;                 // [64 q][68], tf32, prescaled
    float* Ks   = Qs + 64 * 68;       // [64 key][68], tf32
    float* ps   = Ks + 64 * 68;       // [64 q][68], S then P(tf32)
    float* Vs   = ps + 64 * 68;       // [64 key][72], tf32
    float* rhs  = Vs + 64 * 72;       // [64 q][32]
    float* rws  = rhs + 64 * 32;      // [64 q][32]
    float* rowm = rws + 64 * 32;
    float* rowl = rowm + 64;
    float* rowsc = rowl + 64;

    const int tid = threadIdx.x;
    const int wid = tid >> 5, lane = tid & 31;
    const int g = lane >> 2, tig = lane & 3;
    const int wm = wid >> 1, wn = wid & 1;
    const int bh = blockIdx.y;
    const int b = bh / HEADS, head = bh % HEADS;
    const int q0 = blockIdx.x * 64;

    const float* qbase = g_q + (size_t)bh * NSEQ * HD;
    const float* kbase = g_k + (size_t)bh * NSEQ * HD;
    const float* vbase = g_v + (size_t)bh * NSEQ * HD;

#pragma unroll
    for (int it = 0; it < 16; ++it) {
        int idx = tid + it * 256;
        int r = idx >> 6, d = idx & 63;
        int qg = q0 + r;
        float v = (qg < NSEQ) ? qbase[(size_t)qg * HD + d] * 0.125f : 0.f;
        Qs[r * 68 + d] = f2tff(v);
    }
#pragma unroll
    for (int it = 0; it < 8; ++it) {
        int idx = tid + it * 256;
        int r = idx >> 5, cc = idx & 31;
        int qg = q0 + r;
        float hv = 0.f, wv = 0.f;
        if (qg >= NT && qg < NSEQ) {
            int pix = qg - NT;
            int hq = pix >> 5, wq = pix & 31;
            size_t rbase = (((size_t)bh * 32 + hq) * 32 + wq) * 32;
            hv = g_relh[rbase + cc];
            wv = g_relw[rbase + cc];
        }
        rhs[idx] = hv;
        rws[idx] = wv;
    }
    if (tid < 64) { rowm[tid] = -3.0e38f; rowl[tid] = 0.f; }

    float oc[4][4];
#pragma unroll
    for (int nt = 0; nt < 4; ++nt)
#pragma unroll
        for (int j = 0; j < 4; ++j) oc[nt][j] = 0.f;

    __syncthreads();

    for (int k0 = 0; k0 < NSEQ; k0 += 64) {
#pragma unroll
        for (int it = 0; it < 16; ++it) {
            int idx = tid + it * 256;
            int r = idx >> 6, d = idx & 63;
            int kg = k0 + r;
            float kv = 0.f, vv = 0.f;
            if (kg < NSEQ) {
                kv = kbase[(size_t)kg * HD + d];
                vv = vbase[(size_t)kg * HD + d];
            }
            Ks[r * 68 + d] = f2tff(kv);
            Vs[r * 72 + d] = f2tff(vv);
        }
        __syncthreads();

        const unsigned* Qu = (const unsigned*)Qs;
        const unsigned* Ku = (const unsigned*)Ks;

        float sc4[4][4];
#pragma unroll
        for (int nt = 0; nt < 4; ++nt)
#pragma unroll
            for (int j = 0; j < 4; ++j) sc4[nt][j] = 0.f;

#pragma unroll
        for (int ks = 0; ks < 8; ++ks) {
            unsigned a[4];
            int mr = wm * 16;
            a[0] = Qu[(mr + g    ) * 68 + ks * 8 + tig];
            a[1] = Qu[(mr + g + 8) * 68 + ks * 8 + tig];
            a[2] = Qu[(mr + g    ) * 68 + ks * 8 + tig + 4];
            a[3] = Qu[(mr + g + 8) * 68 + ks * 8 + tig + 4];
#pragma unroll
            for (int nt = 0; nt < 4; ++nt) {
                unsigned bb[2];
                int key = wn * 32 + nt * 8 + g;
                bb[0] = Ku[key * 68 + ks * 8 + tig];
                bb[1] = Ku[key * 68 + ks * 8 + tig + 4];
                mma8(sc4[nt], a, bb);
            }
        }

#pragma unroll
        for (int nt = 0; nt < 4; ++nt) {
            int col = wn * 32 + nt * 8 + tig * 2;
            int r0 = wm * 16 + g;
            *(float2*)&ps[r0 * 68 + col] = make_float2(sc4[nt][0], sc4[nt][1]);
            *(float2*)&ps[(r0 + 8) * 68 + col] = make_float2(sc4[nt][2], sc4[nt][3]);
        }
        __syncthreads();

        {
            int r = tid >> 2, tg = tid & 3;
            int qg = q0 + r;
            float vreg[16];
            float tm = -3.0e38f;
#pragma unroll
            for (int cc = 0; cc < 16; ++cc) {
                int cj = tg * 16 + cc;
                int jg = k0 + cj;
                float val = ps[r * 68 + cj];
                if (jg >= NSEQ) {
                    val = -1e30f;
                } else if (qg >= NT) {
                    if (jg < NT) val -= 100.f;
                    else {
                        int pj = jg - NT;
                        val += rhs[r * 32 + (pj >> 5)] + rws[r * 32 + (pj & 31)];
                    }
                }
                vreg[cc] = val;
                tm = fmaxf(tm, val);
            }
            tm = fmaxf(tm, __shfl_xor_sync(0xffffffffu, tm, 1));
            tm = fmaxf(tm, __shfl_xor_sync(0xffffffffu, tm, 2));
            float oldm = rowm[r];
            float newm = fmaxf(oldm, tm);
            float sum = 0.f;
#pragma unroll
            for (int cc = 0; cc < 16; ++cc) {
                float p = __expf(vreg[cc] - newm);
                sum += p;
                ps[r * 68 + tg * 16 + cc] = f2tff(p);
            }
            sum += __shfl_xor_sync(0xffffffffu, sum, 1);
            sum += __shfl_xor_sync(0xffffffffu, sum, 2);
            if (tg == 0) {
                float s = __expf(oldm - newm);
                rowsc[r] = s;
                rowl[r] = rowl[r] * s + sum;
                rowm[r] = newm;
            }
        }
        __syncthreads();

        const unsigned* pu = (const unsigned*)ps;
        const unsigned* Vu = (const unsigned*)Vs;
        float s0 = rowsc[wm * 16 + g], s1 = rowsc[wm * 16 + g + 8];
#pragma unroll
        for (int nt = 0; nt < 4; ++nt) {
            oc[nt][0] *= s0; oc[nt][1] *= s0;
            oc[nt][2] *= s1; oc[nt][3] *= s1;
        }
#pragma unroll
        for (int ks = 0; ks < 8; ++ks) {
            unsigned a[4];
            int mr = wm * 16;
            a[0] = pu[(mr + g    ) * 68 + ks * 8 + tig];
            a[1] = pu[(mr + g + 8) * 68 + ks * 8 + tig];
            a[2] = pu[(mr + g    ) * 68 + ks * 8 + tig + 4];
            a[3] = pu[(mr + g + 8) * 68 + ks * 8 + tig + 4];
#pragma unroll
            for (int nt = 0; nt < 4; ++nt) {
                unsigned bb[2];
                int dcol = wn * 32 + nt * 8 + g;
                bb[0] = Vu[(ks * 8 + tig    ) * 72 + dcol];
                bb[1] = Vu[(ks * 8 + tig + 4) * 72 + dcol];
                mma8(oc[nt], a, bb);
            }
        }
        __syncthreads();
    }

    {
        int r0 = wm * 16 + g, r1 = r0 + 8;
        int qg0 = q0 + r0, qg1 = q0 + r1;
        float inv0 = (qg0 < NSEQ) ? (1.f / rowl[r0]) : 0.f;
        float inv1 = (qg1 < NSEQ) ? (1.f / rowl[r1]) : 0.f;
#pragma unroll
        for (int nt = 0; nt < 4; ++nt) {
            int col = wn * 32 + nt * 8 + tig * 2;
            if (qg0 < NSEQ) {
                float2 v = make_float2(oc[nt][0] * inv0, oc[nt][1] * inv0);
                *(float2*)(g_ctx + ((size_t)b * NSEQ + qg0) * C_DIM + head * HD + col) = v;
            }
            if (qg1 < NSEQ) {
                float2 v = make_float2(oc[nt][2] * inv1, oc[nt][3] * inv1);
                *(float2*)(g_ctx + ((size_t)b * NSEQ + qg1) * C_DIM + head * HD + col) = v;
            }
        }
    }
}

// ---------------------------------------------------------------------------
// K4: output projection GEMM, 3-stage cp.async pipeline, dynamic smem.
// ---------------------------------------------------------------------------
__global__ __launch_bounds__(256) void proj_mma_kernel(
    const float* __restrict__ W, const float* __restrict__ bias,
    float* __restrict__ out)
{
    extern __shared__ float dynsm[];
    float* Asb = dynsm;
    float* Bsb = dynsm + 3 * A_STG;

    const int m0 = blockIdx.y * 128;
    const int n0 = blockIdx.x * 128;
    const int tid = threadIdx.x;
    const int wid = tid >> 5, lane = tid & 31;
    const int g = lane >> 2, tig = lane & 3;
    const int wm = wid >> 1, wn = wid & 1;

    const int aRow = tid >> 1;
    const int aK   = (tid & 1) * 8;
    const int am   = m0 + aRow;
    const bool av  = (am < MROWS);
    const float* arp = g_ctx + (size_t)(av ? am : 0) * C_DIM;

    const int bk = tid >> 5;
    const int bn = (tid & 31) * 4;

    float c[2][8][4];
#pragma unroll
    for (int mt = 0; mt < 2; ++mt)
#pragma unroll
        for (int nt = 0; nt < 8; ++nt)
#pragma unroll
            for (int j = 0; j < 4; ++j) c[mt][nt][j] = 0.f;

    auto load_stage = [&](int s, int k0) {
        unsigned ad = smem_u32(&Asb[s * A_STG + aRow * A_LD + aK]);
        unsigned bd = smem_u32(&Bsb[s * B_STG + bk * B_LD + bn]);
        cpasync16(ad,      arp + k0 + aK,     av);
        cpasync16(ad + 16, arp + k0 + aK + 4, av);
        cpasync16(bd,                 W + (size_t)(k0 + bk)     * C_DIM + n0 + bn, true);
        cpasync16(bd + 8 * B_LD * 4,  W + (size_t)(k0 + bk + 8) * C_DIM + n0 + bn, true);
        CP_COMMIT();
    };

    const int NKT = C_DIM / 16;
    load_stage(0, 0);
    load_stage(1, 16);

    for (int kt = 0; kt < NKT; ++kt) {
        int s = kt % 3;
        if (kt + 2 < NKT) { load_stage((kt + 2) % 3, (kt + 2) * 16); CP_WAIT(2); }
        else if (kt + 1 < NKT) { CP_WAIT(1); }
        else { CP_WAIT(0); }
        __syncthreads();

        const unsigned* Au = (const unsigned*)(Asb + s * A_STG);
        const unsigned* Bu = (const unsigned*)(Bsb + s * B_STG);
#pragma unroll
        for (int ks = 0; ks < 2; ++ks) {
            unsigned a[2][4];
#pragma unroll
            for (int mt = 0; mt < 2; ++mt) {
                int mr = wm * 32 + mt * 16;
                a[mt][0] = u2tf(Au[(mr + g    ) * A_LD + ks * 8 + tig]);
                a[mt][1] = u2tf(Au[(mr + g + 8) * A_LD + ks * 8 + tig]);
                a[mt][2] = u2tf(Au[(mr + g    ) * A_LD + ks * 8 + tig + 4]);
                a[mt][3] = u2tf(Au[(mr + g + 8) * A_LD + ks * 8 + tig + 4]);
            }
            unsigned b[8][2];
#pragma unroll
            for (int nt = 0; nt < 8; ++nt) {
                int nc = wn * 64 + nt * 8 + g;
                b[nt][0] = u2tf(Bu[(ks * 8 + tig    ) * B_LD + nc]);
                b[nt][1] = u2tf(Bu[(ks * 8 + tig + 4) * B_LD + nc]);
            }
#pragma unroll
            for (int mt = 0; mt < 2; ++mt)
#pragma unroll
                for (int nt = 0; nt < 8; ++nt) mma8(c[mt][nt], a[mt], b[nt]);
        }
        __syncthreads();
    }

#pragma unroll
    for (int nt = 0; nt < 8; ++nt) {
        int col = n0 + wn * 64 + nt * 8 + tig * 2;
        float b0v = bias[col], b1v = bias[col + 1];
#pragma unroll
        for (int mt = 0; mt < 2; ++mt) {
#pragma unroll
            for (int h = 0; h < 2; ++h) {
                int m = m0 + wm * 32 + mt * 16 + g + h * 8;
                if (m >= MROWS) continue;
                int bb = m / NSEQ, nn = m % NSEQ;
                float* dst = (nn < NT)
                    ? (out + XOUT_ELEMS + ((size_t)bb * NT + nn) * C_DIM)
                    : (out + ((size_t)bb * HW + (nn - NT)) * C_DIM);
                float2 v;
                v.x = c[mt][nt][h * 2 + 0] + b0v;
                v.y = c[mt][nt][h * 2 + 1] + b1v;
                *(float2*)(dst + col) = v;
            }
        }
    }
}

// ---------------------------------------------------------------------------
extern "C" void kernel_launch(void* const* d_in, const int* in_sizes, int n_in,
                              void* d_out, int out_size)
{
    const float* x      = (const float*)d_in[0];
    const float* vp     = (const float*)d_in[1];
    const float* qkv_w  = (const float*)d_in[2];
    const float* qkv_b  = (const float*)d_in[3];
    const float* proj_w = (const float*)d_in[4];
    const float* proj_b = (const float*)d_in[5];
    const float* rph    = (const float*)d_in[6];
    const float* rpw    = (const float*)d_in[7];
    float* out = (float*)d_out;

    (void)in_sizes; (void)n_in; (void)out_size;

    cudaFuncSetAttribute(qkv_mma_kernel,
                         cudaFuncAttributeMaxDynamicSharedMemorySize,
                         GEMM_SM_BYTES);
    cudaFuncSetAttribute(proj_mma_kernel,
                         cudaFuncAttributeMaxDynamicSharedMemorySize,
                         GEMM_SM_BYTES);
    cudaFuncSetAttribute(attn_mma_kernel,
                         cudaFuncAttributeMaxDynamicSharedMemorySize,
                         ATT_SM_BYTES);

    qkv_mma_kernel<<<dim3(QKV_N / 128, (MROWS + 127) / 128), 256, GEMM_SM_BYTES>>>(x, vp, qkv_w, qkv_b);
    rel_kernel<<<dim3(32, BHN, 2), 256>>>(rph, rpw);
    attn_mma_kernel<<<dim3((NSEQ + 63) / 64, BHN), 256, ATT_SM_BYTES>>>();
    proj_mma_kernel<<<dim3(C_DIM / 128, (MROWS + 127) / 128), 256, GEMM_SM_BYTES>>>(proj_w, proj_b, out);
}

// round 9
// speedup vs baseline: 1.1018x; 1.0093x over previous
#include <cuda_runtime.h>

// ---------------------------------------------------------------------------
// PromptedAttention: B=8, H=W=32, C=768, heads=12, hd=64, nt=8, N=1032
// Round 9: producer-side tf32 rounding — no cvt in any mma hot loop.
// ---------------------------------------------------------------------------

#define BATCH     8
#define HEADS     12
#define HD        64
#define C_DIM     768
#define NT        8
#define HW        1024
#define NSEQ      1032
#define BHN       96
#define MROWS     8256
#define QKV_N     2304
#define XOUT_ELEMS 6291456

__device__ float g_q[BHN * NSEQ * HD];
__device__ float g_k[BHN * NSEQ * HD];
__device__ float g_v[BHN * NSEQ * HD];
__device__ float g_relh[BHN * 32 * 32 * 32];
__device__ float g_relw[BHN * 32 * 32 * 32];
__device__ float g_ctx[MROWS * C_DIM];
__device__ float g_xs[MROWS * C_DIM];          // rounded concat(vp, x)
__device__ float g_wq[C_DIM * QKV_N];          // rounded qkv_w
__device__ float g_wp[C_DIM * C_DIM];          // rounded proj_w

__device__ __forceinline__ unsigned f2tf(float f) {
    unsigned u;
    asm("cvt.rna.tf32.f32 %0, %1;" : "=r"(u) : "f"(f));
    return u;
}
__device__ __forceinline__ float f2tff(float f) { return __uint_as_float(f2tf(f)); }

__device__ __forceinline__ void mma8(float* c, const unsigned* a, const unsigned* b) {
    asm volatile(
        "mma.sync.aligned.m16n8k8.row.col.f32.tf32.tf32.f32 "
        "{%0,%1,%2,%3}, {%4,%5,%6,%7}, {%8,%9}, {%0,%1,%2,%3};\n"
        : "+f"(c[0]), "+f"(c[1]), "+f"(c[2]), "+f"(c[3])
        : "r"(a[0]), "r"(a[1]), "r"(a[2]), "r"(a[3]), "r"(b[0]), "r"(b[1]));
}

__device__ __forceinline__ unsigned smem_u32(const void* p) {
    return (unsigned)__cvta_generic_to_shared(p);
}
__device__ __forceinline__ void cpasync16(unsigned dst, const void* src, bool pred) {
    asm volatile("cp.async.cg.shared.global [%0], [%1], 16, %2;\n"
                 :: "r"(dst), "l"(src), "r"(pred ? 16 : 0));
}
#define CP_COMMIT() asm volatile("cp.async.commit_group;\n" ::: "memory")
#define CP_WAIT(N)  asm volatile("cp.async.wait_group %0;\n" :: "n"(N) : "memory")

#define A_LD 20
#define B_LD 136
#define A_STG (128 * A_LD)
#define B_STG (16 * B_LD)
#define GEMM_SM_BYTES (3 * (A_STG + B_STG) * 4)   // 56832

// ---------------------------------------------------------------------------
// K0a: build rounded concat g_xs.
// ---------------------------------------------------------------------------
__global__ __launch_bounds__(256) void prep_xs_kernel(
    const float* __restrict__ x, const float* __restrict__ vp)
{
    const int F4 = C_DIM / 4;               // 192
    const int total = MROWS * F4;
    for (int idx = blockIdx.x * 256 + threadIdx.x; idx < total;
         idx += gridDim.x * 256) {
        int row = idx / F4;
        int f4 = idx - row * F4;
        int b = row / NSEQ, n = row % NSEQ;
        const float4* src = (n < NT)
            ? (const float4*)(vp + ((size_t)b * NT + n) * C_DIM)
            : (const float4*)(x + ((size_t)b * HW + (n - NT)) * C_DIM);
        float4 t = src[f4];
        float4 o;
        o.x = f2tff(t.x); o.y = f2tff(t.y); o.z = f2tff(t.z); o.w = f2tff(t.w);
        ((float4*)g_xs)[idx] = o;
    }
}

// K0b: round both weight matrices.
__global__ __launch_bounds__(256) void prep_w_kernel(
    const float* __restrict__ wq, const float* __restrict__ wp)
{
    const int T1 = C_DIM * QKV_N / 4;       // 442368
    const int T2 = C_DIM * C_DIM / 4;       // 147456
    for (int idx = blockIdx.x * 256 + threadIdx.x; idx < T1 + T2;
         idx += gridDim.x * 256) {
        float4 t;
        float4* dst;
        if (idx < T1) { t = ((const float4*)wq)[idx]; dst = (float4*)g_wq + idx; }
        else { t = ((const float4*)wp)[idx - T1]; dst = (float4*)g_wp + (idx - T1); }
        float4 o;
        o.x = f2tff(t.x); o.y = f2tff(t.y); o.z = f2tff(t.z); o.w = f2tff(t.w);
        *dst = o;
    }
}

// ---------------------------------------------------------------------------
// K1: fused QKV GEMM (pre-rounded inputs), 3-stage cp.async, dynamic smem.
// ---------------------------------------------------------------------------
__global__ __launch_bounds__(256) void qkv_mma_kernel(const float* __restrict__ bias)
{
    extern __shared__ float dynsm[];
    float* Asb = dynsm;
    float* Bsb = dynsm + 3 * A_STG;

    const int m0 = blockIdx.y * 128;
    const int n0 = blockIdx.x * 128;
    const int tid = threadIdx.x;
    const int wid = tid >> 5, lane = tid & 31;
    const int g = lane >> 2, tig = lane & 3;
    const int wm = wid >> 1, wn = wid & 1;

    const int aRow = tid >> 1;
    const int aK   = (tid & 1) * 8;
    const int am   = m0 + aRow;
    const bool av  = (am < MROWS);
    const float* arp = g_xs + (size_t)(av ? am : 0) * C_DIM;

    const int bk = tid >> 5;
    const int bn = (tid & 31) * 4;

    float c[2][8][4];
#pragma unroll
    for (int mt = 0; mt < 2; ++mt)
#pragma unroll
        for (int nt = 0; nt < 8; ++nt)
#pragma unroll
            for (int j = 0; j < 4; ++j) c[mt][nt][j] = 0.f;

    auto load_stage = [&](int s, int k0) {
        unsigned ad = smem_u32(&Asb[s * A_STG + aRow * A_LD + aK]);
        unsigned bd = smem_u32(&Bsb[s * B_STG + bk * B_LD + bn]);
        cpasync16(ad,      arp + k0 + aK,     av);
        cpasync16(ad + 16, arp + k0 + aK + 4, av);
        cpasync16(bd,                 g_wq + (size_t)(k0 + bk)     * QKV_N + n0 + bn, true);
        cpasync16(bd + 8 * B_LD * 4,  g_wq + (size_t)(k0 + bk + 8) * QKV_N + n0 + bn, true);
        CP_COMMIT();
    };

    const int NKT = C_DIM / 16;      // 48
    load_stage(0, 0);
    load_stage(1, 16);

    for (int kt = 0; kt < NKT; ++kt) {
        int s = kt % 3;
        if (kt + 2 < NKT) { load_stage((kt + 2) % 3, (kt + 2) * 16); CP_WAIT(2); }
        else if (kt + 1 < NKT) { CP_WAIT(1); }
        else { CP_WAIT(0); }
        __syncthreads();

        const unsigned* Au = (const unsigned*)(Asb + s * A_STG);
        const unsigned* Bu = (const unsigned*)(Bsb + s * B_STG);
#pragma unroll
        for (int ks = 0; ks < 2; ++ks) {
            unsigned a[2][4];
#pragma unroll
            for (int mt = 0; mt < 2; ++mt) {
                int mr = wm * 32 + mt * 16;
                a[mt][0] = Au[(mr + g    ) * A_LD + ks * 8 + tig];
                a[mt][1] = Au[(mr + g + 8) * A_LD + ks * 8 + tig];
                a[mt][2] = Au[(mr + g    ) * A_LD + ks * 8 + tig + 4];
                a[mt][3] = Au[(mr + g + 8) * A_LD + ks * 8 + tig + 4];
            }
            unsigned b[8][2];
#pragma unroll
            for (int nt = 0; nt < 8; ++nt) {
                int nc = wn * 64 + nt * 8 + g;
                b[nt][0] = Bu[(ks * 8 + tig    ) * B_LD + nc];
                b[nt][1] = Bu[(ks * 8 + tig + 4) * B_LD + nc];
            }
#pragma unroll
            for (int mt = 0; mt < 2; ++mt)
#pragma unroll
                for (int nt = 0; nt < 8; ++nt) mma8(c[mt][nt], a[mt], b[nt]);
        }
        __syncthreads();
    }

    // epilogue: add bias, tf32-round, scatter to g_q/g_k/g_v
    float* bufs[3] = {g_q, g_k, g_v};
#pragma unroll
    for (int nt = 0; nt < 8; ++nt) {
        int col = n0 + wn * 64 + nt * 8 + tig * 2;
        int which = col / C_DIM;
        int c2 = col % C_DIM;
        int head = c2 >> 6, db = c2 & 63;
        float b0v = bias[col], b1v = bias[col + 1];
        float* buf = bufs[which];
#pragma unroll
        for (int mt = 0; mt < 2; ++mt) {
#pragma unroll
            for (int h = 0; h < 2; ++h) {
                int m = m0 + wm * 32 + mt * 16 + g + h * 8;
                if (m >= MROWS) continue;
                int bb = m / NSEQ, nn = m % NSEQ;
                float* dst = buf + (size_t)bb * (HEADS * NSEQ * HD)
                                 + (size_t)head * (NSEQ * HD)
                                 + (size_t)nn * HD + db;
                float2 v;
                v.x = f2tff(c[mt][nt][h * 2 + 0] + b0v);
                v.y = f2tff(c[mt][nt][h * 2 + 1] + b1v);
                *(float2*)dst = v;
            }
        }
    }
}

// ---------------------------------------------------------------------------
// K2: rel_h / rel_w bias GEMMs (SIMT fp32, small).
// ---------------------------------------------------------------------------
__global__ __launch_bounds__(256) void rel_kernel(
    const float* __restrict__ rph, const float* __restrict__ rpw)
{
    __shared__ float qs[32 * 64];
    __shared__ float RsT[64 * 33];

    const int bh = blockIdx.y;
    const int idx0 = blockIdx.x;
    const int variant = blockIdx.z;
    const int tid = threadIdx.x;

#pragma unroll
    for (int it = 0; it < 8; ++it) {
        int idx = tid + it * 256;
        int r = idx >> 6, c = idx & 63;
        int n = (variant == 0) ? (NT + idx0 * 32 + r) : (NT + r * 32 + idx0);
        qs[idx] = g_q[((size_t)bh * NSEQ + n) * HD + c];
    }
    const float* rp = (variant == 0) ? rph : rpw;
#pragma unroll
    for (int it = 0; it < 8; ++it) {
        int idx = tid + it * 256;
        int k = idx >> 6, c = idx & 63;
        RsT[c * 33 + k] = rp[(size_t)(idx0 - k + 31) * HD + c];
    }
    __syncthreads();

    const int ty = tid >> 3;
    const int txk = tid & 7;
    float acc[4] = {0.f, 0.f, 0.f, 0.f};
#pragma unroll 8
    for (int c = 0; c < 64; ++c) {
        float q = qs[ty * 64 + c];
#pragma unroll
        for (int j = 0; j < 4; ++j) acc[j] += q * RsT[c * 33 + txk * 4 + j];
    }
    float* outb = (variant == 0) ? g_relh : g_relw;
    size_t base = (variant == 0)
        ? ((((size_t)bh * 32 + idx0) * 32 + ty) * 32)
        : ((((size_t)bh * 32 + ty) * 32 + idx0) * 32);
#pragma unroll
    for (int j = 0; j < 4; ++j) outb[base + txk * 4 + j] = acc[j];
}

// ---------------------------------------------------------------------------
// K3: flash attention (sync loads, pre-rounded Q/K/V, 2 CTAs/SM).
// ---------------------------------------------------------------------------
#define ATT_SM_FLOATS (3 * 64 * 68 + 64 * 72 + 2 * 64 * 32 + 3 * 64)
#define ATT_SM_BYTES  (ATT_SM_FLOATS * 4)

__global__ __launch_bounds__(256) void attn_mma_kernel()
{
    extern __shared__ float sm[];
    float* Qs   = sm;                 // [64 q][68], tf32, prescaled
    float* Ks   = Qs + 64 * 68;       // [64 key][68], tf32
    float* ps   = Ks + 64 * 68;       // [64 q][68], S then P(tf32)
    float* Vs   = ps + 64 * 68;       // [64 key][72], tf32
    float* rhs  = Vs + 64 * 72;       // [64 q][32]
    float* rws  = rhs + 64 * 32;      // [64 q][32]
    float* rowm = rws + 64 * 32;
    float* rowl = rowm + 64;
    float* rowsc = rowl + 64;

    const int tid = threadIdx.x;
    const int wid = tid >> 5, lane = tid & 31;
    const int g = lane >> 2, tig = lane & 3;
    const int wm = wid >> 1, wn = wid & 1;
    const int bh = blockIdx.y;
    const int b = bh / HEADS, head = bh % HEADS;
    const int q0 = blockIdx.x * 64;

    const float* qbase = g_q + (size_t)bh * NSEQ * HD;
    const float* kbase = g_k + (size_t)bh * NSEQ * HD;
    const float* vbase = g_v + (size_t)bh * NSEQ * HD;

    // Q pre-rounded; *0.125 is a power-of-2 scale (exact, stays tf32)
#pragma unroll
    for (int it = 0; it < 16; ++it) {
        int idx = tid + it * 256;
        int r = idx >> 6, d = idx & 63;
        int qg = q0 + r;
        Qs[r * 68 + d] = (qg < NSEQ) ? qbase[(size_t)qg * HD + d] * 0.125f : 0.f;
    }
#pragma unroll
    for (int it = 0; it < 8; ++it) {
        int idx = tid + it * 256;
        int r = idx >> 5, cc = idx & 31;
        int qg = q0 + r;
        float hv = 0.f, wv = 0.f;
        if (qg >= NT && qg < NSEQ) {
            int pix = qg - NT;
            int hq = pix >> 5, wq = pix & 31;
            size_t rbase = (((size_t)bh * 32 + hq) * 32 + wq) * 32;
            hv = g_relh[rbase + cc];
            wv = g_relw[rbase + cc];
        }
        rhs[idx] = hv;
        rws[idx] = wv;
    }
    if (tid < 64) { rowm[tid] = -3.0e38f; rowl[tid] = 0.f; }

    float oc[4][4];
#pragma unroll
    for (int nt = 0; nt < 4; ++nt)
#pragma unroll
        for (int j = 0; j < 4; ++j) oc[nt][j] = 0.f;

    __syncthreads();

    for (int k0 = 0; k0 < NSEQ; k0 += 64) {
        // K/V pre-rounded: plain copy
#pragma unroll
        for (int it = 0; it < 16; ++it) {
            int idx = tid + it * 256;
            int r = idx >> 6, d = idx & 63;
            int kg = k0 + r;
            float kv = 0.f, vv = 0.f;
            if (kg < NSEQ) {
                kv = kbase[(size_t)kg * HD + d];
                vv = vbase[(size_t)kg * HD + d];
            }
            Ks[r * 68 + d] = kv;
            Vs[r * 72 + d] = vv;
        }
        __syncthreads();

        const unsigned* Qu = (const unsigned*)Qs;
        const unsigned* Ku = (const unsigned*)Ks;

        float sc4[4][4];
#pragma unroll
        for (int nt = 0; nt < 4; ++nt)
#pragma unroll
            for (int j = 0; j < 4; ++j) sc4[nt][j] = 0.f;

#pragma unroll
        for (int ks = 0; ks < 8; ++ks) {
            unsigned a[4];
            int mr = wm * 16;
            a[0] = Qu[(mr + g    ) * 68 + ks * 8 + tig];
            a[1] = Qu[(mr + g + 8) * 68 + ks * 8 + tig];
            a[2] = Qu[(mr + g    ) * 68 + ks * 8 + tig + 4];
            a[3] = Qu[(mr + g + 8) * 68 + ks * 8 + tig + 4];
#pragma unroll
            for (int nt = 0; nt < 4; ++nt) {
                unsigned bb[2];
                int key = wn * 32 + nt * 8 + g;
                bb[0] = Ku[key * 68 + ks * 8 + tig];
                bb[1] = Ku[key * 68 + ks * 8 + tig + 4];
                mma8(sc4[nt], a, bb);
            }
        }

#pragma unroll
        for (int nt = 0; nt < 4; ++nt) {
            int col = wn * 32 + nt * 8 + tig * 2;
            int r0 = wm * 16 + g;
            *(float2*)&ps[r0 * 68 + col] = make_float2(sc4[nt][0], sc4[nt][1]);
            *(float2*)&ps[(r0 + 8) * 68 + col] = make_float2(sc4[nt][2], sc4[nt][3]);
        }
        __syncthreads();

        {
            int r = tid >> 2, tg = tid & 3;
            int qg = q0 + r;
            float vreg[16];
            float tm = -3.0e38f;
#pragma unroll
            for (int cc = 0; cc < 16; ++cc) {
                int cj = tg * 16 + cc;
                int jg = k0 + cj;
                float val = ps[r * 68 + cj];
                if (jg >= NSEQ) {
                    val = -1e30f;
                } else if (qg >= NT) {
                    if (jg < NT) val -= 100.f;
                    else {
                        int pj = jg - NT;
                        val += rhs[r * 32 + (pj >> 5)] + rws[r * 32 + (pj & 31)];
                    }
                }
                vreg[cc] = val;
                tm = fmaxf(tm, val);
            }
            tm = fmaxf(tm, __shfl_xor_sync(0xffffffffu, tm, 1));
            tm = fmaxf(tm, __shfl_xor_sync(0xffffffffu, tm, 2));
            float oldm = rowm[r];
            float newm = fmaxf(oldm, tm);
            float sum = 0.f;
#pragma unroll
            for (int cc = 0; cc < 16; ++cc) {
                float p = __expf(vreg[cc] - newm);
                sum += p;
                ps[r * 68 + tg * 16 + cc] = f2tff(p);
            }
            sum += __shfl_xor_sync(0xffffffffu, sum, 1);
            sum += __shfl_xor_sync(0xffffffffu, sum, 2);
            if (tg == 0) {
                float s = __expf(oldm - newm);
                rowsc[r] = s;
                rowl[r] = rowl[r] * s + sum;
                rowm[r] = newm;
            }
        }
        __syncthreads();

        const unsigned* pu = (const unsigned*)ps;
        const unsigned* Vu = (const unsigned*)Vs;
        float s0 = rowsc[wm * 16 + g], s1 = rowsc[wm * 16 + g + 8];
#pragma unroll
        for (int nt = 0; nt < 4; ++nt) {
            oc[nt][0] *= s0; oc[nt][1] *= s0;
            oc[nt][2] *= s1; oc[nt][3] *= s1;
        }
#pragma unroll
        for (int ks = 0; ks < 8; ++ks) {
            unsigned a[4];
            int mr = wm * 16;
            a[0] = pu[(mr + g    ) * 68 + ks * 8 + tig];
            a[1] = pu[(mr + g + 8) * 68 + ks * 8 + tig];
            a[2] = pu[(mr + g    ) * 68 + ks * 8 + tig + 4];
            a[3] = pu[(mr + g + 8) * 68 + ks * 8 + tig + 4];
#pragma unroll
            for (int nt = 0; nt < 4; ++nt) {
                unsigned bb[2];
                int dcol = wn * 32 + nt * 8 + g;
                bb[0] = Vu[(ks * 8 + tig    ) * 72 + dcol];
                bb[1] = Vu[(ks * 8 + tig + 4) * 72 + dcol];
                mma8(oc[nt], a, bb);
            }
        }
        __syncthreads();
    }

    // normalize + tf32-round + write context (proj consumes raw)
    {
        int r0 = wm * 16 + g, r1 = r0 + 8;
        int qg0 = q0 + r0, qg1 = q0 + r1;
        float inv0 = (qg0 < NSEQ) ? (1.f / rowl[r0]) : 0.f;
        float inv1 = (qg1 < NSEQ) ? (1.f / rowl[r1]) : 0.f;
#pragma unroll
        for (int nt = 0; nt < 4; ++nt) {
            int col = wn * 32 + nt * 8 + tig * 2;
            if (qg0 < NSEQ) {
                float2 v = make_float2(f2tff(oc[nt][0] * inv0), f2tff(oc[nt][1] * inv0));
                *(float2*)(g_ctx + ((size_t)b * NSEQ + qg0) * C_DIM + head * HD + col) = v;
            }
            if (qg1 < NSEQ) {
                float2 v = make_float2(f2tff(oc[nt][2] * inv1), f2tff(oc[nt][3] * inv1));
                *(float2*)(g_ctx + ((size_t)b * NSEQ + qg1) * C_DIM + head * HD + col) = v;
            }
        }
    }
}

// ---------------------------------------------------------------------------
// K4: output projection GEMM (pre-rounded inputs), 3-stage cp.async.
// ---------------------------------------------------------------------------
__global__ __launch_bounds__(256) void proj_mma_kernel(
    const float* __restrict__ bias, float* __restrict__ out)
{
    extern __shared__ float dynsm[];
    float* Asb = dynsm;
    float* Bsb = dynsm + 3 * A_STG;

    const int m0 = blockIdx.y * 128;
    const int n0 = blockIdx.x * 128;
    const int tid = threadIdx.x;
    const int wid = tid >> 5, lane = tid & 31;
    const int g = lane >> 2, tig = lane & 3;
    const int wm = wid >> 1, wn = wid & 1;

    const int aRow = tid >> 1;
    const int aK   = (tid & 1) * 8;
    const int am   = m0 + aRow;
    const bool av  = (am < MROWS);
    const float* arp = g_ctx + (size_t)(av ? am : 0) * C_DIM;

    const int bk = tid >> 5;
    const int bn = (tid & 31) * 4;

    float c[2][8][4];
#pragma unroll
    for (int mt = 0; mt < 2; ++mt)
#pragma unroll
        for (int nt = 0; nt < 8; ++nt)
#pragma unroll
            for (int j = 0; j < 4; ++j) c[mt][nt][j] = 0.f;

    auto load_stage = [&](int s, int k0) {
        unsigned ad = smem_u32(&Asb[s * A_STG + aRow * A_LD + aK]);
        unsigned bd = smem_u32(&Bsb[s * B_STG + bk * B_LD + bn]);
        cpasync16(ad,      arp + k0 + aK,     av);
        cpasync16(ad + 16, arp + k0 + aK + 4, av);
        cpasync16(bd,                 g_wp + (size_t)(k0 + bk)     * C_DIM + n0 + bn, true);
        cpasync16(bd + 8 * B_LD * 4,  g_wp + (size_t)(k0 + bk + 8) * C_DIM + n0 + bn, true);
        CP_COMMIT();
    };

    const int NKT = C_DIM / 16;
    load_stage(0, 0);
    load_stage(1, 16);

    for (int kt = 0; kt < NKT; ++kt) {
        int s = kt % 3;
        if (kt + 2 < NKT) { load_stage((kt + 2) % 3, (kt + 2) * 16); CP_WAIT(2); }
        else if (kt + 1 < NKT) { CP_WAIT(1); }
        else { CP_WAIT(0); }
        __syncthreads();

        const unsigned* Au = (const unsigned*)(Asb + s * A_STG);
        const unsigned* Bu = (const unsigned*)(Bsb + s * B_STG);
#pragma unroll
        for (int ks = 0; ks < 2; ++ks) {
            unsigned a[2][4];
#pragma unroll
            for (int mt = 0; mt < 2; ++mt) {
                int mr = wm * 32 + mt * 16;
                a[mt][0] = Au[(mr + g    ) * A_LD + ks * 8 + tig];
                a[mt][1] = Au[(mr + g + 8) * A_LD + ks * 8 + tig];
                a[mt][2] = Au[(mr + g    ) * A_LD + ks * 8 + tig + 4];
                a[mt][3] = Au[(mr + g + 8) * A_LD + ks * 8 + tig + 4];
            }
            unsigned b[8][2];
#pragma unroll
            for (int nt = 0; nt < 8; ++nt) {
                int nc = wn * 64 + nt * 8 + g;
                b[nt][0] = Bu[(ks * 8 + tig    ) * B_LD + nc];
                b[nt][1] = Bu[(ks * 8 + tig + 4) * B_LD + nc];
            }
#pragma unroll
            for (int mt = 0; mt < 2; ++mt)
#pragma unroll
                for (int nt = 0; nt < 8; ++nt) mma8(c[mt][nt], a[mt], b[nt]);
        }
        __syncthreads();
    }

#pragma unroll
    for (int nt = 0; nt < 8; ++nt) {
        int col = n0 + wn * 64 + nt * 8 + tig * 2;
        float b0v = bias[col], b1v = bias[col + 1];
#pragma unroll
        for (int mt = 0; mt < 2; ++mt) {
#pragma unroll
            for (int h = 0; h < 2; ++h) {
                int m = m0 + wm * 32 + mt * 16 + g + h * 8;
                if (m >= MROWS) continue;
                int bb = m / NSEQ, nn = m % NSEQ;
                float* dst = (nn < NT)
                    ? (out + XOUT_ELEMS + ((size_t)bb * NT + nn) * C_DIM)
                    : (out + ((size_t)bb * HW + (nn - NT)) * C_DIM);
                float2 v;
                v.x = c[mt][nt][h * 2 + 0] + b0v;
                v.y = c[mt][nt][h * 2 + 1] + b1v;
                *(float2*)(dst + col) = v;
            }
        }
    }
}

// ---------------------------------------------------------------------------
extern "C" void kernel_launch(void* const* d_in, const int* in_sizes, int n_in,
                              void* d_out, int out_size)
{
    const float* x      = (const float*)d_in[0];
    const float* vp     = (const float*)d_in[1];
    const float* qkv_w  = (const float*)d_in[2];
    const float* qkv_b  = (const float*)d_in[3];
    const float* proj_w = (const float*)d_in[4];
    const float* proj_b = (const float*)d_in[5];
    const float* rph    = (const float*)d_in[6];
    const float* rpw    = (const float*)d_in[7];
    float* out = (float*)d_out;

    (void)in_sizes; (void)n_in; (void)out_size;

    cudaFuncSetAttribute(qkv_mma_kernel,
                         cudaFuncAttributeMaxDynamicSharedMemorySize,
                         GEMM_SM_BYTES);
    cudaFuncSetAttribute(proj_mma_kernel,
                         cudaFuncAttributeMaxDynamicSharedMemorySize,
                         GEMM_SM_BYTES);
    cudaFuncSetAttribute(attn_mma_kernel,
                         cudaFuncAttributeMaxDynamicSharedMemorySize,
                         ATT_SM_BYTES);

    prep_xs_kernel<<<1184, 256>>>(x, vp);
    prep_w_kernel<<<1184, 256>>>(qkv_w, proj_w);
    qkv_mma_kernel<<<dim3(QKV_N / 128, (MROWS + 127) / 128), 256, GEMM_SM_BYTES>>>(qkv_b);
    rel_kernel<<<dim3(32, BHN, 2), 256>>>(rph, rpw);
    attn_mma_kernel<<<dim3((NSEQ + 63) / 64, BHN), 256, ATT_SM_BYTES>>>();
    proj_mma_kernel<<<dim3(C_DIM / 128, (MROWS + 127) / 128), 256, GEMM_SM_BYTES>>>(proj_b, out);
}

// round 10
// speedup vs baseline: 1.1837x; 1.0743x over previous
#include <cuda_runtime.h>

// ---------------------------------------------------------------------------
// PromptedAttention: B=8, H=W=32, C=768, heads=12, hd=64, nt=8, N=1032
// Round 10: register-blocked rel_kernel + float4-vectorized attention staging.
// ---------------------------------------------------------------------------

#define BATCH     8
#define HEADS     12
#define HD        64
#define C_DIM     768
#define NT        8
#define HW        1024
#define NSEQ      1032
#define BHN       96
#define MROWS     8256
#define QKV_N     2304
#define XOUT_ELEMS 6291456

__device__ float g_q[BHN * NSEQ * HD];
__device__ float g_k[BHN * NSEQ * HD];
__device__ float g_v[BHN * NSEQ * HD];
__device__ float g_relh[BHN * 32 * 32 * 32];
__device__ float g_relw[BHN * 32 * 32 * 32];
__device__ float g_ctx[MROWS * C_DIM];
__device__ float g_xs[MROWS * C_DIM];
__device__ float g_wq[C_DIM * QKV_N];
__device__ float g_wp[C_DIM * C_DIM];

__device__ __forceinline__ unsigned f2tf(float f) {
    unsigned u;
    asm("cvt.rna.tf32.f32 %0, %1;" : "=r"(u) : "f"(f));
    return u;
}
__device__ __forceinline__ float f2tff(float f) { return __uint_as_float(f2tf(f)); }

__device__ __forceinline__ void mma8(float* c, const unsigned* a, const unsigned* b) {
    asm volatile(
        "mma.sync.aligned.m16n8k8.row.col.f32.tf32.tf32.f32 "
        "{%0,%1,%2,%3}, {%4,%5,%6,%7}, {%8,%9}, {%0,%1,%2,%3};\n"
        : "+f"(c[0]), "+f"(c[1]), "+f"(c[2]), "+f"(c[3])
        : "r"(a[0]), "r"(a[1]), "r"(a[2]), "r"(a[3]), "r"(b[0]), "r"(b[1]));
}

__device__ __forceinline__ unsigned smem_u32(const void* p) {
    return (unsigned)__cvta_generic_to_shared(p);
}
__device__ __forceinline__ void cpasync16(unsigned dst, const void* src, bool pred) {
    asm volatile("cp.async.cg.shared.global [%0], [%1], 16, %2;\n"
                 :: "r"(dst), "l"(src), "r"(pred ? 16 : 0));
}
#define CP_COMMIT() asm volatile("cp.async.commit_group;\n" ::: "memory")
#define CP_WAIT(N)  asm volatile("cp.async.wait_group %0;\n" :: "n"(N) : "memory")

#define A_LD 20
#define B_LD 136
#define A_STG (128 * A_LD)
#define B_STG (16 * B_LD)
#define GEMM_SM_BYTES (3 * (A_STG + B_STG) * 4)   // 56832

// ---------------------------------------------------------------------------
// K0a: build rounded concat g_xs.
// ---------------------------------------------------------------------------
__global__ __launch_bounds__(256) void prep_xs_kernel(
    const float* __restrict__ x, const float* __restrict__ vp)
{
    const int F4 = C_DIM / 4;
    const int total = MROWS * F4;
    for (int idx = blockIdx.x * 256 + threadIdx.x; idx < total;
         idx += gridDim.x * 256) {
        int row = idx / F4;
        int f4 = idx - row * F4;
        int b = row / NSEQ, n = row % NSEQ;
        const float4* src = (n < NT)
            ? (const float4*)(vp + ((size_t)b * NT + n) * C_DIM)
            : (const float4*)(x + ((size_t)b * HW + (n - NT)) * C_DIM);
        float4 t = src[f4];
        float4 o;
        o.x = f2tff(t.x); o.y = f2tff(t.y); o.z = f2tff(t.z); o.w = f2tff(t.w);
        ((float4*)g_xs)[idx] = o;
    }
}

// K0b: round both weight matrices.
__global__ __launch_bounds__(256) void prep_w_kernel(
    const float* __restrict__ wq, const float* __restrict__ wp)
{
    const int T1 = C_DIM * QKV_N / 4;
    const int T2 = C_DIM * C_DIM / 4;
    for (int idx = blockIdx.x * 256 + threadIdx.x; idx < T1 + T2;
         idx += gridDim.x * 256) {
        float4 t;
        float4* dst;
        if (idx < T1) { t = ((const float4*)wq)[idx]; dst = (float4*)g_wq + idx; }
        else { t = ((const float4*)wp)[idx - T1]; dst = (float4*)g_wp + (idx - T1); }
        float4 o;
        o.x = f2tff(t.x); o.y = f2tff(t.y); o.z = f2tff(t.z); o.w = f2tff(t.w);
        *dst = o;
    }
}

// ---------------------------------------------------------------------------
// K1: fused QKV GEMM (pre-rounded inputs), 3-stage cp.async, dynamic smem.
// ---------------------------------------------------------------------------
__global__ __launch_bounds__(256) void qkv_mma_kernel(const float* __restrict__ bias)
{
    extern __shared__ float dynsm[];
    float* Asb = dynsm;
    float* Bsb = dynsm + 3 * A_STG;

    const int m0 = blockIdx.y * 128;
    const int n0 = blockIdx.x * 128;
    const int tid = threadIdx.x;
    const int wid = tid >> 5, lane = tid & 31;
    const int g = lane >> 2, tig = lane & 3;
    const int wm = wid >> 1, wn = wid & 1;

    const int aRow = tid >> 1;
    const int aK   = (tid & 1) * 8;
    const int am   = m0 + aRow;
    const bool av  = (am < MROWS);
    const float* arp = g_xs + (size_t)(av ? am : 0) * C_DIM;

    const int bk = tid >> 5;
    const int bn = (tid & 31) * 4;

    float c[2][8][4];
#pragma unroll
    for (int mt = 0; mt < 2; ++mt)
#pragma unroll
        for (int nt = 0; nt < 8; ++nt)
#pragma unroll
            for (int j = 0; j < 4; ++j) c[mt][nt][j] = 0.f;

    auto load_stage = [&](int s, int k0) {
        unsigned ad = smem_u32(&Asb[s * A_STG + aRow * A_LD + aK]);
        unsigned bd = smem_u32(&Bsb[s * B_STG + bk * B_LD + bn]);
        cpasync16(ad,      arp + k0 + aK,     av);
        cpasync16(ad + 16, arp + k0 + aK + 4, av);
        cpasync16(bd,                 g_wq + (size_t)(k0 + bk)     * QKV_N + n0 + bn, true);
        cpasync16(bd + 8 * B_LD * 4,  g_wq + (size_t)(k0 + bk + 8) * QKV_N + n0 + bn, true);
        CP_COMMIT();
    };

    const int NKT = C_DIM / 16;
    load_stage(0, 0);
    load_stage(1, 16);

    for (int kt = 0; kt < NKT; ++kt) {
        int s = kt % 3;
        if (kt + 2 < NKT) { load_stage((kt + 2) % 3, (kt + 2) * 16); CP_WAIT(2); }
        else if (kt + 1 < NKT) { CP_WAIT(1); }
        else { CP_WAIT(0); }
        __syncthreads();

        const unsigned* Au = (const unsigned*)(Asb + s * A_STG);
        const unsigned* Bu = (const unsigned*)(Bsb + s * B_STG);
#pragma unroll
        for (int ks = 0; ks < 2; ++ks) {
            unsigned a[2][4];
#pragma unroll
            for (int mt = 0; mt < 2; ++mt) {
                int mr = wm * 32 + mt * 16;
                a[mt][0] = Au[(mr + g    ) * A_LD + ks * 8 + tig];
                a[mt][1] = Au[(mr + g + 8) * A_LD + ks * 8 + tig];
                a[mt][2] = Au[(mr + g    ) * A_LD + ks * 8 + tig + 4];
                a[mt][3] = Au[(mr + g + 8) * A_LD + ks * 8 + tig + 4];
            }
            unsigned b[8][2];
#pragma unroll
            for (int nt = 0; nt < 8; ++nt) {
                int nc = wn * 64 + nt * 8 + g;
                b[nt][0] = Bu[(ks * 8 + tig    ) * B_LD + nc];
                b[nt][1] = Bu[(ks * 8 + tig + 4) * B_LD + nc];
            }
#pragma unroll
            for (int mt = 0; mt < 2; ++mt)
#pragma unroll
                for (int nt = 0; nt < 8; ++nt) mma8(c[mt][nt], a[mt], b[nt]);
        }
        __syncthreads();
    }

    float* bufs[3] = {g_q, g_k, g_v};
#pragma unroll
    for (int nt = 0; nt < 8; ++nt) {
        int col = n0 + wn * 64 + nt * 8 + tig * 2;
        int which = col / C_DIM;
        int c2 = col % C_DIM;
        int head = c2 >> 6, db = c2 & 63;
        float b0v = bias[col], b1v = bias[col + 1];
        float* buf = bufs[which];
#pragma unroll
        for (int mt = 0; mt < 2; ++mt) {
#pragma unroll
            for (int h = 0; h < 2; ++h) {
                int m = m0 + wm * 32 + mt * 16 + g + h * 8;
                if (m >= MROWS) continue;
                int bb = m / NSEQ, nn = m % NSEQ;
                float* dst = buf + (size_t)bb * (HEADS * NSEQ * HD)
                                 + (size_t)head * (NSEQ * HD)
                                 + (size_t)nn * HD + db;
                float2 v;
                v.x = f2tff(c[mt][nt][h * 2 + 0] + b0v);
                v.y = f2tff(c[mt][nt][h * 2 + 1] + b1v);
                *(float2*)dst = v;
            }
        }
    }
}

// ---------------------------------------------------------------------------
// K2: rel bias GEMMs — register-blocked: 64 threads, 4x4 outputs each.
// ---------------------------------------------------------------------------
__global__ __launch_bounds__(64) void rel_kernel(
    const float* __restrict__ rph, const float* __restrict__ rpw)
{
    __shared__ float qs[32 * 65];     // [row][c], ld=65 (tr-conflict-free)
    __shared__ float RsT[64 * 33];    // [c][k]

    const int bh = blockIdx.y;
    const int idx0 = blockIdx.x;      // h (variant 0) or w (variant 1)
    const int variant = blockIdx.z;
    const int tid = threadIdx.x;      // 0..63

    // load q tile: 2048 elements, 32 per thread, coalesced per row
#pragma unroll
    for (int it = 0; it < 32; ++it) {
        int idx = tid + it * 64;
        int r = idx >> 6, c = idx & 63;
        int n = (variant == 0) ? (NT + idx0 * 32 + r) : (NT + r * 32 + idx0);
        qs[r * 65 + c] = g_q[((size_t)bh * NSEQ + n) * HD + c];
    }
    const float* rp = (variant == 0) ? rph : rpw;
#pragma unroll
    for (int it = 0; it < 32; ++it) {
        int idx = tid + it * 64;
        int k = idx >> 6, c = idx & 63;
        RsT[c * 33 + k] = rp[(size_t)(idx0 - k + 31) * HD + c];
    }
    __syncthreads();

    const int tr = tid >> 3;          // 0..7 -> rows tr*4..tr*4+3
    const int tk = tid & 7;           // 0..7 -> ks tk*4..tk*4+3
    float acc[4][4];
#pragma unroll
    for (int i = 0; i < 4; ++i)
#pragma unroll
        for (int j = 0; j < 4; ++j) acc[i][j] = 0.f;

#pragma unroll 4
    for (int c = 0; c < 64; ++c) {
        float q[4], rv[4];
#pragma unroll
        for (int i = 0; i < 4; ++i) q[i] = qs[(tr * 4 + i) * 65 + c];
#pragma unroll
        for (int j = 0; j < 4; ++j) rv[j] = RsT[c * 33 + tk * 4 + j];
#pragma unroll
        for (int i = 0; i < 4; ++i)
#pragma unroll
            for (int j = 0; j < 4; ++j) acc[i][j] += q[i] * rv[j];
    }

    float* outb = (variant == 0) ? g_relh : g_relw;
#pragma unroll
    for (int i = 0; i < 4; ++i) {
        int row = tr * 4 + i;
        size_t base = (variant == 0)
            ? ((((size_t)bh * 32 + idx0) * 32 + row) * 32)
            : ((((size_t)bh * 32 + row) * 32 + idx0) * 32);
        float4 v;
        v.x = acc[i][0]; v.y = acc[i][1]; v.z = acc[i][2]; v.w = acc[i][3];
        *(float4*)(outb + base + tk * 4) = v;
    }
}

// ---------------------------------------------------------------------------
// K3: flash attention (sync float4 staging, pre-rounded Q/K/V, 2 CTAs/SM).
// ---------------------------------------------------------------------------
#define ATT_SM_FLOATS (3 * 64 * 68 + 64 * 72 + 2 * 64 * 32 + 3 * 64)
#define ATT_SM_BYTES  (ATT_SM_FLOATS * 4)

__global__ __launch_bounds__(256) void attn_mma_kernel()
{
    extern __shared__ float sm[];
    float* Qs   = sm;                 // [64 q][68], tf32, prescaled
    float* Ks   = Qs + 64 * 68;       // [64 key][68], tf32
    float* ps   = Ks + 64 * 68;       // [64 q][68], S then P(tf32)
    float* Vs   = ps + 64 * 68;       // [64 key][72], tf32
    float* rhs  = Vs + 64 * 72;       // [64 q][32]
    float* rws  = rhs + 64 * 32;      // [64 q][32]
    float* rowm = rws + 64 * 32;
    float* rowl = rowm + 64;
    float* rowsc = rowl + 64;

    const int tid = threadIdx.x;
    const int wid = tid >> 5, lane = tid & 31;
    const int g = lane >> 2, tig = lane & 3;
    const int wm = wid >> 1, wn = wid & 1;
    const int bh = blockIdx.y;
    const int b = bh / HEADS, head = bh % HEADS;
    const int q0 = blockIdx.x * 64;

    const float* qbase = g_q + (size_t)bh * NSEQ * HD;
    const float* kbase = g_k + (size_t)bh * NSEQ * HD;
    const float* vbase = g_v + (size_t)bh * NSEQ * HD;

    // Q tile: float4 staging, *0.125 exact power-of-2 scale
#pragma unroll
    for (int it = 0; it < 4; ++it) {
        int idx = tid + it * 256;       // 1024 float4s
        int r = idx >> 4, d = (idx & 15) * 4;
        int qg = q0 + r;
        float4 t = (qg < NSEQ) ? *(const float4*)(qbase + (size_t)qg * HD + d)
                               : make_float4(0.f, 0.f, 0.f, 0.f);
        float4 o;
        o.x = t.x * 0.125f; o.y = t.y * 0.125f;
        o.z = t.z * 0.125f; o.w = t.w * 0.125f;
        *(float4*)&Qs[r * 68 + d] = o;
    }
    // rel bias rows: float4 staging
#pragma unroll
    for (int it = 0; it < 2; ++it) {
        int idx = tid + it * 256;       // 512 float4s
        int r = idx >> 3, c4 = (idx & 7) * 4;
        int qg = q0 + r;
        float4 hv = make_float4(0.f, 0.f, 0.f, 0.f), wv = hv;
        if (qg >= NT && qg < NSEQ) {
            int pix = qg - NT;
            int hq = pix >> 5, wq = pix & 31;
            size_t rbase = (((size_t)bh * 32 + hq) * 32 + wq) * 32;
            hv = *(const float4*)(g_relh + rbase + c4);
            wv = *(const float4*)(g_relw + rbase + c4);
        }
        *(float4*)&rhs[r * 32 + c4] = hv;
        *(float4*)&rws[r * 32 + c4] = wv;
    }
    if (tid < 64) { rowm[tid] = -3.0e38f; rowl[tid] = 0.f; }

    float oc[4][4];
#pragma unroll
    for (int nt = 0; nt < 4; ++nt)
#pragma unroll
        for (int j = 0; j < 4; ++j) oc[nt][j] = 0.f;

    __syncthreads();

    for (int k0 = 0; k0 < NSEQ; k0 += 64) {
        // K/V: float4 staging
#pragma unroll
        for (int it = 0; it < 4; ++it) {
            int idx = tid + it * 256;
            int r = idx >> 4, d = (idx & 15) * 4;
            int kg = k0 + r;
            float4 kv, vv;
            if (kg < NSEQ) {
                kv = *(const float4*)(kbase + (size_t)kg * HD + d);
                vv = *(const float4*)(vbase + (size_t)kg * HD + d);
            } else {
                kv = make_float4(0.f, 0.f, 0.f, 0.f);
                vv = kv;
            }
            *(float4*)&Ks[r * 68 + d] = kv;
            *(float4*)&Vs[r * 72 + d] = vv;
        }
        __syncthreads();

        const unsigned* Qu = (const unsigned*)Qs;
        const unsigned* Ku = (const unsigned*)Ks;

        float sc4[4][4];
#pragma unroll
        for (int nt = 0; nt < 4; ++nt)
#pragma unroll
            for (int j = 0; j < 4; ++j) sc4[nt][j] = 0.f;

#pragma unroll
        for (int ks = 0; ks < 8; ++ks) {
            unsigned a[4];
            int mr = wm * 16;
            a[0] = Qu[(mr + g    ) * 68 + ks * 8 + tig];
            a[1] = Qu[(mr + g + 8) * 68 + ks * 8 + tig];
            a[2] = Qu[(mr + g    ) * 68 + ks * 8 + tig + 4];
            a[3] = Qu[(mr + g + 8) * 68 + ks * 8 + tig + 4];
#pragma unroll
            for (int nt = 0; nt < 4; ++nt) {
                unsigned bb[2];
                int key = wn * 32 + nt * 8 + g;
                bb[0] = Ku[key * 68 + ks * 8 + tig];
                bb[1] = Ku[key * 68 + ks * 8 + tig + 4];
                mma8(sc4[nt], a, bb);
            }
        }

#pragma unroll
        for (int nt = 0; nt < 4; ++nt) {
            int col = wn * 32 + nt * 8 + tig * 2;
            int r0 = wm * 16 + g;
            *(float2*)&ps[r0 * 68 + col] = make_float2(sc4[nt][0], sc4[nt][1]);
            *(float2*)&ps[(r0 + 8) * 68 + col] = make_float2(sc4[nt][2], sc4[nt][3]);
        }
        __syncthreads();

        {
            int r = tid >> 2, tg = tid & 3;
            int qg = q0 + r;
            float vreg[16];
            float tm = -3.0e38f;
#pragma unroll
            for (int cc = 0; cc < 16; ++cc) {
                int cj = tg * 16 + cc;
                int jg = k0 + cj;
                float val = ps[r * 68 + cj];
                if (jg >= NSEQ) {
                    val = -1e30f;
                } else if (qg >= NT) {
                    if (jg < NT) val -= 100.f;
                    else {
                        int pj = jg - NT;
                        val += rhs[r * 32 + (pj >> 5)] + rws[r * 32 + (pj & 31)];
                    }
                }
                vreg[cc] = val;
                tm = fmaxf(tm, val);
            }
            tm = fmaxf(tm, __shfl_xor_sync(0xffffffffu, tm, 1));
            tm = fmaxf(tm, __shfl_xor_sync(0xffffffffu, tm, 2));
            float oldm = rowm[r];
            float newm = fmaxf(oldm, tm);
            float sum = 0.f;
#pragma unroll
            for (int cc = 0; cc < 16; ++cc) {
                float p = __expf(vreg[cc] - newm);
                sum += p;
                ps[r * 68 + tg * 16 + cc] = f2tff(p);
            }
            sum += __shfl_xor_sync(0xffffffffu, sum, 1);
            sum += __shfl_xor_sync(0xffffffffu, sum, 2);
            if (tg == 0) {
                float s = __expf(oldm - newm);
                rowsc[r] = s;
                rowl[r] = rowl[r] * s + sum;
                rowm[r] = newm;
            }
        }
        __syncthreads();

        const unsigned* pu = (const unsigned*)ps;
        const unsigned* Vu = (const unsigned*)Vs;
        float s0 = rowsc[wm * 16 + g], s1 = rowsc[wm * 16 + g + 8];
#pragma unroll
        for (int nt = 0; nt < 4; ++nt) {
            oc[nt][0] *= s0; oc[nt][1] *= s0;
            oc[nt][2] *= s1; oc[nt][3] *= s1;
        }
#pragma unroll
        for (int ks = 0; ks < 8; ++ks) {
            unsigned a[4];
            int mr = wm * 16;
            a[0] = pu[(mr + g    ) * 68 + ks * 8 + tig];
            a[1] = pu[(mr + g + 8) * 68 + ks * 8 + tig];
            a[2] = pu[(mr + g    ) * 68 + ks * 8 + tig + 4];
            a[3] = pu[(mr + g + 8) * 68 + ks * 8 + tig + 4];
#pragma unroll
            for (int nt = 0; nt < 4; ++nt) {
                unsigned bb[2];
                int dcol = wn * 32 + nt * 8 + g;
                bb[0] = Vu[(ks * 8 + tig    ) * 72 + dcol];
                bb[1] = Vu[(ks * 8 + tig + 4) * 72 + dcol];
                mma8(oc[nt], a, bb);
            }
        }
        __syncthreads();
    }

    {
        int r0 = wm * 16 + g, r1 = r0 + 8;
        int qg0 = q0 + r0, qg1 = q0 + r1;
        float inv0 = (qg0 < NSEQ) ? (1.f / rowl[r0]) : 0.f;
        float inv1 = (qg1 < NSEQ) ? (1.f / rowl[r1]) : 0.f;
#pragma unroll
        for (int nt = 0; nt < 4; ++nt) {
            int col = wn * 32 + nt * 8 + tig * 2;
            if (qg0 < NSEQ) {
                float2 v = make_float2(f2tff(oc[nt][0] * inv0), f2tff(oc[nt][1] * inv0));
                *(float2*)(g_ctx + ((size_t)b * NSEQ + qg0) * C_DIM + head * HD + col) = v;
            }
            if (qg1 < NSEQ) {
                float2 v = make_float2(f2tff(oc[nt][2] * inv1), f2tff(oc[nt][3] * inv1));
                *(float2*)(g_ctx + ((size_t)b * NSEQ + qg1) * C_DIM + head * HD + col) = v;
            }
        }
    }
}

// ---------------------------------------------------------------------------
// K4: output projection GEMM (pre-rounded inputs), 3-stage cp.async.
// ---------------------------------------------------------------------------
__global__ __launch_bounds__(256) void proj_mma_kernel(
    const float* __restrict__ bias, float* __restrict__ out)
{
    extern __shared__ float dynsm[];
    float* Asb = dynsm;
    float* Bsb = dynsm + 3 * A_STG;

    const int m0 = blockIdx.y * 128;
    const int n0 = blockIdx.x * 128;
    const int tid = threadIdx.x;
    const int wid = tid >> 5, lane = tid & 31;
    const int g = lane >> 2, tig = lane & 3;
    const int wm = wid >> 1, wn = wid & 1;

    const int aRow = tid >> 1;
    const int aK   = (tid & 1) * 8;
    const int am   = m0 + aRow;
    const bool av  = (am < MROWS);
    const float* arp = g_ctx + (size_t)(av ? am : 0) * C_DIM;

    const int bk = tid >> 5;
    const int bn = (tid & 31) * 4;

    float c[2][8][4];
#pragma unroll
    for (int mt = 0; mt < 2; ++mt)
#pragma unroll
        for (int nt = 0; nt < 8; ++nt)
#pragma unroll
            for (int j = 0; j < 4; ++j) c[mt][nt][j] = 0.f;

    auto load_stage = [&](int s, int k0) {
        unsigned ad = smem_u32(&Asb[s * A_STG + aRow * A_LD + aK]);
        unsigned bd = smem_u32(&Bsb[s * B_STG + bk * B_LD + bn]);
        cpasync16(ad,      arp + k0 + aK,     av);
        cpasync16(ad + 16, arp + k0 + aK + 4, av);
        cpasync16(bd,                 g_wp + (size_t)(k0 + bk)     * C_DIM + n0 + bn, true);
        cpasync16(bd + 8 * B_LD * 4,  g_wp + (size_t)(k0 + bk + 8) * C_DIM + n0 + bn, true);
        CP_COMMIT();
    };

    const int NKT = C_DIM / 16;
    load_stage(0, 0);
    load_stage(1, 16);

    for (int kt = 0; kt < NKT; ++kt) {
        int s = kt % 3;
        if (kt + 2 < NKT) { load_stage((kt + 2) % 3, (kt + 2) * 16); CP_WAIT(2); }
        else if (kt + 1 < NKT) { CP_WAIT(1); }
        else { CP_WAIT(0); }
        __syncthreads();

        const unsigned* Au = (const unsigned*)(Asb + s * A_STG);
        const unsigned* Bu = (const unsigned*)(Bsb + s * B_STG);
#pragma unroll
        for (int ks = 0; ks < 2; ++ks) {
            unsigned a[2][4];
#pragma unroll
            for (int mt = 0; mt < 2; ++mt) {
                int mr = wm * 32 + mt * 16;
                a[mt][0] = Au[(mr + g    ) * A_LD + ks * 8 + tig];
                a[mt][1] = Au[(mr + g + 8) * A_LD + ks * 8 + tig];
                a[mt][2] = Au[(mr + g    ) * A_LD + ks * 8 + tig + 4];
                a[mt][3] = Au[(mr + g + 8) * A_LD + ks * 8 + tig + 4];
            }
            unsigned b[8][2];
#pragma unroll
            for (int nt = 0; nt < 8; ++nt) {
                int nc = wn * 64 + nt * 8 + g;
                b[nt][0] = Bu[(ks * 8 + tig    ) * B_LD + nc];
                b[nt][1] = Bu[(ks * 8 + tig + 4) * B_LD + nc];
            }
#pragma unroll
            for (int mt = 0; mt < 2; ++mt)
#pragma unroll
                for (int nt = 0; nt < 8; ++nt) mma8(c[mt][nt], a[mt], b[nt]);
        }
        __syncthreads();
    }

#pragma unroll
    for (int nt = 0; nt < 8; ++nt) {
        int col = n0 + wn * 64 + nt * 8 + tig * 2;
        float b0v = bias[col], b1v = bias[col + 1];
#pragma unroll
        for (int mt = 0; mt < 2; ++mt) {
#pragma unroll
            for (int h = 0; h < 2; ++h) {
                int m = m0 + wm * 32 + mt * 16 + g + h * 8;
                if (m >= MROWS) continue;
                int bb = m / NSEQ, nn = m % NSEQ;
                float* dst = (nn < NT)
                    ? (out + XOUT_ELEMS + ((size_t)bb * NT + nn) * C_DIM)
                    : (out + ((size_t)bb * HW + (nn - NT)) * C_DIM);
                float2 v;
                v.x = c[mt][nt][h * 2 + 0] + b0v;
                v.y = c[mt][nt][h * 2 + 1] + b1v;
                *(float2*)(dst + col) = v;
            }
        }
    }
}

// ---------------------------------------------------------------------------
extern "C" void kernel_launch(void* const* d_in, const int* in_sizes, int n_in,
                              void* d_out, int out_size)
{
    const float* x      = (const float*)d_in[0];
    const float* vp     = (const float*)d_in[1];
    const float* qkv_w  = (const float*)d_in[2];
    const float* qkv_b  = (const float*)d_in[3];
    const float* proj_w = (const float*)d_in[4];
    const float* proj_b = (const float*)d_in[5];
    const float* rph    = (const float*)d_in[6];
    const float* rpw    = (const float*)d_in[7];
    float* out = (float*)d_out;

    (void)in_sizes; (void)n_in; (void)out_size;

    cudaFuncSetAttribute(qkv_mma_kernel,
                         cudaFuncAttributeMaxDynamicSharedMemorySize,
                         GEMM_SM_BYTES);
    cudaFuncSetAttribute(proj_mma_kernel,
                         cudaFuncAttributeMaxDynamicSharedMemorySize,
                         GEMM_SM_BYTES);
    cudaFuncSetAttribute(attn_mma_kernel,
                         cudaFuncAttributeMaxDynamicSharedMemorySize,
                         ATT_SM_BYTES);

    prep_xs_kernel<<<1184, 256>>>(x, vp);
    prep_w_kernel<<<1184, 256>>>(qkv_w, proj_w);
    qkv_mma_kernel<<<dim3(QKV_N / 128, (MROWS + 127) / 128), 256, GEMM_SM_BYTES>>>(qkv_b);
    rel_kernel<<<dim3(32, BHN, 2), 64>>>(rph, rpw);
    attn_mma_kernel<<<dim3((NSEQ + 63) / 64, BHN), 256, ATT_SM_BYTES>>>();
    proj_mma_kernel<<<dim3(C_DIM / 128, (MROWS + 127) / 128), 256, GEMM_SM_BYTES>>>(proj_b, out);
}

// round 12
// speedup vs baseline: 1.1885x; 1.0040x over previous
#include <cuda_runtime.h>

// ---------------------------------------------------------------------------
// PromptedAttention: B=8, H=W=32, C=768, heads=12, hd=64, nt=8, N=1032
// Round 12: resubmit of R11 (infra failure) — BK=32 2-stage GEMMs;
// rel_kernel shares R across 4 bh per block; attention unchanged.
// ---------------------------------------------------------------------------

#define BATCH     8
#define HEADS     12
#define HD        64
#define C_DIM     768
#define NT        8
#define HW        1024
#define NSEQ      1032
#define BHN       96
#define MROWS     8256
#define QKV_N     2304
#define XOUT_ELEMS 6291456

__device__ float g_q[BHN * NSEQ * HD];
__device__ float g_k[BHN * NSEQ * HD];
__device__ float g_v[BHN * NSEQ * HD];
__device__ float g_relh[BHN * 32 * 32 * 32];
__device__ float g_relw[BHN * 32 * 32 * 32];
__device__ float g_ctx[MROWS * C_DIM];
__device__ float g_xs[MROWS * C_DIM];
__device__ float g_wq[C_DIM * QKV_N];
__device__ float g_wp[C_DIM * C_DIM];

__device__ __forceinline__ unsigned f2tf(float f) {
    unsigned u;
    asm("cvt.rna.tf32.f32 %0, %1;" : "=r"(u) : "f"(f));
    return u;
}
__device__ __forceinline__ float f2tff(float f) { return __uint_as_float(f2tf(f)); }

__device__ __forceinline__ void mma8(float* c, const unsigned* a, const unsigned* b) {
    asm volatile(
        "mma.sync.aligned.m16n8k8.row.col.f32.tf32.tf32.f32 "
        "{%0,%1,%2,%3}, {%4,%5,%6,%7}, {%8,%9}, {%0,%1,%2,%3};\n"
        : "+f"(c[0]), "+f"(c[1]), "+f"(c[2]), "+f"(c[3])
        : "r"(a[0]), "r"(a[1]), "r"(a[2]), "r"(a[3]), "r"(b[0]), "r"(b[1]));
}

__device__ __forceinline__ unsigned smem_u32(const void* p) {
    return (unsigned)__cvta_generic_to_shared(p);
}
__device__ __forceinline__ void cpasync16(unsigned dst, const void* src, bool pred) {
    asm volatile("cp.async.cg.shared.global [%0], [%1], 16, %2;\n"
                 :: "r"(dst), "l"(src), "r"(pred ? 16 : 0));
}
#define CP_COMMIT() asm volatile("cp.async.commit_group;\n" ::: "memory")
#define CP_WAIT(N)  asm volatile("cp.async.wait_group %0;\n" :: "n"(N) : "memory")

// BK=32 stage geometry
#define A_LD 36                      // 36 % 32 == 4 -> 4g+tig conflict-free
#define B_LD 136                     // 136 % 32 == 8 -> 8tig+g conflict-free
#define A_STG (128 * A_LD)           // 4608 floats
#define B_STG (32 * B_LD)            // 4352 floats
#define GEMM_SM_BYTES (2 * (A_STG + B_STG) * 4)   // 71680

// ---------------------------------------------------------------------------
// K0a: build rounded concat g_xs.
// ---------------------------------------------------------------------------
__global__ __launch_bounds__(256) void prep_xs_kernel(
    const float* __restrict__ x, const float* __restrict__ vp)
{
    const int F4 = C_DIM / 4;
    const int total = MROWS * F4;
    for (int idx = blockIdx.x * 256 + threadIdx.x; idx < total;
         idx += gridDim.x * 256) {
        int row = idx / F4;
        int f4 = idx - row * F4;
        int b = row / NSEQ, n = row % NSEQ;
        const float4* src = (n < NT)
            ? (const float4*)(vp + ((size_t)b * NT + n) * C_DIM)
            : (const float4*)(x + ((size_t)b * HW + (n - NT)) * C_DIM);
        float4 t = src[f4];
        float4 o;
        o.x = f2tff(t.x); o.y = f2tff(t.y); o.z = f2tff(t.z); o.w = f2tff(t.w);
        ((float4*)g_xs)[idx] = o;
    }
}

// K0b: round both weight matrices.
__global__ __launch_bounds__(256) void prep_w_kernel(
    const float* __restrict__ wq, const float* __restrict__ wp)
{
    const int T1 = C_DIM * QKV_N / 4;
    const int T2 = C_DIM * C_DIM / 4;
    for (int idx = blockIdx.x * 256 + threadIdx.x; idx < T1 + T2;
         idx += gridDim.x * 256) {
        float4 t;
        float4* dst;
        if (idx < T1) { t = ((const float4*)wq)[idx]; dst = (float4*)g_wq + idx; }
        else { t = ((const float4*)wp)[idx - T1]; dst = (float4*)g_wp + (idx - T1); }
        float4 o;
        o.x = f2tff(t.x); o.y = f2tff(t.y); o.z = f2tff(t.z); o.w = f2tff(t.w);
        *dst = o;
    }
}

// ---------------------------------------------------------------------------
// K1: fused QKV GEMM, BK=32, 2-stage cp.async, dynamic smem.
// ---------------------------------------------------------------------------
__global__ __launch_bounds__(256) void qkv_mma_kernel(const float* __restrict__ bias)
{
    extern __shared__ float dynsm[];
    float* Asb = dynsm;                 // [2][A_STG]
    float* Bsb = dynsm + 2 * A_STG;     // [2][B_STG]

    const int m0 = blockIdx.y * 128;
    const int n0 = blockIdx.x * 128;
    const int tid = threadIdx.x;
    const int wid = tid >> 5, lane = tid & 31;
    const int g = lane >> 2, tig = lane & 3;
    const int wm = wid >> 1, wn = wid & 1;

    const int aRow = tid >> 1;
    const int aK   = (tid & 1) * 16;
    const int am   = m0 + aRow;
    const bool av  = (am < MROWS);
    const float* arp = g_xs + (size_t)(av ? am : 0) * C_DIM;

    const int bk = tid >> 5;            // 0..7
    const int bn = (tid & 31) * 4;

    float c[2][8][4];
#pragma unroll
    for (int mt = 0; mt < 2; ++mt)
#pragma unroll
        for (int nt = 0; nt < 8; ++nt)
#pragma unroll
            for (int j = 0; j < 4; ++j) c[mt][nt][j] = 0.f;

    auto load_stage = [&](int s, int k0) {
        unsigned ad = smem_u32(&Asb[s * A_STG + aRow * A_LD + aK]);
        unsigned bd = smem_u32(&Bsb[s * B_STG + bk * B_LD + bn]);
#pragma unroll
        for (int i = 0; i < 4; ++i)
            cpasync16(ad + 16 * i, arp + k0 + aK + 4 * i, av);
#pragma unroll
        for (int i = 0; i < 4; ++i)
            cpasync16(bd + (8 * i) * B_LD * 4,
                      g_wq + (size_t)(k0 + bk + 8 * i) * QKV_N + n0 + bn, true);
        CP_COMMIT();
    };

    const int NKT = C_DIM / 32;      // 24
    load_stage(0, 0);

    for (int kt = 0; kt < NKT; ++kt) {
        int s = kt & 1;
        if (kt + 1 < NKT) { load_stage(s ^ 1, (kt + 1) * 32); CP_WAIT(1); }
        else              { CP_WAIT(0); }
        __syncthreads();

        const unsigned* Au = (const unsigned*)(Asb + s * A_STG);
        const unsigned* Bu = (const unsigned*)(Bsb + s * B_STG);
#pragma unroll
        for (int ks = 0; ks < 4; ++ks) {
            unsigned a[2][4];
#pragma unroll
            for (int mt = 0; mt < 2; ++mt) {
                int mr = wm * 32 + mt * 16;
                a[mt][0] = Au[(mr + g    ) * A_LD + ks * 8 + tig];
                a[mt][1] = Au[(mr + g + 8) * A_LD + ks * 8 + tig];
                a[mt][2] = Au[(mr + g    ) * A_LD + ks * 8 + tig + 4];
                a[mt][3] = Au[(mr + g + 8) * A_LD + ks * 8 + tig + 4];
            }
            unsigned b[8][2];
#pragma unroll
            for (int nt = 0; nt < 8; ++nt) {
                int nc = wn * 64 + nt * 8 + g;
                b[nt][0] = Bu[(ks * 8 + tig    ) * B_LD + nc];
                b[nt][1] = Bu[(ks * 8 + tig + 4) * B_LD + nc];
            }
#pragma unroll
            for (int mt = 0; mt < 2; ++mt)
#pragma unroll
                for (int nt = 0; nt < 8; ++nt) mma8(c[mt][nt], a[mt], b[nt]);
        }
        __syncthreads();
    }

    float* bufs[3] = {g_q, g_k, g_v};
#pragma unroll
    for (int nt = 0; nt < 8; ++nt) {
        int col = n0 + wn * 64 + nt * 8 + tig * 2;
        int which = col / C_DIM;
        int c2 = col % C_DIM;
        int head = c2 >> 6, db = c2 & 63;
        float b0v = bias[col], b1v = bias[col + 1];
        float* buf = bufs[which];
#pragma unroll
        for (int mt = 0; mt < 2; ++mt) {
#pragma unroll
            for (int h = 0; h < 2; ++h) {
                int m = m0 + wm * 32 + mt * 16 + g + h * 8;
                if (m >= MROWS) continue;
                int bb = m / NSEQ, nn = m % NSEQ;
                float* dst = buf + (size_t)bb * (HEADS * NSEQ * HD)
                                 + (size_t)head * (NSEQ * HD)
                                 + (size_t)nn * HD + db;
                float2 v;
                v.x = f2tff(c[mt][nt][h * 2 + 0] + b0v);
                v.y = f2tff(c[mt][nt][h * 2 + 1] + b1v);
                *(float2*)dst = v;
            }
        }
    }
}

// ---------------------------------------------------------------------------
// K2: rel bias GEMMs — 4 bh per block sharing one R tile; 4x4 reg blocking.
// ---------------------------------------------------------------------------
__global__ __launch_bounds__(256) void rel_kernel(
    const float* __restrict__ rph, const float* __restrict__ rpw)
{
    __shared__ float qs[4][32 * 65];
    __shared__ float RsT[64 * 33];

    const int bh0 = blockIdx.y * 4;
    const int idx0 = blockIdx.x;
    const int variant = blockIdx.z;
    const int tid = threadIdx.x;

    const float* rp = (variant == 0) ? rph : rpw;
#pragma unroll
    for (int it = 0; it < 8; ++it) {
        int idx = tid + it * 256;       // 2048
        int k = idx >> 6, c = idx & 63;
        RsT[c * 33 + k] = rp[(size_t)(idx0 - k + 31) * HD + c];
    }
#pragma unroll
    for (int it = 0; it < 32; ++it) {
        int idx = tid + it * 256;       // 8192
        int grp = idx >> 11;
        int w = idx & 2047;
        int r = w >> 6, c = w & 63;
        int bh = bh0 + grp;
        int n = (variant == 0) ? (NT + idx0 * 32 + r) : (NT + r * 32 + idx0);
        qs[grp][r * 65 + c] = g_q[((size_t)bh * NSEQ + n) * HD + c];
    }
    __syncthreads();

    const int grp = tid >> 6;
    const int stid = tid & 63;
    const int bh = bh0 + grp;
    const int tr = stid >> 3;
    const int tk = stid & 7;
    const float* qsg = qs[grp];

    float acc[4][4];
#pragma unroll
    for (int i = 0; i < 4; ++i)
#pragma unroll
        for (int j = 0; j < 4; ++j) acc[i][j] = 0.f;

#pragma unroll 4
    for (int c = 0; c < 64; ++c) {
        float q[4], rv[4];
#pragma unroll
        for (int i = 0; i < 4; ++i) q[i] = qsg[(tr * 4 + i) * 65 + c];
#pragma unroll
        for (int j = 0; j < 4; ++j) rv[j] = RsT[c * 33 + tk * 4 + j];
#pragma unroll
        for (int i = 0; i < 4; ++i)
#pragma unroll
            for (int j = 0; j < 4; ++j) acc[i][j] += q[i] * rv[j];
    }

    float* outb = (variant == 0) ? g_relh : g_relw;
#pragma unroll
    for (int i = 0; i < 4; ++i) {
        int row = tr * 4 + i;
        size_t base = (variant == 0)
            ? ((((size_t)bh * 32 + idx0) * 32 + row) * 32)
            : ((((size_t)bh * 32 + row) * 32 + idx0) * 32);
        float4 v;
        v.x = acc[i][0]; v.y = acc[i][1]; v.z = acc[i][2]; v.w = acc[i][3];
        *(float4*)(outb + base + tk * 4) = v;
    }
}

// ---------------------------------------------------------------------------
// K3: flash attention (sync float4 staging, pre-rounded Q/K/V, 2 CTAs/SM).
// ---------------------------------------------------------------------------
#define ATT_SM_FLOATS (3 * 64 * 68 + 64 * 72 + 2 * 64 * 32 + 3 * 64)
#define ATT_SM_BYTES  (ATT_SM_FLOATS * 4)

__global__ __launch_bounds__(256) void attn_mma_kernel()
{
    extern __shared__ float sm[];
    float* Qs   = sm;                 // [64 q][68], tf32, prescaled
    float* Ks   = Qs + 64 * 68;       // [64 key][68], tf32
    float* ps   = Ks + 64 * 68;       // [64 q][68], S then P(tf32)
    float* Vs   = ps + 64 * 68;       // [64 key][72], tf32
    float* rhs  = Vs + 64 * 72;       // [64 q][32]
    float* rws  = rhs + 64 * 32;      // [64 q][32]
    float* rowm = rws + 64 * 32;
    float* rowl = rowm + 64;
    float* rowsc = rowl + 64;

    const int tid = threadIdx.x;
    const int wid = tid >> 5, lane = tid & 31;
    const int g = lane >> 2, tig = lane & 3;
    const int wm = wid >> 1, wn = wid & 1;
    const int bh = blockIdx.y;
    const int b = bh / HEADS, head = bh % HEADS;
    const int q0 = blockIdx.x * 64;

    const float* qbase = g_q + (size_t)bh * NSEQ * HD;
    const float* kbase = g_k + (size_t)bh * NSEQ * HD;
    const float* vbase = g_v + (size_t)bh * NSEQ * HD;

#pragma unroll
    for (int it = 0; it < 4; ++it) {
        int idx = tid + it * 256;
        int r = idx >> 4, d = (idx & 15) * 4;
        int qg = q0 + r;
        float4 t = (qg < NSEQ) ? *(const float4*)(qbase + (size_t)qg * HD + d)
                               : make_float4(0.f, 0.f, 0.f, 0.f);
        float4 o;
        o.x = t.x * 0.125f; o.y = t.y * 0.125f;
        o.z = t.z * 0.125f; o.w = t.w * 0.125f;
        *(float4*)&Qs[r * 68 + d] = o;
    }
#pragma unroll
    for (int it = 0; it < 2; ++it) {
        int idx = tid + it * 256;
        int r = idx >> 3, c4 = (idx & 7) * 4;
        int qg = q0 + r;
        float4 hv = make_float4(0.f, 0.f, 0.f, 0.f), wv = hv;
        if (qg >= NT && qg < NSEQ) {
            int pix = qg - NT;
            int hq = pix >> 5, wq = pix & 31;
            size_t rbase = (((size_t)bh * 32 + hq) * 32 + wq) * 32;
            hv = *(const float4*)(g_relh + rbase + c4);
            wv = *(const float4*)(g_relw + rbase + c4);
        }
        *(float4*)&rhs[r * 32 + c4] = hv;
        *(float4*)&rws[r * 32 + c4] = wv;
    }
    if (tid < 64) { rowm[tid] = -3.0e38f; rowl[tid] = 0.f; }

    float oc[4][4];
#pragma unroll
    for (int nt = 0; nt < 4; ++nt)
#pragma unroll
        for (int j = 0; j < 4; ++j) oc[nt][j] = 0.f;

    __syncthreads();

    for (int k0 = 0; k0 < NSEQ; k0 += 64) {
#pragma unroll
        for (int it = 0; it < 4; ++it) {
            int idx = tid + it * 256;
            int r = idx >> 4, d = (idx & 15) * 4;
            int kg = k0 + r;
            float4 kv, vv;
            if (kg < NSEQ) {
                kv = *(const float4*)(kbase + (size_t)kg * HD + d);
                vv = *(const float4*)(vbase + (size_t)kg * HD + d);
            } else {
                kv = make_float4(0.f, 0.f, 0.f, 0.f);
                vv = kv;
            }
            *(float4*)&Ks[r * 68 + d] = kv;
            *(float4*)&Vs[r * 72 + d] = vv;
        }
        __syncthreads();

        const unsigned* Qu = (const unsigned*)Qs;
        const unsigned* Ku = (const unsigned*)Ks;

        float sc4[4][4];
#pragma unroll
        for (int nt = 0; nt < 4; ++nt)
#pragma unroll
            for (int j = 0; j < 4; ++j) sc4[nt][j] = 0.f;

#pragma unroll
        for (int ks = 0; ks < 8; ++ks) {
            unsigned a[4];
            int mr = wm * 16;
            a[0] = Qu[(mr + g    ) * 68 + ks * 8 + tig];
            a[1] = Qu[(mr + g + 8) * 68 + ks * 8 + tig];
            a[2] = Qu[(mr + g    ) * 68 + ks * 8 + tig + 4];
            a[3] = Qu[(mr + g + 8) * 68 + ks * 8 + tig + 4];
#pragma unroll
            for (int nt = 0; nt < 4; ++nt) {
                unsigned bb[2];
                int key = wn * 32 + nt * 8 + g;
                bb[0] = Ku[key * 68 + ks * 8 + tig];
                bb[1] = Ku[key * 68 + ks * 8 + tig + 4];
                mma8(sc4[nt], a, bb);
            }
        }

#pragma unroll
        for (int nt = 0; nt < 4; ++nt) {
            int col = wn * 32 + nt * 8 + tig * 2;
            int r0 = wm * 16 + g;
            *(float2*)&ps[r0 * 68 + col] = make_float2(sc4[nt][0], sc4[nt][1]);
            *(float2*)&ps[(r0 + 8) * 68 + col] = make_float2(sc4[nt][2], sc4[nt][3]);
        }
        __syncthreads();

        {
            int r = tid >> 2, tg = tid & 3;
            int qg = q0 + r;
            float vreg[16];
            float tm = -3.0e38f;
#pragma unroll
            for (int cc = 0; cc < 16; ++cc) {
                int cj = tg * 16 + cc;
                int jg = k0 + cj;
                float val = ps[r * 68 + cj];
                if (jg >= NSEQ) {
                    val = -1e30f;
                } else if (qg >= NT) {
                    if (jg < NT) val -= 100.f;
                    else {
                        int pj = jg - NT;
                        val += rhs[r * 32 + (pj >> 5)] + rws[r * 32 + (pj & 31)];
                    }
                }
                vreg[cc] = val;
                tm = fmaxf(tm, val);
            }
            tm = fmaxf(tm, __shfl_xor_sync(0xffffffffu, tm, 1));
            tm = fmaxf(tm, __shfl_xor_sync(0xffffffffu, tm, 2));
            float oldm = rowm[r];
            float newm = fmaxf(oldm, tm);
            float sum = 0.f;
#pragma unroll
            for (int cc = 0; cc < 16; ++cc) {
                float p = __expf(vreg[cc] - newm);
                sum += p;
                ps[r * 68 + tg * 16 + cc] = f2tff(p);
            }
            sum += __shfl_xor_sync(0xffffffffu, sum, 1);
            sum += __shfl_xor_sync(0xffffffffu, sum, 2);
            if (tg == 0) {
                float s = __expf(oldm - newm);
                rowsc[r] = s;
                rowl[r] = rowl[r] * s + sum;
                rowm[r] = newm;
            }
        }
        __syncthreads();

        const unsigned* pu = (const unsigned*)ps;
        const unsigned* Vu = (const unsigned*)Vs;
        float s0 = rowsc[wm * 16 + g], s1 = rowsc[wm * 16 + g + 8];
#pragma unroll
        for (int nt = 0; nt < 4; ++nt) {
            oc[nt][0] *= s0; oc[nt][1] *= s0;
            oc[nt][2] *= s1; oc[nt][3] *= s1;
        }
#pragma unroll
        for (int ks = 0; ks < 8; ++ks) {
            unsigned a[4];
            int mr = wm * 16;
            a[0] = pu[(mr + g    ) * 68 + ks * 8 + tig];
            a[1] = pu[(mr + g + 8) * 68 + ks * 8 + tig];
            a[2] = pu[(mr + g    ) * 68 + ks * 8 + tig + 4];
            a[3] = pu[(mr + g + 8) * 68 + ks * 8 + tig + 4];
#pragma unroll
            for (int nt = 0; nt < 4; ++nt) {
                unsigned bb[2];
                int dcol = wn * 32 + nt * 8 + g;
                bb[0] = Vu[(ks * 8 + tig    ) * 72 + dcol];
                bb[1] = Vu[(ks * 8 + tig + 4) * 72 + dcol];
                mma8(oc[nt], a, bb);
            }
        }
        __syncthreads();
    }

    {
        int r0 = wm * 16 + g, r1 = r0 + 8;
        int qg0 = q0 + r0, qg1 = q0 + r1;
        float inv0 = (qg0 < NSEQ) ? (1.f / rowl[r0]) : 0.f;
        float inv1 = (qg1 < NSEQ) ? (1.f / rowl[r1]) : 0.f;
#pragma unroll
        for (int nt = 0; nt < 4; ++nt) {
            int col = wn * 32 + nt * 8 + tig * 2;
            if (qg0 < NSEQ) {
                float2 v = make_float2(f2tff(oc[nt][0] * inv0), f2tff(oc[nt][1] * inv0));
                *(float2*)(g_ctx + ((size_t)b * NSEQ + qg0) * C_DIM + head * HD + col) = v;
            }
            if (qg1 < NSEQ) {
                float2 v = make_float2(f2tff(oc[nt][2] * inv1), f2tff(oc[nt][3] * inv1));
                *(float2*)(g_ctx + ((size_t)b * NSEQ + qg1) * C_DIM + head * HD + col) = v;
            }
        }
    }
}

// ---------------------------------------------------------------------------
// K4: output projection GEMM, BK=32, 2-stage cp.async, dynamic smem.
// ---------------------------------------------------------------------------
__global__ __launch_bounds__(256) void proj_mma_kernel(
    const float* __restrict__ bias, float* __restrict__ out)
{
    extern __shared__ float dynsm[];
    float* Asb = dynsm;
    float* Bsb = dynsm + 2 * A_STG;

    const int m0 = blockIdx.y * 128;
    const int n0 = blockIdx.x * 128;
    const int tid = threadIdx.x;
    const int wid = tid >> 5, lane = tid & 31;
    const int g = lane >> 2, tig = lane & 3;
    const int wm = wid >> 1, wn = wid & 1;

    const int aRow = tid >> 1;
    const int aK   = (tid & 1) * 16;
    const int am   = m0 + aRow;
    const bool av  = (am < MROWS);
    const float* arp = g_ctx + (size_t)(av ? am : 0) * C_DIM;

    const int bk = tid >> 5;
    const int bn = (tid & 31) * 4;

    float c[2][8][4];
#pragma unroll
    for (int mt = 0; mt < 2; ++mt)
#pragma unroll
        for (int nt = 0; nt < 8; ++nt)
#pragma unroll
            for (int j = 0; j < 4; ++j) c[mt][nt][j] = 0.f;

    auto load_stage = [&](int s, int k0) {
        unsigned ad = smem_u32(&Asb[s * A_STG + aRow * A_LD + aK]);
        unsigned bd = smem_u32(&Bsb[s * B_STG + bk * B_LD + bn]);
#pragma unroll
        for (int i = 0; i < 4; ++i)
            cpasync16(ad + 16 * i, arp + k0 + aK + 4 * i, av);
#pragma unroll
        for (int i = 0; i < 4; ++i)
            cpasync16(bd + (8 * i) * B_LD * 4,
                      g_wp + (size_t)(k0 + bk + 8 * i) * C_DIM + n0 + bn, true);
        CP_COMMIT();
    };

    const int NKT = C_DIM / 32;      // 24
    load_stage(0, 0);

    for (int kt = 0; kt < NKT; ++kt) {
        int s = kt & 1;
        if (kt + 1 < NKT) { load_stage(s ^ 1, (kt + 1) * 32); CP_WAIT(1); }
        else              { CP_WAIT(0); }
        __syncthreads();

        const unsigned* Au = (const unsigned*)(Asb + s * A_STG);
        const unsigned* Bu = (const unsigned*)(Bsb + s * B_STG);
#pragma unroll
        for (int ks = 0; ks < 4; ++ks) {
            unsigned a[2][4];
#pragma unroll
            for (int mt = 0; mt < 2; ++mt) {
                int mr = wm * 32 + mt * 16;
                a[mt][0] = Au[(mr + g    ) * A_LD + ks * 8 + tig];
                a[mt][1] = Au[(mr + g + 8) * A_LD + ks * 8 + tig];
                a[mt][2] = Au[(mr + g    ) * A_LD + ks * 8 + tig + 4];
                a[mt][3] = Au[(mr + g + 8) * A_LD + ks * 8 + tig + 4];
            }
            unsigned b[8][2];
#pragma unroll
            for (int nt = 0; nt < 8; ++nt) {
                int nc = wn * 64 + nt * 8 + g;
                b[nt][0] = Bu[(ks * 8 + tig    ) * B_LD + nc];
                b[nt][1] = Bu[(ks * 8 + tig + 4) * B_LD + nc];
            }
#pragma unroll
            for (int mt = 0; mt < 2; ++mt)
#pragma unroll
                for (int nt = 0; nt < 8; ++nt) mma8(c[mt][nt], a[mt], b[nt]);
        }
        __syncthreads();
    }

#pragma unroll
    for (int nt = 0; nt < 8; ++nt) {
        int col = n0 + wn * 64 + nt * 8 + tig * 2;
        float b0v = bias[col], b1v = bias[col + 1];
#pragma unroll
        for (int mt = 0; mt < 2; ++mt) {
#pragma unroll
            for (int h = 0; h < 2; ++h) {
                int m = m0 + wm * 32 + mt * 16 + g + h * 8;
                if (m >= MROWS) continue;
                int bb = m / NSEQ, nn = m % NSEQ;
                float* dst = (nn < NT)
                    ? (out + XOUT_ELEMS + ((size_t)bb * NT + nn) * C_DIM)
                    : (out + ((size_t)bb * HW + (nn - NT)) * C_DIM);
                float2 v;
                v.x = c[mt][nt][h * 2 + 0] + b0v;
                v.y = c[mt][nt][h * 2 + 1] + b1v;
                *(float2*)(dst + col) = v;
            }
        }
    }
}

// ---------------------------------------------------------------------------
extern "C" void kernel_launch(void* const* d_in, const int* in_sizes, int n_in,
                              void* d_out, int out_size)
{
    const float* x      = (const float*)d_in[0];
    const float* vp     = (const float*)d_in[1];
    const float* qkv_w  = (const float*)d_in[2];
    const float* qkv_b  = (const float*)d_in[3];
    const float* proj_w = (const float*)d_in[4];
    const float* proj_b = (const float*)d_in[5];
    const float* rph    = (const float*)d_in[6];
    const float* rpw    = (const float*)d_in[7];
    float* out = (float*)d_out;

    (void)in_sizes; (void)n_in; (void)out_size;

    cudaFuncSetAttribute(qkv_mma_kernel,
                         cudaFuncAttributeMaxDynamicSharedMemorySize,
                         GEMM_SM_BYTES);
    cudaFuncSetAttribute(proj_mma_kernel,
                         cudaFuncAttributeMaxDynamicSharedMemorySize,
                         GEMM_SM_BYTES);
    cudaFuncSetAttribute(attn_mma_kernel,
                         cudaFuncAttributeMaxDynamicSharedMemorySize,
                         ATT_SM_BYTES);

    prep_xs_kernel<<<1184, 256>>>(x, vp);
    prep_w_kernel<<<1184, 256>>>(qkv_w, proj_w);
    qkv_mma_kernel<<<dim3(QKV_N / 128, (MROWS + 127) / 128), 256, GEMM_SM_BYTES>>>(qkv_b);
    rel_kernel<<<dim3(32, BHN / 4, 2), 256>>>(rph, rpw);
    attn_mma_kernel<<<dim3((NSEQ + 63) / 64, BHN), 256, ATT_SM_BYTES>>>();
    proj_mma_kernel<<<dim3(C_DIM / 128, (MROWS + 127) / 128), 256, GEMM_SM_BYTES>>>(proj_b, out);
}

// round 13
// speedup vs baseline: 1.3929x; 1.1720x over previous
#include <cuda_runtime.h>

// ---------------------------------------------------------------------------
// PromptedAttention: B=8, H=W=32, C=768, heads=12, hd=64, nt=8, N=1032
// Round 13: FA2-style attention — q-tile 128, warp-owns-row register softmax,
// P via shfl permutation (no S/P smem round trip). GEMMs/rel from R12.
// ---------------------------------------------------------------------------

#define BATCH     8
#define HEADS     12
#define HD        64
#define C_DIM     768
#define NT        8
#define HW        1024
#define NSEQ      1032
#define BHN       96
#define MROWS     8256
#define QKV_N     2304
#define XOUT_ELEMS 6291456

__device__ float g_q[BHN * NSEQ * HD];
__device__ float g_k[BHN * NSEQ * HD];
__device__ float g_v[BHN * NSEQ * HD];
__device__ float g_relh[BHN * 32 * 32 * 32];
__device__ float g_relw[BHN * 32 * 32 * 32];
__device__ float g_ctx[MROWS * C_DIM];
__device__ float g_xs[MROWS * C_DIM];
__device__ float g_wq[C_DIM * QKV_N];
__device__ float g_wp[C_DIM * C_DIM];

__device__ __forceinline__ unsigned f2tf(float f) {
    unsigned u;
    asm("cvt.rna.tf32.f32 %0, %1;" : "=r"(u) : "f"(f));
    return u;
}
__device__ __forceinline__ float f2tff(float f) { return __uint_as_float(f2tf(f)); }

__device__ __forceinline__ void mma8(float* c, const unsigned* a, const unsigned* b) {
    asm volatile(
        "mma.sync.aligned.m16n8k8.row.col.f32.tf32.tf32.f32 "
        "{%0,%1,%2,%3}, {%4,%5,%6,%7}, {%8,%9}, {%0,%1,%2,%3};\n"
        : "+f"(c[0]), "+f"(c[1]), "+f"(c[2]), "+f"(c[3])
        : "r"(a[0]), "r"(a[1]), "r"(a[2]), "r"(a[3]), "r"(b[0]), "r"(b[1]));
}

__device__ __forceinline__ unsigned smem_u32(const void* p) {
    return (unsigned)__cvta_generic_to_shared(p);
}
__device__ __forceinline__ void cpasync16(unsigned dst, const void* src, bool pred) {
    asm volatile("cp.async.cg.shared.global [%0], [%1], 16, %2;\n"
                 :: "r"(dst), "l"(src), "r"(pred ? 16 : 0));
}
#define CP_COMMIT() asm volatile("cp.async.commit_group;\n" ::: "memory")
#define CP_WAIT(N)  asm volatile("cp.async.wait_group %0;\n" :: "n"(N) : "memory")

#define A_LD 36
#define B_LD 136
#define A_STG (128 * A_LD)
#define B_STG (32 * B_LD)
#define GEMM_SM_BYTES (2 * (A_STG + B_STG) * 4)   // 71680

// ---------------------------------------------------------------------------
// K0a: build rounded concat g_xs.
// ---------------------------------------------------------------------------
__global__ __launch_bounds__(256) void prep_xs_kernel(
    const float* __restrict__ x, const float* __restrict__ vp)
{
    const int F4 = C_DIM / 4;
    const int total = MROWS * F4;
    for (int idx = blockIdx.x * 256 + threadIdx.x; idx < total;
         idx += gridDim.x * 256) {
        int row = idx / F4;
        int f4 = idx - row * F4;
        int b = row / NSEQ, n = row % NSEQ;
        const float4* src = (n < NT)
            ? (const float4*)(vp + ((size_t)b * NT + n) * C_DIM)
            : (const float4*)(x + ((size_t)b * HW + (n - NT)) * C_DIM);
        float4 t = src[f4];
        float4 o;
        o.x = f2tff(t.x); o.y = f2tff(t.y); o.z = f2tff(t.z); o.w = f2tff(t.w);
        ((float4*)g_xs)[idx] = o;
    }
}

__global__ __launch_bounds__(256) void prep_w_kernel(
    const float* __restrict__ wq, const float* __restrict__ wp)
{
    const int T1 = C_DIM * QKV_N / 4;
    const int T2 = C_DIM * C_DIM / 4;
    for (int idx = blockIdx.x * 256 + threadIdx.x; idx < T1 + T2;
         idx += gridDim.x * 256) {
        float4 t;
        float4* dst;
        if (idx < T1) { t = ((const float4*)wq)[idx]; dst = (float4*)g_wq + idx; }
        else { t = ((const float4*)wp)[idx - T1]; dst = (float4*)g_wp + (idx - T1); }
        float4 o;
        o.x = f2tff(t.x); o.y = f2tff(t.y); o.z = f2tff(t.z); o.w = f2tff(t.w);
        *dst = o;
    }
}

// ---------------------------------------------------------------------------
// K1: fused QKV GEMM, BK=32, 2-stage cp.async, dynamic smem.
// ---------------------------------------------------------------------------
__global__ __launch_bounds__(256) void qkv_mma_kernel(const float* __restrict__ bias)
{
    extern __shared__ float dynsm[];
    float* Asb = dynsm;
    float* Bsb = dynsm + 2 * A_STG;

    const int m0 = blockIdx.y * 128;
    const int n0 = blockIdx.x * 128;
    const int tid = threadIdx.x;
    const int wid = tid >> 5, lane = tid & 31;
    const int g = lane >> 2, tig = lane & 3;
    const int wm = wid >> 1, wn = wid & 1;

    const int aRow = tid >> 1;
    const int aK   = (tid & 1) * 16;
    const int am   = m0 + aRow;
    const bool av  = (am < MROWS);
    const float* arp = g_xs + (size_t)(av ? am : 0) * C_DIM;

    const int bk = tid >> 5;
    const int bn = (tid & 31) * 4;

    float c[2][8][4];
#pragma unroll
    for (int mt = 0; mt < 2; ++mt)
#pragma unroll
        for (int nt = 0; nt < 8; ++nt)
#pragma unroll
            for (int j = 0; j < 4; ++j) c[mt][nt][j] = 0.f;

    auto load_stage = [&](int s, int k0) {
        unsigned ad = smem_u32(&Asb[s * A_STG + aRow * A_LD + aK]);
        unsigned bd = smem_u32(&Bsb[s * B_STG + bk * B_LD + bn]);
#pragma unroll
        for (int i = 0; i < 4; ++i)
            cpasync16(ad + 16 * i, arp + k0 + aK + 4 * i, av);
#pragma unroll
        for (int i = 0; i < 4; ++i)
            cpasync16(bd + (8 * i) * B_LD * 4,
                      g_wq + (size_t)(k0 + bk + 8 * i) * QKV_N + n0 + bn, true);
        CP_COMMIT();
    };

    const int NKT = C_DIM / 32;
    load_stage(0, 0);

    for (int kt = 0; kt < NKT; ++kt) {
        int s = kt & 1;
        if (kt + 1 < NKT) { load_stage(s ^ 1, (kt + 1) * 32); CP_WAIT(1); }
        else              { CP_WAIT(0); }
        __syncthreads();

        const unsigned* Au = (const unsigned*)(Asb + s * A_STG);
        const unsigned* Bu = (const unsigned*)(Bsb + s * B_STG);
#pragma unroll
        for (int ks = 0; ks < 4; ++ks) {
            unsigned a[2][4];
#pragma unroll
            for (int mt = 0; mt < 2; ++mt) {
                int mr = wm * 32 + mt * 16;
                a[mt][0] = Au[(mr + g    ) * A_LD + ks * 8 + tig];
                a[mt][1] = Au[(mr + g + 8) * A_LD + ks * 8 + tig];
                a[mt][2] = Au[(mr + g    ) * A_LD + ks * 8 + tig + 4];
                a[mt][3] = Au[(mr + g + 8) * A_LD + ks * 8 + tig + 4];
            }
            unsigned b[8][2];
#pragma unroll
            for (int nt = 0; nt < 8; ++nt) {
                int nc = wn * 64 + nt * 8 + g;
                b[nt][0] = Bu[(ks * 8 + tig    ) * B_LD + nc];
                b[nt][1] = Bu[(ks * 8 + tig + 4) * B_LD + nc];
            }
#pragma unroll
            for (int mt = 0; mt < 2; ++mt)
#pragma unroll
                for (int nt = 0; nt < 8; ++nt) mma8(c[mt][nt], a[mt], b[nt]);
        }
        __syncthreads();
    }

    float* bufs[3] = {g_q, g_k, g_v};
#pragma unroll
    for (int nt = 0; nt < 8; ++nt) {
        int col = n0 + wn * 64 + nt * 8 + tig * 2;
        int which = col / C_DIM;
        int c2 = col % C_DIM;
        int head = c2 >> 6, db = c2 & 63;
        float b0v = bias[col], b1v = bias[col + 1];
        float* buf = bufs[which];
#pragma unroll
        for (int mt = 0; mt < 2; ++mt) {
#pragma unroll
            for (int h = 0; h < 2; ++h) {
                int m = m0 + wm * 32 + mt * 16 + g + h * 8;
                if (m >= MROWS) continue;
                int bb = m / NSEQ, nn = m % NSEQ;
                float* dst = buf + (size_t)bb * (HEADS * NSEQ * HD)
                                 + (size_t)head * (NSEQ * HD)
                                 + (size_t)nn * HD + db;
                float2 v;
                v.x = f2tff(c[mt][nt][h * 2 + 0] + b0v);
                v.y = f2tff(c[mt][nt][h * 2 + 1] + b1v);
                *(float2*)dst = v;
            }
        }
    }
}

// ---------------------------------------------------------------------------
// K2: rel bias GEMMs — 4 bh per block sharing one R tile; 4x4 reg blocking.
// ---------------------------------------------------------------------------
__global__ __launch_bounds__(256) void rel_kernel(
    const float* __restrict__ rph, const float* __restrict__ rpw)
{
    __shared__ float qs[4][32 * 65];
    __shared__ float RsT[64 * 33];

    const int bh0 = blockIdx.y * 4;
    const int idx0 = blockIdx.x;
    const int variant = blockIdx.z;
    const int tid = threadIdx.x;

    const float* rp = (variant == 0) ? rph : rpw;
#pragma unroll
    for (int it = 0; it < 8; ++it) {
        int idx = tid + it * 256;
        int k = idx >> 6, c = idx & 63;
        RsT[c * 33 + k] = rp[(size_t)(idx0 - k + 31) * HD + c];
    }
#pragma unroll
    for (int it = 0; it < 32; ++it) {
        int idx = tid + it * 256;
        int grp = idx >> 11;
        int w = idx & 2047;
        int r = w >> 6, c = w & 63;
        int bh = bh0 + grp;
        int n = (variant == 0) ? (NT + idx0 * 32 + r) : (NT + r * 32 + idx0);
        qs[grp][r * 65 + c] = g_q[((size_t)bh * NSEQ + n) * HD + c];
    }
    __syncthreads();

    const int grp = tid >> 6;
    const int stid = tid & 63;
    const int bh = bh0 + grp;
    const int tr = stid >> 3;
    const int tk = stid & 7;
    const float* qsg = qs[grp];

    float acc[4][4];
#pragma unroll
    for (int i = 0; i < 4; ++i)
#pragma unroll
        for (int j = 0; j < 4; ++j) acc[i][j] = 0.f;

#pragma unroll 4
    for (int c = 0; c < 64; ++c) {
        float q[4], rv[4];
#pragma unroll
        for (int i = 0; i < 4; ++i) q[i] = qsg[(tr * 4 + i) * 65 + c];
#pragma unroll
        for (int j = 0; j < 4; ++j) rv[j] = RsT[c * 33 + tk * 4 + j];
#pragma unroll
        for (int i = 0; i < 4; ++i)
#pragma unroll
            for (int j = 0; j < 4; ++j) acc[i][j] += q[i] * rv[j];
    }

    float* outb = (variant == 0) ? g_relh : g_relw;
#pragma unroll
    for (int i = 0; i < 4; ++i) {
        int row = tr * 4 + i;
        size_t base = (variant == 0)
            ? ((((size_t)bh * 32 + idx0) * 32 + row) * 32)
            : ((((size_t)bh * 32 + row) * 32 + idx0) * 32);
        float4 v;
        v.x = acc[i][0]; v.y = acc[i][1]; v.z = acc[i][2]; v.w = acc[i][3];
        *(float4*)(outb + base + tk * 4) = v;
    }
}

// ---------------------------------------------------------------------------
// K3: FA2-style flash attention. q-tile 128, warp = 16 rows x 64 keys.
// Register softmax (4-lane shfl), P via shfl permutation, no S/P smem.
// ---------------------------------------------------------------------------
#define ATT_SM_FLOATS (128 * 68 + 64 * 68 + 64 * 72 + 2 * 128 * 32)
#define ATT_SM_BYTES  (ATT_SM_FLOATS * 4)   // 103424

__global__ __launch_bounds__(256, 2) void attn_mma_kernel()
{
    extern __shared__ float sm[];
    float* Qs  = sm;                    // [128][68] tf32, prescaled
    float* Ks  = Qs + 128 * 68;         // [64][68]
    float* Vs  = Ks + 64 * 68;          // [64][72]
    float* rhs = Vs + 64 * 72;          // [128][32]
    float* rws = rhs + 128 * 32;        // [128][32]

    const int tid = threadIdx.x;
    const int wid = tid >> 5, lane = tid & 31;
    const int g = lane >> 2, tig = lane & 3;
    const int bh = blockIdx.y;
    const int b = bh / HEADS, head = bh % HEADS;
    const int q0 = blockIdx.x * 128;

    const float* qbase = g_q + (size_t)bh * NSEQ * HD;
    const float* kbase = g_k + (size_t)bh * NSEQ * HD;
    const float* vbase = g_v + (size_t)bh * NSEQ * HD;

    const int r0 = wid * 16 + g;        // warp-owned rows
    const int r1 = r0 + 8;
    const int qg0 = q0 + r0, qg1 = q0 + r1;

    // stage Q (128 rows), prescaled by 0.125 (exact pow2)
#pragma unroll
    for (int it = 0; it < 8; ++it) {
        int idx = tid + it * 256;       // 2048 float4
        int r = idx >> 4, d = (idx & 15) * 4;
        int qg = q0 + r;
        float4 t = (qg < NSEQ) ? *(const float4*)(qbase + (size_t)qg * HD + d)
                               : make_float4(0.f, 0.f, 0.f, 0.f);
        float4 o;
        o.x = t.x * 0.125f; o.y = t.y * 0.125f;
        o.z = t.z * 0.125f; o.w = t.w * 0.125f;
        *(float4*)&Qs[r * 68 + d] = o;
    }
    // stage rel bias rows
#pragma unroll
    for (int it = 0; it < 4; ++it) {
        int idx = tid + it * 256;       // 1024 float4
        int r = idx >> 3, c4 = (idx & 7) * 4;
        int qg = q0 + r;
        float4 hv = make_float4(0.f, 0.f, 0.f, 0.f), wv = hv;
        if (qg >= NT && qg < NSEQ) {
            int pix = qg - NT;
            int hq = pix >> 5, wq = pix & 31;
            size_t rbase = (((size_t)bh * 32 + hq) * 32 + wq) * 32;
            hv = *(const float4*)(g_relh + rbase + c4);
            wv = *(const float4*)(g_relw + rbase + c4);
        }
        *(float4*)&rhs[r * 32 + c4] = hv;
        *(float4*)&rws[r * 32 + c4] = wv;
    }

    float m0r = -3.0e38f, l0r = 0.f;
    float m1r = -3.0e38f, l1r = 0.f;
    float oc[8][4];
#pragma unroll
    for (int nt = 0; nt < 8; ++nt)
#pragma unroll
        for (int j = 0; j < 4; ++j) oc[nt][j] = 0.f;

    __syncthreads();

    const int srcA = (lane & ~3) | (tig >> 1);
    const int srcB = srcA + 2;
    const bool odd = (tig & 1);

    for (int k0 = 0; k0 < NSEQ; k0 += 64) {
        // stage K/V
#pragma unroll
        for (int it = 0; it < 4; ++it) {
            int idx = tid + it * 256;   // 1024 float4
            int r = idx >> 4, d = (idx & 15) * 4;
            int kg = k0 + r;
            float4 kv, vv;
            if (kg < NSEQ) {
                kv = *(const float4*)(kbase + (size_t)kg * HD + d);
                vv = *(const float4*)(vbase + (size_t)kg * HD + d);
            } else {
                kv = make_float4(0.f, 0.f, 0.f, 0.f);
                vv = kv;
            }
            *(float4*)&Ks[r * 68 + d] = kv;
            *(float4*)&Vs[r * 72 + d] = vv;
        }
        __syncthreads();

        const unsigned* Qu = (const unsigned*)Qs;
        const unsigned* Ku = (const unsigned*)Ks;
        const unsigned* Vu = (const unsigned*)Vs;

        // S = Q @ K^T : warp tile 16 x 64
        float sc[8][4];
#pragma unroll
        for (int nt = 0; nt < 8; ++nt)
#pragma unroll
            for (int j = 0; j < 4; ++j) sc[nt][j] = 0.f;
#pragma unroll
        for (int ks = 0; ks < 8; ++ks) {
            unsigned a[4];
            int mr = wid * 16;
            a[0] = Qu[(mr + g    ) * 68 + ks * 8 + tig];
            a[1] = Qu[(mr + g + 8) * 68 + ks * 8 + tig];
            a[2] = Qu[(mr + g    ) * 68 + ks * 8 + tig + 4];
            a[3] = Qu[(mr + g + 8) * 68 + ks * 8 + tig + 4];
#pragma unroll
            for (int nt = 0; nt < 8; ++nt) {
                unsigned bb[2];
                int key = nt * 8 + g;
                bb[0] = Ku[key * 68 + ks * 8 + tig];
                bb[1] = Ku[key * 68 + ks * 8 + tig + 4];
                mma8(sc[nt], a, bb);
            }
        }

        // bias + mask in registers; local row maxes
        float tm0 = -3.0e38f, tm1 = -3.0e38f;
#pragma unroll
        for (int nt = 0; nt < 8; ++nt) {
#pragma unroll
            for (int e = 0; e < 2; ++e) {
                int jg = k0 + nt * 8 + tig * 2 + e;
                float v0 = sc[nt][e];
                float v1 = sc[nt][2 + e];
                if (jg >= NSEQ) {
                    v0 = -1e30f; v1 = -1e30f;
                } else {
                    if (qg0 >= NT) {
                        if (jg < NT) v0 -= 100.f;
                        else {
                            int pj = jg - NT;
                            v0 += rhs[r0 * 32 + (pj >> 5)] + rws[r0 * 32 + (pj & 31)];
                        }
                    }
                    if (qg1 >= NT) {
                        if (jg < NT) v1 -= 100.f;
                        else {
                            int pj = jg - NT;
                            v1 += rhs[r1 * 32 + (pj >> 5)] + rws[r1 * 32 + (pj & 31)];
                        }
                    }
                }
                sc[nt][e] = v0;     tm0 = fmaxf(tm0, v0);
                sc[nt][2 + e] = v1; tm1 = fmaxf(tm1, v1);
            }
        }
        tm0 = fmaxf(tm0, __shfl_xor_sync(0xffffffffu, tm0, 1));
        tm0 = fmaxf(tm0, __shfl_xor_sync(0xffffffffu, tm0, 2));
        tm1 = fmaxf(tm1, __shfl_xor_sync(0xffffffffu, tm1, 1));
        tm1 = fmaxf(tm1, __shfl_xor_sync(0xffffffffu, tm1, 2));

        float nm0 = fmaxf(m0r, tm0), nm1 = fmaxf(m1r, tm1);
        float s0 = __expf(m0r - nm0), s1 = __expf(m1r - nm1);
        float sum0 = 0.f, sum1 = 0.f;
#pragma unroll
        for (int nt = 0; nt < 8; ++nt) {
#pragma unroll
            for (int e = 0; e < 2; ++e) {
                float p0 = __expf(sc[nt][e] - nm0);
                float p1 = __expf(sc[nt][2 + e] - nm1);
                sum0 += p0; sum1 += p1;
                sc[nt][e] = f2tff(p0);
                sc[nt][2 + e] = f2tff(p1);
            }
        }
        sum0 += __shfl_xor_sync(0xffffffffu, sum0, 1);
        sum0 += __shfl_xor_sync(0xffffffffu, sum0, 2);
        sum1 += __shfl_xor_sync(0xffffffffu, sum1, 1);
        sum1 += __shfl_xor_sync(0xffffffffu, sum1, 2);
        l0r = l0r * s0 + sum0; m0r = nm0;
        l1r = l1r * s1 + sum1; m1r = nm1;

        // rescale O
#pragma unroll
        for (int nt = 0; nt < 8; ++nt) {
            oc[nt][0] *= s0; oc[nt][1] *= s0;
            oc[nt][2] *= s1; oc[nt][3] *= s1;
        }

        // O += P @ V, A-fragments by shfl permutation of sc
#pragma unroll
        for (int ks = 0; ks < 8; ++ks) {
            float x0 = __shfl_sync(0xffffffffu, sc[ks][0], srcA);
            float x1 = __shfl_sync(0xffffffffu, sc[ks][1], srcA);
            float x2 = __shfl_sync(0xffffffffu, sc[ks][2], srcA);
            float x3 = __shfl_sync(0xffffffffu, sc[ks][3], srcA);
            float y0 = __shfl_sync(0xffffffffu, sc[ks][0], srcB);
            float y1 = __shfl_sync(0xffffffffu, sc[ks][1], srcB);
            float y2 = __shfl_sync(0xffffffffu, sc[ks][2], srcB);
            float y3 = __shfl_sync(0xffffffffu, sc[ks][3], srcB);
            unsigned a[4];
            a[0] = __float_as_uint(odd ? x1 : x0);
            a[1] = __float_as_uint(odd ? x3 : x2);
            a[2] = __float_as_uint(odd ? y1 : y0);
            a[3] = __float_as_uint(odd ? y3 : y2);
#pragma unroll
            for (int nt = 0; nt < 8; ++nt) {
                unsigned bb[2];
                int dcol = nt * 8 + g;
                bb[0] = Vu[(ks * 8 + tig    ) * 72 + dcol];
                bb[1] = Vu[(ks * 8 + tig + 4) * 72 + dcol];
                mma8(oc[nt], a, bb);
            }
        }
        __syncthreads();
    }

    // normalize + tf32-round + write context
    {
        float inv0 = (qg0 < NSEQ) ? (1.f / l0r) : 0.f;
        float inv1 = (qg1 < NSEQ) ? (1.f / l1r) : 0.f;
#pragma unroll
        for (int nt = 0; nt < 8; ++nt) {
            int col = nt * 8 + tig * 2;
            if (qg0 < NSEQ) {
                float2 v = make_float2(f2tff(oc[nt][0] * inv0), f2tff(oc[nt][1] * inv0));
                *(float2*)(g_ctx + ((size_t)b * NSEQ + qg0) * C_DIM + head * HD + col) = v;
            }
            if (qg1 < NSEQ) {
                float2 v = make_float2(f2tff(oc[nt][2] * inv1), f2tff(oc[nt][3] * inv1));
                *(float2*)(g_ctx + ((size_t)b * NSEQ + qg1) * C_DIM + head * HD + col) = v;
            }
        }
    }
}

// ---------------------------------------------------------------------------
// K4: output projection GEMM, BK=32, 2-stage cp.async, dynamic smem.
// ---------------------------------------------------------------------------
__global__ __launch_bounds__(256) void proj_mma_kernel(
    const float* __restrict__ bias, float* __restrict__ out)
{
    extern __shared__ float dynsm[];
    float* Asb = dynsm;
    float* Bsb = dynsm + 2 * A_STG;

    const int m0 = blockIdx.y * 128;
    const int n0 = blockIdx.x * 128;
    const int tid = threadIdx.x;
    const int wid = tid >> 5, lane = tid & 31;
    const int g = lane >> 2, tig = lane & 3;
    const int wm = wid >> 1, wn = wid & 1;

    const int aRow = tid >> 1;
    const int aK   = (tid & 1) * 16;
    const int am   = m0 + aRow;
    const bool av  = (am < MROWS);
    const float* arp = g_ctx + (size_t)(av ? am : 0) * C_DIM;

    const int bk = tid >> 5;
    const int bn = (tid & 31) * 4;

    float c[2][8][4];
#pragma unroll
    for (int mt = 0; mt < 2; ++mt)
#pragma unroll
        for (int nt = 0; nt < 8; ++nt)
#pragma unroll
            for (int j = 0; j < 4; ++j) c[mt][nt][j] = 0.f;

    auto load_stage = [&](int s, int k0) {
        unsigned ad = smem_u32(&Asb[s * A_STG + aRow * A_LD + aK]);
        unsigned bd = smem_u32(&Bsb[s * B_STG + bk * B_LD + bn]);
#pragma unroll
        for (int i = 0; i < 4; ++i)
            cpasync16(ad + 16 * i, arp + k0 + aK + 4 * i, av);
#pragma unroll
        for (int i = 0; i < 4; ++i)
            cpasync16(bd + (8 * i) * B_LD * 4,
                      g_wp + (size_t)(k0 + bk + 8 * i) * C_DIM + n0 + bn, true);
        CP_COMMIT();
    };

    const int NKT = C_DIM / 32;
    load_stage(0, 0);

    for (int kt = 0; kt < NKT; ++kt) {
        int s = kt & 1;
        if (kt + 1 < NKT) { load_stage(s ^ 1, (kt + 1) * 32); CP_WAIT(1); }
        else              { CP_WAIT(0); }
        __syncthreads();

        const unsigned* Au = (const unsigned*)(Asb + s * A_STG);
        const unsigned* Bu = (const unsigned*)(Bsb + s * B_STG);
#pragma unroll
        for (int ks = 0; ks < 4; ++ks) {
            unsigned a[2][4];
#pragma unroll
            for (int mt = 0; mt < 2; ++mt) {
                int mr = wm * 32 + mt * 16;
                a[mt][0] = Au[(mr + g    ) * A_LD + ks * 8 + tig];
                a[mt][1] = Au[(mr + g + 8) * A_LD + ks * 8 + tig];
                a[mt][2] = Au[(mr + g    ) * A_LD + ks * 8 + tig + 4];
                a[mt][3] = Au[(mr + g + 8) * A_LD + ks * 8 + tig + 4];
            }
            unsigned b[8][2];
#pragma unroll
            for (int nt = 0; nt < 8; ++nt) {
                int nc = wn * 64 + nt * 8 + g;
                b[nt][0] = Bu[(ks * 8 + tig    ) * B_LD + nc];
                b[nt][1] = Bu[(ks * 8 + tig + 4) * B_LD + nc];
            }
#pragma unroll
            for (int mt = 0; mt < 2; ++mt)
#pragma unroll
                for (int nt = 0; nt < 8; ++nt) mma8(c[mt][nt], a[mt], b[nt]);
        }
        __syncthreads();
    }

#pragma unroll
    for (int nt = 0; nt < 8; ++nt) {
        int col = n0 + wn * 64 + nt * 8 + tig * 2;
        float b0v = bias[col], b1v = bias[col + 1];
#pragma unroll
        for (int mt = 0; mt < 2; ++mt) {
#pragma unroll
            for (int h = 0; h < 2; ++h) {
                int m = m0 + wm * 32 + mt * 16 + g + h * 8;
                if (m >= MROWS) continue;
                int bb = m / NSEQ, nn = m % NSEQ;
                float* dst = (nn < NT)
                    ? (out + XOUT_ELEMS + ((size_t)bb * NT + nn) * C_DIM)
                    : (out + ((size_t)bb * HW + (nn - NT)) * C_DIM);
                float2 v;
                v.x = c[mt][nt][h * 2 + 0] + b0v;
                v.y = c[mt][nt][h * 2 + 1] + b1v;
                *(float2*)(dst + col) = v;
            }
        }
    }
}

// ---------------------------------------------------------------------------
extern "C" void kernel_launch(void* const* d_in, const int* in_sizes, int n_in,
                              void* d_out, int out_size)
{
    const float* x      = (const float*)d_in[0];
    const float* vp     = (const float*)d_in[1];
    const float* qkv_w  = (const float*)d_in[2];
    const float* qkv_b  = (const float*)d_in[3];
    const float* proj_w = (const float*)d_in[4];
    const float* proj_b = (const float*)d_in[5];
    const float* rph    = (const float*)d_in[6];
    const float* rpw    = (const float*)d_in[7];
    float* out = (float*)d_out;

    (void)in_sizes; (void)n_in; (void)out_size;

    cudaFuncSetAttribute(qkv_mma_kernel,
                         cudaFuncAttributeMaxDynamicSharedMemorySize,
                         GEMM_SM_BYTES);
    cudaFuncSetAttribute(proj_mma_kernel,
                         cudaFuncAttributeMaxDynamicSharedMemorySize,
                         GEMM_SM_BYTES);
    cudaFuncSetAttribute(attn_mma_kernel,
                         cudaFuncAttributeMaxDynamicSharedMemorySize,
                         ATT_SM_BYTES);

    prep_xs_kernel<<<1184, 256>>>(x, vp);
    prep_w_kernel<<<1184, 256>>>(qkv_w, proj_w);
    qkv_mma_kernel<<<dim3(QKV_N / 128, (MROWS + 127) / 128), 256, GEMM_SM_BYTES>>>(qkv_b);
    rel_kernel<<<dim3(32, BHN / 4, 2), 256>>>(rph, rpw);
    attn_mma_kernel<<<dim3((NSEQ + 127) / 128, BHN), 256, ATT_SM_BYTES>>>();
    proj_mma_kernel<<<dim3(C_DIM / 128, (MROWS + 127) / 128), 256, GEMM_SM_BYTES>>>(proj_b, out);
}

// round 14
// speedup vs baseline: 1.4446x; 1.0371x over previous
#include <cuda_runtime.h>

// ---------------------------------------------------------------------------
// PromptedAttention: B=8, H=W=32, C=768, heads=12, hd=64, nt=8, N=1032
// Round 14: attention with register-resident Q fragments + cp.async
// double-buffered K/V at 2 CTAs/SM. GEMMs/rel from R12/R13.
// ---------------------------------------------------------------------------

#define BATCH     8
#define HEADS     12
#define HD        64
#define C_DIM     768
#define NT        8
#define HW        1024
#define NSEQ      1032
#define BHN       96
#define MROWS     8256
#define QKV_N     2304
#define XOUT_ELEMS 6291456

__device__ float g_q[BHN * NSEQ * HD];
__device__ float g_k[BHN * NSEQ * HD];
__device__ float g_v[BHN * NSEQ * HD];
__device__ float g_relh[BHN * 32 * 32 * 32];
__device__ float g_relw[BHN * 32 * 32 * 32];
__device__ float g_ctx[MROWS * C_DIM];
__device__ float g_xs[MROWS * C_DIM];
__device__ float g_wq[C_DIM * QKV_N];
__device__ float g_wp[C_DIM * C_DIM];

__device__ __forceinline__ unsigned f2tf(float f) {
    unsigned u;
    asm("cvt.rna.tf32.f32 %0, %1;" : "=r"(u) : "f"(f));
    return u;
}
__device__ __forceinline__ float f2tff(float f) { return __uint_as_float(f2tf(f)); }

__device__ __forceinline__ void mma8(float* c, const unsigned* a, const unsigned* b) {
    asm volatile(
        "mma.sync.aligned.m16n8k8.row.col.f32.tf32.tf32.f32 "
        "{%0,%1,%2,%3}, {%4,%5,%6,%7}, {%8,%9}, {%0,%1,%2,%3};\n"
        : "+f"(c[0]), "+f"(c[1]), "+f"(c[2]), "+f"(c[3])
        : "r"(a[0]), "r"(a[1]), "r"(a[2]), "r"(a[3]), "r"(b[0]), "r"(b[1]));
}

__device__ __forceinline__ unsigned smem_u32(const void* p) {
    return (unsigned)__cvta_generic_to_shared(p);
}
__device__ __forceinline__ void cpasync16(unsigned dst, const void* src, bool pred) {
    asm volatile("cp.async.cg.shared.global [%0], [%1], 16, %2;\n"
                 :: "r"(dst), "l"(src), "r"(pred ? 16 : 0));
}
#define CP_COMMIT() asm volatile("cp.async.commit_group;\n" ::: "memory")
#define CP_WAIT(N)  asm volatile("cp.async.wait_group %0;\n" :: "n"(N) : "memory")

#define A_LD 36
#define B_LD 136
#define A_STG (128 * A_LD)
#define B_STG (32 * B_LD)
#define GEMM_SM_BYTES (2 * (A_STG + B_STG) * 4)   // 71680

// ---------------------------------------------------------------------------
// K0a: build rounded concat g_xs.
// ---------------------------------------------------------------------------
__global__ __launch_bounds__(256) void prep_xs_kernel(
    const float* __restrict__ x, const float* __restrict__ vp)
{
    const int F4 = C_DIM / 4;
    const int total = MROWS * F4;
    for (int idx = blockIdx.x * 256 + threadIdx.x; idx < total;
         idx += gridDim.x * 256) {
        int row = idx / F4;
        int f4 = idx - row * F4;
        int b = row / NSEQ, n = row % NSEQ;
        const float4* src = (n < NT)
            ? (const float4*)(vp + ((size_t)b * NT + n) * C_DIM)
            : (const float4*)(x + ((size_t)b * HW + (n - NT)) * C_DIM);
        float4 t = src[f4];
        float4 o;
        o.x = f2tff(t.x); o.y = f2tff(t.y); o.z = f2tff(t.z); o.w = f2tff(t.w);
        ((float4*)g_xs)[idx] = o;
    }
}

__global__ __launch_bounds__(256) void prep_w_kernel(
    const float* __restrict__ wq, const float* __restrict__ wp)
{
    const int T1 = C_DIM * QKV_N / 4;
    const int T2 = C_DIM * C_DIM / 4;
    for (int idx = blockIdx.x * 256 + threadIdx.x; idx < T1 + T2;
         idx += gridDim.x * 256) {
        float4 t;
        float4* dst;
        if (idx < T1) { t = ((const float4*)wq)[idx]; dst = (float4*)g_wq + idx; }
        else { t = ((const float4*)wp)[idx - T1]; dst = (float4*)g_wp + (idx - T1); }
        float4 o;
        o.x = f2tff(t.x); o.y = f2tff(t.y); o.z = f2tff(t.z); o.w = f2tff(t.w);
        *dst = o;
    }
}

// ---------------------------------------------------------------------------
// K1: fused QKV GEMM, BK=32, 2-stage cp.async, dynamic smem.
// ---------------------------------------------------------------------------
__global__ __launch_bounds__(256) void qkv_mma_kernel(const float* __restrict__ bias)
{
    extern __shared__ float dynsm[];
    float* Asb = dynsm;
    float* Bsb = dynsm + 2 * A_STG;

    const int m0 = blockIdx.y * 128;
    const int n0 = blockIdx.x * 128;
    const int tid = threadIdx.x;
    const int wid = tid >> 5, lane = tid & 31;
    const int g = lane >> 2, tig = lane & 3;
    const int wm = wid >> 1, wn = wid & 1;

    const int aRow = tid >> 1;
    const int aK   = (tid & 1) * 16;
    const int am   = m0 + aRow;
    const bool av  = (am < MROWS);
    const float* arp = g_xs + (size_t)(av ? am : 0) * C_DIM;

    const int bk = tid >> 5;
    const int bn = (tid & 31) * 4;

    float c[2][8][4];
#pragma unroll
    for (int mt = 0; mt < 2; ++mt)
#pragma unroll
        for (int nt = 0; nt < 8; ++nt)
#pragma unroll
            for (int j = 0; j < 4; ++j) c[mt][nt][j] = 0.f;

    auto load_stage = [&](int s, int k0) {
        unsigned ad = smem_u32(&Asb[s * A_STG + aRow * A_LD + aK]);
        unsigned bd = smem_u32(&Bsb[s * B_STG + bk * B_LD + bn]);
#pragma unroll
        for (int i = 0; i < 4; ++i)
            cpasync16(ad + 16 * i, arp + k0 + aK + 4 * i, av);
#pragma unroll
        for (int i = 0; i < 4; ++i)
            cpasync16(bd + (8 * i) * B_LD * 4,
                      g_wq + (size_t)(k0 + bk + 8 * i) * QKV_N + n0 + bn, true);
        CP_COMMIT();
    };

    const int NKT = C_DIM / 32;
    load_stage(0, 0);

    for (int kt = 0; kt < NKT; ++kt) {
        int s = kt & 1;
        if (kt + 1 < NKT) { load_stage(s ^ 1, (kt + 1) * 32); CP_WAIT(1); }
        else              { CP_WAIT(0); }
        __syncthreads();

        const unsigned* Au = (const unsigned*)(Asb + s * A_STG);
        const unsigned* Bu = (const unsigned*)(Bsb + s * B_STG);
#pragma unroll
        for (int ks = 0; ks < 4; ++ks) {
            unsigned a[2][4];
#pragma unroll
            for (int mt = 0; mt < 2; ++mt) {
                int mr = wm * 32 + mt * 16;
                a[mt][0] = Au[(mr + g    ) * A_LD + ks * 8 + tig];
                a[mt][1] = Au[(mr + g + 8) * A_LD + ks * 8 + tig];
                a[mt][2] = Au[(mr + g    ) * A_LD + ks * 8 + tig + 4];
                a[mt][3] = Au[(mr + g + 8) * A_LD + ks * 8 + tig + 4];
            }
            unsigned b[8][2];
#pragma unroll
            for (int nt = 0; nt < 8; ++nt) {
                int nc = wn * 64 + nt * 8 + g;
                b[nt][0] = Bu[(ks * 8 + tig    ) * B_LD + nc];
                b[nt][1] = Bu[(ks * 8 + tig + 4) * B_LD + nc];
            }
#pragma unroll
            for (int mt = 0; mt < 2; ++mt)
#pragma unroll
                for (int nt = 0; nt < 8; ++nt) mma8(c[mt][nt], a[mt], b[nt]);
        }
        __syncthreads();
    }

    float* bufs[3] = {g_q, g_k, g_v};
#pragma unroll
    for (int nt = 0; nt < 8; ++nt) {
        int col = n0 + wn * 64 + nt * 8 + tig * 2;
        int which = col / C_DIM;
        int c2 = col % C_DIM;
        int head = c2 >> 6, db = c2 & 63;
        float b0v = bias[col], b1v = bias[col + 1];
        float* buf = bufs[which];
#pragma unroll
        for (int mt = 0; mt < 2; ++mt) {
#pragma unroll
            for (int h = 0; h < 2; ++h) {
                int m = m0 + wm * 32 + mt * 16 + g + h * 8;
                if (m >= MROWS) continue;
                int bb = m / NSEQ, nn = m % NSEQ;
                float* dst = buf + (size_t)bb * (HEADS * NSEQ * HD)
                                 + (size_t)head * (NSEQ * HD)
                                 + (size_t)nn * HD + db;
                float2 v;
                v.x = f2tff(c[mt][nt][h * 2 + 0] + b0v);
                v.y = f2tff(c[mt][nt][h * 2 + 1] + b1v);
                *(float2*)dst = v;
            }
        }
    }
}

// ---------------------------------------------------------------------------
// K2: rel bias GEMMs — 4 bh per block sharing one R tile; 4x4 reg blocking.
// ---------------------------------------------------------------------------
__global__ __launch_bounds__(256) void rel_kernel(
    const float* __restrict__ rph, const float* __restrict__ rpw)
{
    __shared__ float qs[4][32 * 65];
    __shared__ float RsT[64 * 33];

    const int bh0 = blockIdx.y * 4;
    const int idx0 = blockIdx.x;
    const int variant = blockIdx.z;
    const int tid = threadIdx.x;

    const float* rp = (variant == 0) ? rph : rpw;
#pragma unroll
    for (int it = 0; it < 8; ++it) {
        int idx = tid + it * 256;
        int k = idx >> 6, c = idx & 63;
        RsT[c * 33 + k] = rp[(size_t)(idx0 - k + 31) * HD + c];
    }
#pragma unroll
    for (int it = 0; it < 32; ++it) {
        int idx = tid + it * 256;
        int grp = idx >> 11;
        int w = idx & 2047;
        int r = w >> 6, c = w & 63;
        int bh = bh0 + grp;
        int n = (variant == 0) ? (NT + idx0 * 32 + r) : (NT + r * 32 + idx0);
        qs[grp][r * 65 + c] = g_q[((size_t)bh * NSEQ + n) * HD + c];
    }
    __syncthreads();

    const int grp = tid >> 6;
    const int stid = tid & 63;
    const int bh = bh0 + grp;
    const int tr = stid >> 3;
    const int tk = stid & 7;
    const float* qsg = qs[grp];

    float acc[4][4];
#pragma unroll
    for (int i = 0; i < 4; ++i)
#pragma unroll
        for (int j = 0; j < 4; ++j) acc[i][j] = 0.f;

#pragma unroll 4
    for (int c = 0; c < 64; ++c) {
        float q[4], rv[4];
#pragma unroll
        for (int i = 0; i < 4; ++i) q[i] = qsg[(tr * 4 + i) * 65 + c];
#pragma unroll
        for (int j = 0; j < 4; ++j) rv[j] = RsT[c * 33 + tk * 4 + j];
#pragma unroll
        for (int i = 0; i < 4; ++i)
#pragma unroll
            for (int j = 0; j < 4; ++j) acc[i][j] += q[i] * rv[j];
    }

    float* outb = (variant == 0) ? g_relh : g_relw;
#pragma unroll
    for (int i = 0; i < 4; ++i) {
        int row = tr * 4 + i;
        size_t base = (variant == 0)
            ? ((((size_t)bh * 32 + idx0) * 32 + row) * 32)
            : ((((size_t)bh * 32 + row) * 32 + idx0) * 32);
        float4 v;
        v.x = acc[i][0]; v.y = acc[i][1]; v.z = acc[i][2]; v.w = acc[i][3];
        *(float4*)(outb + base + tk * 4) = v;
    }
}

// ---------------------------------------------------------------------------
// K3: FA2 attention, register Q fragments, cp.async double-buffered K/V.
// ---------------------------------------------------------------------------
#define KS_STG (64 * 68)
#define VS_STG (64 * 72)
#define ATT_SM_FLOATS (2 * KS_STG + 2 * VS_STG + 2 * 128 * 32)
#define ATT_SM_BYTES  (ATT_SM_FLOATS * 4)   // 104448

__global__ __launch_bounds__(256, 2) void attn_mma_kernel()
{
    extern __shared__ float sm[];
    float* Ks  = sm;                    // [2][64][68]
    float* Vs  = Ks + 2 * KS_STG;       // [2][64][72]
    float* rhs = Vs + 2 * VS_STG;       // [128][32]
    float* rws = rhs + 128 * 32;        // [128][32]

    const int tid = threadIdx.x;
    const int wid = tid >> 5, lane = tid & 31;
    const int g = lane >> 2, tig = lane & 3;
    const int bh = blockIdx.y;
    const int b = bh / HEADS, head = bh % HEADS;
    const int q0 = blockIdx.x * 128;

    const float* qbase = g_q + (size_t)bh * NSEQ * HD;
    const float* kbase = g_k + (size_t)bh * NSEQ * HD;
    const float* vbase = g_v + (size_t)bh * NSEQ * HD;

    const int r0 = wid * 16 + g;
    const int r1 = r0 + 8;
    const int qg0 = q0 + r0, qg1 = q0 + r1;

    // K/V staging (cp.async, float4 granularity)
    const int lr  = tid >> 4;           // 0..15
    const int ld4 = (tid & 15) * 4;     // 0..60
    auto load_kv = [&](int s, int k0) {
        float* Ksb = Ks + s * KS_STG;
        float* Vsb = Vs + s * VS_STG;
#pragma unroll
        for (int t = 0; t < 4; ++t) {
            int r = lr + t * 16;
            int kg = k0 + r;
            bool pv = (kg < NSEQ);
            const float* ksrc = kbase + (size_t)(pv ? kg : 0) * HD + ld4;
            const float* vsrc = vbase + (size_t)(pv ? kg : 0) * HD + ld4;
            cpasync16(smem_u32(&Ksb[r * 68 + ld4]), ksrc, pv);
            cpasync16(smem_u32(&Vsb[r * 72 + ld4]), vsrc, pv);
        }
        CP_COMMIT();
    };

    load_kv(0, 0);

    // Q fragments straight from gmem (row-major == fragment layout), x0.125
    float qa[8][4];
    {
        const bool v0 = (qg0 < NSEQ), v1 = (qg1 < NSEQ);
        const float* qr0 = qbase + (size_t)(v0 ? qg0 : 0) * HD;
        const float* qr1 = qbase + (size_t)(v1 ? qg1 : 0) * HD;
#pragma unroll
        for (int ks = 0; ks < 8; ++ks) {
            qa[ks][0] = v0 ? qr0[ks * 8 + tig]     * 0.125f : 0.f;
            qa[ks][1] = v1 ? qr1[ks * 8 + tig]     * 0.125f : 0.f;
            qa[ks][2] = v0 ? qr0[ks * 8 + tig + 4] * 0.125f : 0.f;
            qa[ks][3] = v1 ? qr1[ks * 8 + tig + 4] * 0.125f : 0.f;
        }
    }

    // rel bias rows for the q-tile
#pragma unroll
    for (int it = 0; it < 4; ++it) {
        int idx = tid + it * 256;       // 1024 float4
        int r = idx >> 3, c4 = (idx & 7) * 4;
        int qg = q0 + r;
        float4 hv = make_float4(0.f, 0.f, 0.f, 0.f), wv = hv;
        if (qg >= NT && qg < NSEQ) {
            int pix = qg - NT;
            int hq = pix >> 5, wq = pix & 31;
            size_t rbase = (((size_t)bh * 32 + hq) * 32 + wq) * 32;
            hv = *(const float4*)(g_relh + rbase + c4);
            wv = *(const float4*)(g_relw + rbase + c4);
        }
        *(float4*)&rhs[r * 32 + c4] = hv;
        *(float4*)&rws[r * 32 + c4] = wv;
    }

    float m0r = -3.0e38f, l0r = 0.f;
    float m1r = -3.0e38f, l1r = 0.f;
    float oc[8][4];
#pragma unroll
    for (int nt = 0; nt < 8; ++nt)
#pragma unroll
        for (int j = 0; j < 4; ++j) oc[nt][j] = 0.f;

    __syncthreads();   // rhs/rws visible (K/V stage 0 guarded by CP_WAIT below)

    const int srcA = (lane & ~3) | (tig >> 1);
    const int srcB = srcA + 2;
    const bool odd = (tig & 1);

    const int NIT = (NSEQ + 63) / 64;   // 17
    for (int itk = 0; itk < NIT; ++itk) {
        int s = itk & 1;
        int k0 = itk * 64;
        if (itk + 1 < NIT) { load_kv(s ^ 1, k0 + 64); CP_WAIT(1); }
        else               { CP_WAIT(0); }
        __syncthreads();

        const unsigned* Ku = (const unsigned*)(Ks + s * KS_STG);
        const unsigned* Vu = (const unsigned*)(Vs + s * VS_STG);

        // S = Q @ K^T : warp tile 16 x 64
        float sc[8][4];
#pragma unroll
        for (int nt = 0; nt < 8; ++nt)
#pragma unroll
            for (int j = 0; j < 4; ++j) sc[nt][j] = 0.f;
#pragma unroll
        for (int ks = 0; ks < 8; ++ks) {
            unsigned a[4];
            a[0] = f2tf(qa[ks][0]);
            a[1] = f2tf(qa[ks][1]);
            a[2] = f2tf(qa[ks][2]);
            a[3] = f2tf(qa[ks][3]);
#pragma unroll
            for (int nt = 0; nt < 8; ++nt) {
                unsigned bb[2];
                int key = nt * 8 + g;
                bb[0] = Ku[key * 68 + ks * 8 + tig];
                bb[1] = Ku[key * 68 + ks * 8 + tig + 4];
                mma8(sc[nt], a, bb);
            }
        }

        // bias + mask in registers; local row maxes
        float tm0 = -3.0e38f, tm1 = -3.0e38f;
#pragma unroll
        for (int nt = 0; nt < 8; ++nt) {
#pragma unroll
            for (int e = 0; e < 2; ++e) {
                int jg = k0 + nt * 8 + tig * 2 + e;
                float v0 = sc[nt][e];
                float v1 = sc[nt][2 + e];
                if (jg >= NSEQ) {
                    v0 = -1e30f; v1 = -1e30f;
                } else {
                    if (qg0 >= NT) {
                        if (jg < NT) v0 -= 100.f;
                        else {
                            int pj = jg - NT;
                            v0 += rhs[r0 * 32 + (pj >> 5)] + rws[r0 * 32 + (pj & 31)];
                        }
                    }
                    if (qg1 >= NT) {
                        if (jg < NT) v1 -= 100.f;
                        else {
                            int pj = jg - NT;
                            v1 += rhs[r1 * 32 + (pj >> 5)] + rws[r1 * 32 + (pj & 31)];
                        }
                    }
                }
                sc[nt][e] = v0;     tm0 = fmaxf(tm0, v0);
                sc[nt][2 + e] = v1; tm1 = fmaxf(tm1, v1);
            }
        }
        tm0 = fmaxf(tm0, __shfl_xor_sync(0xffffffffu, tm0, 1));
        tm0 = fmaxf(tm0, __shfl_xor_sync(0xffffffffu, tm0, 2));
        tm1 = fmaxf(tm1, __shfl_xor_sync(0xffffffffu, tm1, 1));
        tm1 = fmaxf(tm1, __shfl_xor_sync(0xffffffffu, tm1, 2));

        float nm0 = fmaxf(m0r, tm0), nm1 = fmaxf(m1r, tm1);
        float s0 = __expf(m0r - nm0), s1 = __expf(m1r - nm1);
        float sum0 = 0.f, sum1 = 0.f;
#pragma unroll
        for (int nt = 0; nt < 8; ++nt) {
#pragma unroll
            for (int e = 0; e < 2; ++e) {
                float p0 = __expf(sc[nt][e] - nm0);
                float p1 = __expf(sc[nt][2 + e] - nm1);
                sum0 += p0; sum1 += p1;
                sc[nt][e] = f2tff(p0);
                sc[nt][2 + e] = f2tff(p1);
            }
        }
        sum0 += __shfl_xor_sync(0xffffffffu, sum0, 1);
        sum0 += __shfl_xor_sync(0xffffffffu, sum0, 2);
        sum1 += __shfl_xor_sync(0xffffffffu, sum1, 1);
        sum1 += __shfl_xor_sync(0xffffffffu, sum1, 2);
        l0r = l0r * s0 + sum0; m0r = nm0;
        l1r = l1r * s1 + sum1; m1r = nm1;

#pragma unroll
        for (int nt = 0; nt < 8; ++nt) {
            oc[nt][0] *= s0; oc[nt][1] *= s0;
            oc[nt][2] *= s1; oc[nt][3] *= s1;
        }

        // O += P @ V, A-fragments via shfl permutation
#pragma unroll
        for (int ks = 0; ks < 8; ++ks) {
            float x0 = __shfl_sync(0xffffffffu, sc[ks][0], srcA);
            float x1 = __shfl_sync(0xffffffffu, sc[ks][1], srcA);
            float x2 = __shfl_sync(0xffffffffu, sc[ks][2], srcA);
            float x3 = __shfl_sync(0xffffffffu, sc[ks][3], srcA);
            float y0 = __shfl_sync(0xffffffffu, sc[ks][0], srcB);
            float y1 = __shfl_sync(0xffffffffu, sc[ks][1], srcB);
            float y2 = __shfl_sync(0xffffffffu, sc[ks][2], srcB);
            float y3 = __shfl_sync(0xffffffffu, sc[ks][3], srcB);
            unsigned a[4];
            a[0] = __float_as_uint(odd ? x1 : x0);
            a[1] = __float_as_uint(odd ? x3 : x2);
            a[2] = __float_as_uint(odd ? y1 : y0);
            a[3] = __float_as_uint(odd ? y3 : y2);
#pragma unroll
            for (int nt = 0; nt < 8; ++nt) {
                unsigned bb[2];
                int dcol = nt * 8 + g;
                bb[0] = Vu[(ks * 8 + tig    ) * 72 + dcol];
                bb[1] = Vu[(ks * 8 + tig + 4) * 72 + dcol];
                mma8(oc[nt], a, bb);
            }
        }
        __syncthreads();
    }

    // normalize + tf32-round + write context
    {
        float inv0 = (qg0 < NSEQ) ? (1.f / l0r) : 0.f;
        float inv1 = (qg1 < NSEQ) ? (1.f / l1r) : 0.f;
#pragma unroll
        for (int nt = 0; nt < 8; ++nt) {
            int col = nt * 8 + tig * 2;
            if (qg0 < NSEQ) {
                float2 v = make_float2(f2tff(oc[nt][0] * inv0), f2tff(oc[nt][1] * inv0));
                *(float2*)(g_ctx + ((size_t)b * NSEQ + qg0) * C_DIM + head * HD + col) = v;
            }
            if (qg1 < NSEQ) {
                float2 v = make_float2(f2tff(oc[nt][2] * inv1), f2tff(oc[nt][3] * inv1));
                *(float2*)(g_ctx + ((size_t)b * NSEQ + qg1) * C_DIM + head * HD + col) = v;
            }
        }
    }
}

// ---------------------------------------------------------------------------
// K4: output projection GEMM, BK=32, 2-stage cp.async, dynamic smem.
// ---------------------------------------------------------------------------
__global__ __launch_bounds__(256) void proj_mma_kernel(
    const float* __restrict__ bias, float* __restrict__ out)
{
    extern __shared__ float dynsm[];
    float* Asb = dynsm;
    float* Bsb = dynsm + 2 * A_STG;

    const int m0 = blockIdx.y * 128;
    const int n0 = blockIdx.x * 128;
    const int tid = threadIdx.x;
    const int wid = tid >> 5, lane = tid & 31;
    const int g = lane >> 2, tig = lane & 3;
    const int wm = wid >> 1, wn = wid & 1;

    const int aRow = tid >> 1;
    const int aK   = (tid & 1) * 16;
    const int am   = m0 + aRow;
    const bool av  = (am < MROWS);
    const float* arp = g_ctx + (size_t)(av ? am : 0) * C_DIM;

    const int bk = tid >> 5;
    const int bn = (tid & 31) * 4;

    float c[2][8][4];
#pragma unroll
    for (int mt = 0; mt < 2; ++mt)
#pragma unroll
        for (int nt = 0; nt < 8; ++nt)
#pragma unroll
            for (int j = 0; j < 4; ++j) c[mt][nt][j] = 0.f;

    auto load_stage = [&](int s, int k0) {
        unsigned ad = smem_u32(&Asb[s * A_STG + aRow * A_LD + aK]);
        unsigned bd = smem_u32(&Bsb[s * B_STG + bk * B_LD + bn]);
#pragma unroll
        for (int i = 0; i < 4; ++i)
            cpasync16(ad + 16 * i, arp + k0 + aK + 4 * i, av);
#pragma unroll
        for (int i = 0; i < 4; ++i)
            cpasync16(bd + (8 * i) * B_LD * 4,
                      g_wp + (size_t)(k0 + bk + 8 * i) * C_DIM + n0 + bn, true);
        CP_COMMIT();
    };

    const int NKT = C_DIM / 32;
    load_stage(0, 0);

    for (int kt = 0; kt < NKT; ++kt) {
        int s = kt & 1;
        if (kt + 1 < NKT) { load_stage(s ^ 1, (kt + 1) * 32); CP_WAIT(1); }
        else              { CP_WAIT(0); }
        __syncthreads();

        const unsigned* Au = (const unsigned*)(Asb + s * A_STG);
        const unsigned* Bu = (const unsigned*)(Bsb + s * B_STG);
#pragma unroll
        for (int ks = 0; ks < 4; ++ks) {
            unsigned a[2][4];
#pragma unroll
            for (int mt = 0; mt < 2; ++mt) {
                int mr = wm * 32 + mt * 16;
                a[mt][0] = Au[(mr + g    ) * A_LD + ks * 8 + tig];
                a[mt][1] = Au[(mr + g + 8) * A_LD + ks * 8 + tig];
                a[mt][2] = Au[(mr + g    ) * A_LD + ks * 8 + tig + 4];
                a[mt][3] = Au[(mr + g + 8) * A_LD + ks * 8 + tig + 4];
            }
            unsigned b[8][2];
#pragma unroll
            for (int nt = 0; nt < 8; ++nt) {
                int nc = wn * 64 + nt * 8 + g;
                b[nt][0] = Bu[(ks * 8 + tig    ) * B_LD + nc];
                b[nt][1] = Bu[(ks * 8 + tig + 4) * B_LD + nc];
            }
#pragma unroll
            for (int mt = 0; mt < 2; ++mt)
#pragma unroll
                for (int nt = 0; nt < 8; ++nt) mma8(c[mt][nt], a[mt], b[nt]);
        }
        __syncthreads();
    }

#pragma unroll
    for (int nt = 0; nt < 8; ++nt) {
        int col = n0 + wn * 64 + nt * 8 + tig * 2;
        float b0v = bias[col], b1v = bias[col + 1];
#pragma unroll
        for (int mt = 0; mt < 2; ++mt) {
#pragma unroll
            for (int h = 0; h < 2; ++h) {
                int m = m0 + wm * 32 + mt * 16 + g + h * 8;
                if (m >= MROWS) continue;
                int bb = m / NSEQ, nn = m % NSEQ;
                float* dst = (nn < NT)
                    ? (out + XOUT_ELEMS + ((size_t)bb * NT + nn) * C_DIM)
                    : (out + ((size_t)bb * HW + (nn - NT)) * C_DIM);
                float2 v;
                v.x = c[mt][nt][h * 2 + 0] + b0v;
                v.y = c[mt][nt][h * 2 + 1] + b1v;
                *(float2*)(dst + col) = v;
            }
        }
    }
}

// ---------------------------------------------------------------------------
extern "C" void kernel_launch(void* const* d_in, const int* in_sizes, int n_in,
                              void* d_out, int out_size)
{
    const float* x      = (const float*)d_in[0];
    const float* vp     = (const float*)d_in[1];
    const float* qkv_w  = (const float*)d_in[2];
    const float* qkv_b  = (const float*)d_in[3];
    const float* proj_w = (const float*)d_in[4];
    const float* proj_b = (const float*)d_in[5];
    const float* rph    = (const float*)d_in[6];
    const float* rpw    = (const float*)d_in[7];
    float* out = (float*)d_out;

    (void)in_sizes; (void)n_in; (void)out_size;

    cudaFuncSetAttribute(qkv_mma_kernel,
                         cudaFuncAttributeMaxDynamicSharedMemorySize,
                         GEMM_SM_BYTES);
    cudaFuncSetAttribute(proj_mma_kernel,
                         cudaFuncAttributeMaxDynamicSharedMemorySize,
                         GEMM_SM_BYTES);
    cudaFuncSetAttribute(attn_mma_kernel,
                         cudaFuncAttributeMaxDynamicSharedMemorySize,
                         ATT_SM_BYTES);

    prep_xs_kernel<<<1184, 256>>>(x, vp);
    prep_w_kernel<<<1184, 256>>>(qkv_w, proj_w);
    qkv_mma_kernel<<<dim3(QKV_N / 128, (MROWS + 127) / 128), 256, GEMM_SM_BYTES>>>(qkv_b);
    rel_kernel<<<dim3(32, BHN / 4, 2), 256>>>(rph, rpw);
    attn_mma_kernel<<<dim3((NSEQ + 127) / 128, BHN), 256, ATT_SM_BYTES>>>();
    proj_mma_kernel<<<dim3(C_DIM / 128, (MROWS + 127) / 128), 256, GEMM_SM_BYTES>>>(proj_b, out);
}

// round 15
// speedup vs baseline: 1.6340x; 1.1311x over previous
#include <cuda_runtime.h>

// ---------------------------------------------------------------------------
// PromptedAttention: B=8, H=W=32, C=768, heads=12, hd=64, nt=8, N=1032
// Round 15: paired float2 rel-bias loads in attention; float4 RsT loads in
// rel_kernel (ld=36). Structure otherwise identical to R14.
// ---------------------------------------------------------------------------

#define BATCH     8
#define HEADS     12
#define HD        64
#define C_DIM     768
#define NT        8
#define HW        1024
#define NSEQ      1032
#define BHN       96
#define MROWS     8256
#define QKV_N     2304
#define XOUT_ELEMS 6291456

__device__ float g_q[BHN * NSEQ * HD];
__device__ float g_k[BHN * NSEQ * HD];
__device__ float g_v[BHN * NSEQ * HD];
__device__ float g_relh[BHN * 32 * 32 * 32];
__device__ float g_relw[BHN * 32 * 32 * 32];
__device__ float g_ctx[MROWS * C_DIM];
__device__ float g_xs[MROWS * C_DIM];
__device__ float g_wq[C_DIM * QKV_N];
__device__ float g_wp[C_DIM * C_DIM];

__device__ __forceinline__ unsigned f2tf(float f) {
    unsigned u;
    asm("cvt.rna.tf32.f32 %0, %1;" : "=r"(u) : "f"(f));
    return u;
}
__device__ __forceinline__ float f2tff(float f) { return __uint_as_float(f2tf(f)); }

__device__ __forceinline__ void mma8(float* c, const unsigned* a, const unsigned* b) {
    asm volatile(
        "mma.sync.aligned.m16n8k8.row.col.f32.tf32.tf32.f32 "
        "{%0,%1,%2,%3}, {%4,%5,%6,%7}, {%8,%9}, {%0,%1,%2,%3};\n"
        : "+f"(c[0]), "+f"(c[1]), "+f"(c[2]), "+f"(c[3])
        : "r"(a[0]), "r"(a[1]), "r"(a[2]), "r"(a[3]), "r"(b[0]), "r"(b[1]));
}

__device__ __forceinline__ unsigned smem_u32(const void* p) {
    return (unsigned)__cvta_generic_to_shared(p);
}
__device__ __forceinline__ void cpasync16(unsigned dst, const void* src, bool pred) {
    asm volatile("cp.async.cg.shared.global [%0], [%1], 16, %2;\n"
                 :: "r"(dst), "l"(src), "r"(pred ? 16 : 0));
}
#define CP_COMMIT() asm volatile("cp.async.commit_group;\n" ::: "memory")
#define CP_WAIT(N)  asm volatile("cp.async.wait_group %0;\n" :: "n"(N) : "memory")

#define A_LD 36
#define B_LD 136
#define A_STG (128 * A_LD)
#define B_STG (32 * B_LD)
#define GEMM_SM_BYTES (2 * (A_STG + B_STG) * 4)   // 71680

// ---------------------------------------------------------------------------
// K0a: build rounded concat g_xs.
// ---------------------------------------------------------------------------
__global__ __launch_bounds__(256) void prep_xs_kernel(
    const float* __restrict__ x, const float* __restrict__ vp)
{
    const int F4 = C_DIM / 4;
    const int total = MROWS * F4;
    for (int idx = blockIdx.x * 256 + threadIdx.x; idx < total;
         idx += gridDim.x * 256) {
        int row = idx / F4;
        int f4 = idx - row * F4;
        int b = row / NSEQ, n = row % NSEQ;
        const float4* src = (n < NT)
            ? (const float4*)(vp + ((size_t)b * NT + n) * C_DIM)
            : (const float4*)(x + ((size_t)b * HW + (n - NT)) * C_DIM);
        float4 t = src[f4];
        float4 o;
        o.x = f2tff(t.x); o.y = f2tff(t.y); o.z = f2tff(t.z); o.w = f2tff(t.w);
        ((float4*)g_xs)[idx] = o;
    }
}

__global__ __launch_bounds__(256) void prep_w_kernel(
    const float* __restrict__ wq, const float* __restrict__ wp)
{
    const int T1 = C_DIM * QKV_N / 4;
    const int T2 = C_DIM * C_DIM / 4;
    for (int idx = blockIdx.x * 256 + threadIdx.x; idx < T1 + T2;
         idx += gridDim.x * 256) {
        float4 t;
        float4* dst;
        if (idx < T1) { t = ((const float4*)wq)[idx]; dst = (float4*)g_wq + idx; }
        else { t = ((const float4*)wp)[idx - T1]; dst = (float4*)g_wp + (idx - T1); }
        float4 o;
        o.x = f2tff(t.x); o.y = f2tff(t.y); o.z = f2tff(t.z); o.w = f2tff(t.w);
        *dst = o;
    }
}

// ---------------------------------------------------------------------------
// K1: fused QKV GEMM, BK=32, 2-stage cp.async, dynamic smem.
// ---------------------------------------------------------------------------
__global__ __launch_bounds__(256) void qkv_mma_kernel(const float* __restrict__ bias)
{
    extern __shared__ float dynsm[];
    float* Asb = dynsm;
    float* Bsb = dynsm + 2 * A_STG;

    const int m0 = blockIdx.y * 128;
    const int n0 = blockIdx.x * 128;
    const int tid = threadIdx.x;
    const int wid = tid >> 5, lane = tid & 31;
    const int g = lane >> 2, tig = lane & 3;
    const int wm = wid >> 1, wn = wid & 1;

    const int aRow = tid >> 1;
    const int aK   = (tid & 1) * 16;
    const int am   = m0 + aRow;
    const bool av  = (am < MROWS);
    const float* arp = g_xs + (size_t)(av ? am : 0) * C_DIM;

    const int bk = tid >> 5;
    const int bn = (tid & 31) * 4;

    float c[2][8][4];
#pragma unroll
    for (int mt = 0; mt < 2; ++mt)
#pragma unroll
        for (int nt = 0; nt < 8; ++nt)
#pragma unroll
            for (int j = 0; j < 4; ++j) c[mt][nt][j] = 0.f;

    auto load_stage = [&](int s, int k0) {
        unsigned ad = smem_u32(&Asb[s * A_STG + aRow * A_LD + aK]);
        unsigned bd = smem_u32(&Bsb[s * B_STG + bk * B_LD + bn]);
#pragma unroll
        for (int i = 0; i < 4; ++i)
            cpasync16(ad + 16 * i, arp + k0 + aK + 4 * i, av);
#pragma unroll
        for (int i = 0; i < 4; ++i)
            cpasync16(bd + (8 * i) * B_LD * 4,
                      g_wq + (size_t)(k0 + bk + 8 * i) * QKV_N + n0 + bn, true);
        CP_COMMIT();
    };

    const int NKT = C_DIM / 32;
    load_stage(0, 0);

    for (int kt = 0; kt < NKT; ++kt) {
        int s = kt & 1;
        if (kt + 1 < NKT) { load_stage(s ^ 1, (kt + 1) * 32); CP_WAIT(1); }
        else              { CP_WAIT(0); }
        __syncthreads();

        const unsigned* Au = (const unsigned*)(Asb + s * A_STG);
        const unsigned* Bu = (const unsigned*)(Bsb + s * B_STG);
#pragma unroll
        for (int ks = 0; ks < 4; ++ks) {
            unsigned a[2][4];
#pragma unroll
            for (int mt = 0; mt < 2; ++mt) {
                int mr = wm * 32 + mt * 16;
                a[mt][0] = Au[(mr + g    ) * A_LD + ks * 8 + tig];
                a[mt][1] = Au[(mr + g + 8) * A_LD + ks * 8 + tig];
                a[mt][2] = Au[(mr + g    ) * A_LD + ks * 8 + tig + 4];
                a[mt][3] = Au[(mr + g + 8) * A_LD + ks * 8 + tig + 4];
            }
            unsigned b[8][2];
#pragma unroll
            for (int nt = 0; nt < 8; ++nt) {
                int nc = wn * 64 + nt * 8 + g;
                b[nt][0] = Bu[(ks * 8 + tig    ) * B_LD + nc];
                b[nt][1] = Bu[(ks * 8 + tig + 4) * B_LD + nc];
            }
#pragma unroll
            for (int mt = 0; mt < 2; ++mt)
#pragma unroll
                for (int nt = 0; nt < 8; ++nt) mma8(c[mt][nt], a[mt], b[nt]);
        }
        __syncthreads();
    }

    float* bufs[3] = {g_q, g_k, g_v};
#pragma unroll
    for (int nt = 0; nt < 8; ++nt) {
        int col = n0 + wn * 64 + nt * 8 + tig * 2;
        int which = col / C_DIM;
        int c2 = col % C_DIM;
        int head = c2 >> 6, db = c2 & 63;
        float b0v = bias[col], b1v = bias[col + 1];
        float* buf = bufs[which];
#pragma unroll
        for (int mt = 0; mt < 2; ++mt) {
#pragma unroll
            for (int h = 0; h < 2; ++h) {
                int m = m0 + wm * 32 + mt * 16 + g + h * 8;
                if (m >= MROWS) continue;
                int bb = m / NSEQ, nn = m % NSEQ;
                float* dst = buf + (size_t)bb * (HEADS * NSEQ * HD)
                                 + (size_t)head * (NSEQ * HD)
                                 + (size_t)nn * HD + db;
                float2 v;
                v.x = f2tff(c[mt][nt][h * 2 + 0] + b0v);
                v.y = f2tff(c[mt][nt][h * 2 + 1] + b1v);
                *(float2*)dst = v;
            }
        }
    }
}

// ---------------------------------------------------------------------------
// K2: rel bias GEMMs — 4 bh per block, shared R tile (ld=36, float4 loads).
// ---------------------------------------------------------------------------
__global__ __launch_bounds__(256) void rel_kernel(
    const float* __restrict__ rph, const float* __restrict__ rpw)
{
    __shared__ float qs[4][32 * 65];
    __shared__ float RsT[64 * 36];    // [c][k], ld=36 -> float4 @ c*36+4t aligned

    const int bh0 = blockIdx.y * 4;
    const int idx0 = blockIdx.x;
    const int variant = blockIdx.z;
    const int tid = threadIdx.x;

    const float* rp = (variant == 0) ? rph : rpw;
#pragma unroll
    for (int it = 0; it < 8; ++it) {
        int idx = tid + it * 256;       // 2048
        int k = idx >> 6, c = idx & 63;
        RsT[c * 36 + k] = rp[(size_t)(idx0 - k + 31) * HD + c];
    }
#pragma unroll
    for (int it = 0; it < 32; ++it) {
        int idx = tid + it * 256;       // 8192
        int grp = idx >> 11;
        int w = idx & 2047;
        int r = w >> 6, c = w & 63;
        int bh = bh0 + grp;
        int n = (variant == 0) ? (NT + idx0 * 32 + r) : (NT + r * 32 + idx0);
        qs[grp][r * 65 + c] = g_q[((size_t)bh * NSEQ + n) * HD + c];
    }
    __syncthreads();

    const int grp = tid >> 6;
    const int stid = tid & 63;
    const int bh = bh0 + grp;
    const int tr = stid >> 3;
    const int tk = stid & 7;
    const float* qsg = qs[grp];

    float acc[4][4];
#pragma unroll
    for (int i = 0; i < 4; ++i)
#pragma unroll
        for (int j = 0; j < 4; ++j) acc[i][j] = 0.f;

#pragma unroll 4
    for (int c = 0; c < 64; ++c) {
        float q[4];
#pragma unroll
        for (int i = 0; i < 4; ++i) q[i] = qsg[(tr * 4 + i) * 65 + c];
        float4 rv = *(const float4*)&RsT[c * 36 + tk * 4];
#pragma unroll
        for (int i = 0; i < 4; ++i) {
            acc[i][0] += q[i] * rv.x;
            acc[i][1] += q[i] * rv.y;
            acc[i][2] += q[i] * rv.z;
            acc[i][3] += q[i] * rv.w;
        }
    }

    float* outb = (variant == 0) ? g_relh : g_relw;
#pragma unroll
    for (int i = 0; i < 4; ++i) {
        int row = tr * 4 + i;
        size_t base = (variant == 0)
            ? ((((size_t)bh * 32 + idx0) * 32 + row) * 32)
            : ((((size_t)bh * 32 + row) * 32 + idx0) * 32);
        float4 v;
        v.x = acc[i][0]; v.y = acc[i][1]; v.z = acc[i][2]; v.w = acc[i][3];
        *(float4*)(outb + base + tk * 4) = v;
    }
}

// ---------------------------------------------------------------------------
// K3: FA2 attention, register Q fragments, cp.async double-buffered K/V,
// paired float2 rel-bias loads.
// ---------------------------------------------------------------------------
#define KS_STG (64 * 68)
#define VS_STG (64 * 72)
#define ATT_SM_FLOATS (2 * KS_STG + 2 * VS_STG + 2 * 128 * 32)
#define ATT_SM_BYTES  (ATT_SM_FLOATS * 4)   // 104448

__global__ __launch_bounds__(256, 2) void attn_mma_kernel()
{
    extern __shared__ float sm[];
    float* Ks  = sm;                    // [2][64][68]
    float* Vs  = Ks + 2 * KS_STG;       // [2][64][72]
    float* rhs = Vs + 2 * VS_STG;       // [128][32]
    float* rws = rhs + 128 * 32;        // [128][32]

    const int tid = threadIdx.x;
    const int wid = tid >> 5, lane = tid & 31;
    const int g = lane >> 2, tig = lane & 3;
    const int bh = blockIdx.y;
    const int b = bh / HEADS, head = bh % HEADS;
    const int q0 = blockIdx.x * 128;

    const float* qbase = g_q + (size_t)bh * NSEQ * HD;
    const float* kbase = g_k + (size_t)bh * NSEQ * HD;
    const float* vbase = g_v + (size_t)bh * NSEQ * HD;

    const int r0 = wid * 16 + g;
    const int r1 = r0 + 8;
    const int qg0 = q0 + r0, qg1 = q0 + r1;

    const int lr  = tid >> 4;
    const int ld4 = (tid & 15) * 4;
    auto load_kv = [&](int s, int k0) {
        float* Ksb = Ks + s * KS_STG;
        float* Vsb = Vs + s * VS_STG;
#pragma unroll
        for (int t = 0; t < 4; ++t) {
            int r = lr + t * 16;
            int kg = k0 + r;
            bool pv = (kg < NSEQ);
            const float* ksrc = kbase + (size_t)(pv ? kg : 0) * HD + ld4;
            const float* vsrc = vbase + (size_t)(pv ? kg : 0) * HD + ld4;
            cpasync16(smem_u32(&Ksb[r * 68 + ld4]), ksrc, pv);
            cpasync16(smem_u32(&Vsb[r * 72 + ld4]), vsrc, pv);
        }
        CP_COMMIT();
    };

    load_kv(0, 0);

    // Q fragments straight from gmem, x0.125 (exact)
    float qa[8][4];
    {
        const bool v0 = (qg0 < NSEQ), v1 = (qg1 < NSEQ);
        const float* qr0 = qbase + (size_t)(v0 ? qg0 : 0) * HD;
        const float* qr1 = qbase + (size_t)(v1 ? qg1 : 0) * HD;
#pragma unroll
        for (int ks = 0; ks < 8; ++ks) {
            qa[ks][0] = v0 ? qr0[ks * 8 + tig]     * 0.125f : 0.f;
            qa[ks][1] = v1 ? qr1[ks * 8 + tig]     * 0.125f : 0.f;
            qa[ks][2] = v0 ? qr0[ks * 8 + tig + 4] * 0.125f : 0.f;
            qa[ks][3] = v1 ? qr1[ks * 8 + tig + 4] * 0.125f : 0.f;
        }
    }

#pragma unroll
    for (int it = 0; it < 4; ++it) {
        int idx = tid + it * 256;
        int r = idx >> 3, c4 = (idx & 7) * 4;
        int qg = q0 + r;
        float4 hv = make_float4(0.f, 0.f, 0.f, 0.f), wv = hv;
        if (qg >= NT && qg < NSEQ) {
            int pix = qg - NT;
            int hq = pix >> 5, wq = pix & 31;
            size_t rbase = (((size_t)bh * 32 + hq) * 32 + wq) * 32;
            hv = *(const float4*)(g_relh + rbase + c4);
            wv = *(const float4*)(g_relw + rbase + c4);
        }
        *(float4*)&rhs[r * 32 + c4] = hv;
        *(float4*)&rws[r * 32 + c4] = wv;
    }

    float m0r = -3.0e38f, l0r = 0.f;
    float m1r = -3.0e38f, l1r = 0.f;
    float oc[8][4];
#pragma unroll
    for (int nt = 0; nt < 8; ++nt)
#pragma unroll
        for (int j = 0; j < 4; ++j) oc[nt][j] = 0.f;

    __syncthreads();

    const int srcA = (lane & ~3) | (tig >> 1);
    const int srcB = srcA + 2;
    const bool odd = (tig & 1);
    const bool qp0 = (qg0 >= NT), qp1 = (qg1 >= NT);

    const int NIT = (NSEQ + 63) / 64;
    for (int itk = 0; itk < NIT; ++itk) {
        int s = itk & 1;
        int k0 = itk * 64;
        if (itk + 1 < NIT) { load_kv(s ^ 1, k0 + 64); CP_WAIT(1); }
        else               { CP_WAIT(0); }
        __syncthreads();

        const unsigned* Ku = (const unsigned*)(Ks + s * KS_STG);
        const unsigned* Vu = (const unsigned*)(Vs + s * VS_STG);

        float sc[8][4];
#pragma unroll
        for (int nt = 0; nt < 8; ++nt)
#pragma unroll
            for (int j = 0; j < 4; ++j) sc[nt][j] = 0.f;
#pragma unroll
        for (int ks = 0; ks < 8; ++ks) {
            unsigned a[4];
            a[0] = f2tf(qa[ks][0]);
            a[1] = f2tf(qa[ks][1]);
            a[2] = f2tf(qa[ks][2]);
            a[3] = f2tf(qa[ks][3]);
#pragma unroll
            for (int nt = 0; nt < 8; ++nt) {
                unsigned bb[2];
                int key = nt * 8 + g;
                bb[0] = Ku[key * 68 + ks * 8 + tig];
                bb[1] = Ku[key * 68 + ks * 8 + tig + 4];
                mma8(sc[nt], a, bb);
            }
        }

        // bias + mask: jg0 even; (e0,e1) uniformly masked; paired rws loads.
        float tm0 = -3.0e38f, tm1 = -3.0e38f;
#pragma unroll
        for (int nt = 0; nt < 8; ++nt) {
            int jg = k0 + nt * 8 + tig * 2;     // even
            float v00 = sc[nt][0], v01 = sc[nt][1];
            float v10 = sc[nt][2], v11 = sc[nt][3];
            if (jg >= NSEQ) {
                v00 = v01 = v10 = v11 = -1e30f;
            } else if (jg < NT) {
                if (qp0) { v00 -= 100.f; v01 -= 100.f; }
                if (qp1) { v10 -= 100.f; v11 -= 100.f; }
            } else {
                int pj = jg - NT;               // even, pj&31 <= 30
                int hidx = pj >> 5, widx = pj & 31;
                if (qp0) {
                    float rh = rhs[r0 * 32 + hidx];
                    float2 rw = *(const float2*)&rws[r0 * 32 + widx];
                    v00 += rh + rw.x; v01 += rh + rw.y;
                }
                if (qp1) {
                    float rh = rhs[r1 * 32 + hidx];
                    float2 rw = *(const float2*)&rws[r1 * 32 + widx];
                    v10 += rh + rw.x; v11 += rh + rw.y;
                }
            }
            sc[nt][0] = v00; sc[nt][1] = v01;
            sc[nt][2] = v10; sc[nt][3] = v11;
            tm0 = fmaxf(tm0, fmaxf(v00, v01));
            tm1 = fmaxf(tm1, fmaxf(v10, v11));
        }
        tm0 = fmaxf(tm0, __shfl_xor_sync(0xffffffffu, tm0, 1));
        tm0 = fmaxf(tm0, __shfl_xor_sync(0xffffffffu, tm0, 2));
        tm1 = fmaxf(tm1, __shfl_xor_sync(0xffffffffu, tm1, 1));
        tm1 = fmaxf(tm1, __shfl_xor_sync(0xffffffffu, tm1, 2));

        float nm0 = fmaxf(m0r, tm0), nm1 = fmaxf(m1r, tm1);
        float s0 = __expf(m0r - nm0), s1 = __expf(m1r - nm1);
        float sum0 = 0.f, sum1 = 0.f;
#pragma unroll
        for (int nt = 0; nt < 8; ++nt) {
#pragma unroll
            for (int e = 0; e < 2; ++e) {
                float p0 = __expf(sc[nt][e] - nm0);
                float p1 = __expf(sc[nt][2 + e] - nm1);
                sum0 += p0; sum1 += p1;
                sc[nt][e] = f2tff(p0);
                sc[nt][2 + e] = f2tff(p1);
            }
        }
        sum0 += __shfl_xor_sync(0xffffffffu, sum0, 1);
        sum0 += __shfl_xor_sync(0xffffffffu, sum0, 2);
        sum1 += __shfl_xor_sync(0xffffffffu, sum1, 1);
        sum1 += __shfl_xor_sync(0xffffffffu, sum1, 2);
        l0r = l0r * s0 + sum0; m0r = nm0;
        l1r = l1r * s1 + sum1; m1r = nm1;

#pragma unroll
        for (int nt = 0; nt < 8; ++nt) {
            oc[nt][0] *= s0; oc[nt][1] *= s0;
            oc[nt][2] *= s1; oc[nt][3] *= s1;
        }

#pragma unroll
        for (int ks = 0; ks < 8; ++ks) {
            float x0 = __shfl_sync(0xffffffffu, sc[ks][0], srcA);
            float x1 = __shfl_sync(0xffffffffu, sc[ks][1], srcA);
            float x2 = __shfl_sync(0xffffffffu, sc[ks][2], srcA);
            float x3 = __shfl_sync(0xffffffffu, sc[ks][3], srcA);
            float y0 = __shfl_sync(0xffffffffu, sc[ks][0], srcB);
            float y1 = __shfl_sync(0xffffffffu, sc[ks][1], srcB);
            float y2 = __shfl_sync(0xffffffffu, sc[ks][2], srcB);
            float y3 = __shfl_sync(0xffffffffu, sc[ks][3], srcB);
            unsigned a[4];
            a[0] = __float_as_uint(odd ? x1 : x0);
            a[1] = __float_as_uint(odd ? x3 : x2);
            a[2] = __float_as_uint(odd ? y1 : y0);
            a[3] = __float_as_uint(odd ? y3 : y2);
#pragma unroll
            for (int nt = 0; nt < 8; ++nt) {
                unsigned bb[2];
                int dcol = nt * 8 + g;
                bb[0] = Vu[(ks * 8 + tig    ) * 72 + dcol];
                bb[1] = Vu[(ks * 8 + tig + 4) * 72 + dcol];
                mma8(oc[nt], a, bb);
            }
        }
        __syncthreads();
    }

    {
        float inv0 = (qg0 < NSEQ) ? (1.f / l0r) : 0.f;
        float inv1 = (qg1 < NSEQ) ? (1.f / l1r) : 0.f;
#pragma unroll
        for (int nt = 0; nt < 8; ++nt) {
            int col = nt * 8 + tig * 2;
            if (qg0 < NSEQ) {
                float2 v = make_float2(f2tff(oc[nt][0] * inv0), f2tff(oc[nt][1] * inv0));
                *(float2*)(g_ctx + ((size_t)b * NSEQ + qg0) * C_DIM + head * HD + col) = v;
            }
            if (qg1 < NSEQ) {
                float2 v = make_float2(f2tff(oc[nt][2] * inv1), f2tff(oc[nt][3] * inv1));
                *(float2*)(g_ctx + ((size_t)b * NSEQ + qg1) * C_DIM + head * HD + col) = v;
            }
        }
    }
}

// ---------------------------------------------------------------------------
// K4: output projection GEMM, BK=32, 2-stage cp.async, dynamic smem.
// ---------------------------------------------------------------------------
__global__ __launch_bounds__(256) void proj_mma_kernel(
    const float* __restrict__ bias, float* __restrict__ out)
{
    extern __shared__ float dynsm[];
    float* Asb = dynsm;
    float* Bsb = dynsm + 2 * A_STG;

    const int m0 = blockIdx.y * 128;
    const int n0 = blockIdx.x * 128;
    const int tid = threadIdx.x;
    const int wid = tid >> 5, lane = tid & 31;
    const int g = lane >> 2, tig = lane & 3;
    const int wm = wid >> 1, wn = wid & 1;

    const int aRow = tid >> 1;
    const int aK   = (tid & 1) * 16;
    const int am   = m0 + aRow;
    const bool av  = (am < MROWS);
    const float* arp = g_ctx + (size_t)(av ? am : 0) * C_DIM;

    const int bk = tid >> 5;
    const int bn = (tid & 31) * 4;

    float c[2][8][4];
#pragma unroll
    for (int mt = 0; mt < 2; ++mt)
#pragma unroll
        for (int nt = 0; nt < 8; ++nt)
#pragma unroll
            for (int j = 0; j < 4; ++j) c[mt][nt][j] = 0.f;

    auto load_stage = [&](int s, int k0) {
        unsigned ad = smem_u32(&Asb[s * A_STG + aRow * A_LD + aK]);
        unsigned bd = smem_u32(&Bsb[s * B_STG + bk * B_LD + bn]);
#pragma unroll
        for (int i = 0; i < 4; ++i)
            cpasync16(ad + 16 * i, arp + k0 + aK + 4 * i, av);
#pragma unroll
        for (int i = 0; i < 4; ++i)
            cpasync16(bd + (8 * i) * B_LD * 4,
                      g_wp + (size_t)(k0 + bk + 8 * i) * C_DIM + n0 + bn, true);
        CP_COMMIT();
    };

    const int NKT = C_DIM / 32;
    load_stage(0, 0);

    for (int kt = 0; kt < NKT; ++kt) {
        int s = kt & 1;
        if (kt + 1 < NKT) { load_stage(s ^ 1, (kt + 1) * 32); CP_WAIT(1); }
        else              { CP_WAIT(0); }
        __syncthreads();

        const unsigned* Au = (const unsigned*)(Asb + s * A_STG);
        const unsigned* Bu = (const unsigned*)(Bsb + s * B_STG);
#pragma unroll
        for (int ks = 0; ks < 4; ++ks) {
            unsigned a[2][4];
#pragma unroll
            for (int mt = 0; mt < 2; ++mt) {
                int mr = wm * 32 + mt * 16;
                a[mt][0] = Au[(mr + g    ) * A_LD + ks * 8 + tig];
                a[mt][1] = Au[(mr + g + 8) * A_LD + ks * 8 + tig];
                a[mt][2] = Au[(mr + g    ) * A_LD + ks * 8 + tig + 4];
                a[mt][3] = Au[(mr + g + 8) * A_LD + ks * 8 + tig + 4];
            }
            unsigned b[8][2];
#pragma unroll
            for (int nt = 0; nt < 8; ++nt) {
                int nc = wn * 64 + nt * 8 + g;
                b[nt][0] = Bu[(ks * 8 + tig    ) * B_LD + nc];
                b[nt][1] = Bu[(ks * 8 + tig + 4) * B_LD + nc];
            }
#pragma unroll
            for (int mt = 0; mt < 2; ++mt)
#pragma unroll
                for (int nt = 0; nt < 8; ++nt) mma8(c[mt][nt], a[mt], b[nt]);
        }
        __syncthreads();
    }

#pragma unroll
    for (int nt = 0; nt < 8; ++nt) {
        int col = n0 + wn * 64 + nt * 8 + tig * 2;
        float b0v = bias[col], b1v = bias[col + 1];
#pragma unroll
        for (int mt = 0; mt < 2; ++mt) {
#pragma unroll
            for (int h = 0; h < 2; ++h) {
                int m = m0 + wm * 32 + mt * 16 + g + h * 8;
                if (m >= MROWS) continue;
                int bb = m / NSEQ, nn = m % NSEQ;
                float* dst = (nn < NT)
                    ? (out + XOUT_ELEMS + ((size_t)bb * NT + nn) * C_DIM)
                    : (out + ((size_t)bb * HW + (nn - NT)) * C_DIM);
                float2 v;
                v.x = c[mt][nt][h * 2 + 0] + b0v;
                v.y = c[mt][nt][h * 2 + 1] + b1v;
                *(float2*)(dst + col) = v;
            }
        }
    }
}

// ---------------------------------------------------------------------------
extern "C" void kernel_launch(void* const* d_in, const int* in_sizes, int n_in,
                              void* d_out, int out_size)
{
    const float* x      = (const float*)d_in[0];
    const float* vp     = (const float*)d_in[1];
    const float* qkv_w  = (const float*)d_in[2];
    const float* qkv_b  = (const float*)d_in[3];
    const float* proj_w = (const float*)d_in[4];
    const float* proj_b = (const float*)d_in[5];
    const float* rph    = (const float*)d_in[6];
    const float* rpw    = (const float*)d_in[7];
    float* out = (float*)d_out;

    (void)in_sizes; (void)n_in; (void)out_size;

    cudaFuncSetAttribute(qkv_mma_kernel,
                         cudaFuncAttributeMaxDynamicSharedMemorySize,
                         GEMM_SM_BYTES);
    cudaFuncSetAttribute(proj_mma_kernel,
                         cudaFuncAttributeMaxDynamicSharedMemorySize,
                         GEMM_SM_BYTES);
    cudaFuncSetAttribute(attn_mma_kernel,
                         cudaFuncAttributeMaxDynamicSharedMemorySize,
                         ATT_SM_BYTES);

    prep_xs_kernel<<<1184, 256>>>(x, vp);
    prep_w_kernel<<<1184, 256>>>(qkv_w, proj_w);
    qkv_mma_kernel<<<dim3(QKV_N / 128, (MROWS + 127) / 128), 256, GEMM_SM_BYTES>>>(qkv_b);
    rel_kernel<<<dim3(32, BHN / 4, 2), 256>>>(rph, rpw);
    attn_mma_kernel<<<dim3((NSEQ + 127) / 128, BHN), 256, ATT_SM_BYTES>>>();
    proj_mma_kernel<<<dim3(C_DIM / 128, (MROWS + 127) / 128), 256, GEMM_SM_BYTES>>>(proj_b, out);
}